// round 3
// baseline (speedup 1.0000x reference)
#include <cuda_runtime.h>
#include <math.h>

#define BB 2
#define LL 512
#define LCC 64
#define DM 768
#define DI 1536
#define NH 24
#define HD 64
#define DSTATE 128
#define CONVD 1792
#define DIP 3352
#define NLAYER 8
#define AHH 8
#define ADD 64
#define AINNER 512

// ---------------- scratch (device globals; no allocation allowed) ----------------
__device__ float g_hidden[BB*LL*DM];
__device__ float g_resid [BB*LL*DM];
__device__ float g_u     [BB*LL*DM];     // mod() output feeding in_proj / q_proj
__device__ float g_tmp   [BB*LL*DM];     // mamba_out / attn_out projection result
__device__ float g_zx    [BB*LL*DIP];    // zxbcdt
__device__ float g_xBC   [BB*LL*CONVD]; // conv+silu output
__device__ float g_dt    [BB*LL*NH];
__device__ float g_dA    [BB*LL*NH];
__device__ float g_y     [BB*LL*DI];
__device__ float g_q     [BB*LL*AINNER];
__device__ float g_k     [BB*LCC*AINNER];
__device__ float g_v     [BB*LCC*AINNER];
__device__ float g_ao    [BB*LL*AINNER]; // attention output (pre o_proj)
__device__ float g_aff   [NLAYER*BB*6*DM];
__device__ float g_csilu [BB*DM];

__device__ __forceinline__ float siluf(float x) { return x / (1.f + expf(-x)); }

__device__ __forceinline__ float block_reduce_sum(float v) {
    __shared__ float red_s[33];
    int lane = threadIdx.x & 31;
    int wid  = threadIdx.x >> 5;
    #pragma unroll
    for (int o = 16; o > 0; o >>= 1) v += __shfl_xor_sync(0xffffffffu, v, o);
    if (lane == 0) red_s[wid] = v;
    __syncthreads();
    int nw = (blockDim.x + 31) >> 5;
    if (wid == 0) {
        float x = (lane < nw) ? red_s[lane] : 0.f;
        #pragma unroll
        for (int o = 16; o > 0; o >>= 1) x += __shfl_xor_sync(0xffffffffu, x, o);
        if (lane == 0) red_s[32] = x;
    }
    __syncthreads();
    float r = red_s[32];
    __syncthreads();
    return r;
}

// ---------------- init ----------------
__global__ void k_init(const float* __restrict__ hs) {
    int i = blockIdx.x * 256 + threadIdx.x;
    if (i < BB*LL*DM) { g_hidden[i] = hs[i]; g_resid[i] = 0.f; }
}

// silu(mean(cond, axis=1)) -> g_csilu (B, DM)
__global__ void k_condsilu(const float* __restrict__ ref) {
    int i = blockIdx.x * 256 + threadIdx.x;
    if (i >= BB*DM) return;
    int b = i / DM, d = i % DM;
    float s = 0.f;
    for (int m = 0; m < LCC; m++) s += ref[(b*LCC + m)*DM + d];
    s *= (1.f / LCC);
    g_csilu[i] = siluf(s);
}

// aff[l][b][j] = csilu[b] . ada_w[l][:,j] + ada_b[l][j]
__global__ void k_ada(const float* __restrict__ ada_w, const float* __restrict__ ada_b) {
    int i = blockIdx.x * 256 + threadIdx.x;
    if (i >= NLAYER*BB*6*DM) return;
    int j  = i % (6*DM);
    int lb = i / (6*DM);
    int b  = lb % BB;
    int l  = lb / BB;
    float s = ada_b[l*6*DM + j];
    const float* cs = &g_csilu[b*DM];
    const float* w  = ada_w + (size_t)l*DM*6*DM + j;
    for (int d = 0; d < DM; d++) s += cs[d] * w[(size_t)d*6*DM];
    g_aff[i] = s;
}

// ---------------- generic SGEMM C[M,N] = A[M,K] @ W[K,N] (+bias) ----------------
// requires M % 128 == 0, K % 8 == 0, N % 4 == 0
__global__ __launch_bounds__(256) void sgemm(const float* __restrict__ A,
                                             const float* __restrict__ W,
                                             const float* __restrict__ bias,
                                             float* __restrict__ C,
                                             int M, int N, int K) {
    __shared__ float As[8][128];
    __shared__ float Bs[8][128];
    int tid = threadIdx.x;
    int n0 = blockIdx.x * 128, m0 = blockIdx.y * 128;
    int tx = tid & 15, ty = tid >> 4;
    float acc[8][8];
    #pragma unroll
    for (int i = 0; i < 8; i++)
        #pragma unroll
        for (int j = 0; j < 8; j++) acc[i][j] = 0.f;

    int a_row = tid >> 1, a_k4 = (tid & 1) * 4;
    int b_row = tid >> 5, b_c4 = (tid & 31) * 4;

    for (int k0 = 0; k0 < K; k0 += 8) {
        float4 av = *reinterpret_cast<const float4*>(A + (size_t)(m0 + a_row)*K + k0 + a_k4);
        As[a_k4+0][a_row] = av.x;
        As[a_k4+1][a_row] = av.y;
        As[a_k4+2][a_row] = av.z;
        As[a_k4+3][a_row] = av.w;
        float4 bv = make_float4(0.f,0.f,0.f,0.f);
        if (n0 + b_c4 < N)
            bv = *reinterpret_cast<const float4*>(W + (size_t)(k0 + b_row)*N + n0 + b_c4);
        *reinterpret_cast<float4*>(&Bs[b_row][b_c4]) = bv;
        __syncthreads();
        #pragma unroll
        for (int kk = 0; kk < 8; kk++) {
            float4 a0 = *reinterpret_cast<const float4*>(&As[kk][ty*8]);
            float4 a1 = *reinterpret_cast<const float4*>(&As[kk][ty*8+4]);
            float4 b0 = *reinterpret_cast<const float4*>(&Bs[kk][tx*8]);
            float4 b1 = *reinterpret_cast<const float4*>(&Bs[kk][tx*8+4]);
            float ar[8] = {a0.x,a0.y,a0.z,a0.w,a1.x,a1.y,a1.z,a1.w};
            float br[8] = {b0.x,b0.y,b0.z,b0.w,b1.x,b1.y,b1.z,b1.w};
            #pragma unroll
            for (int i = 0; i < 8; i++)
                #pragma unroll
                for (int j = 0; j < 8; j++)
                    acc[i][j] += ar[i]*br[j];
        }
        __syncthreads();
    }
    #pragma unroll
    for (int i = 0; i < 8; i++) {
        int m = m0 + ty*8 + i;
        #pragma unroll
        for (int j = 0; j < 8; j++) {
            int n = n0 + tx*8 + j;
            if (n < N) {
                float v = acc[i][j];
                if (bias) v += bias[n];
                C[(size_t)m*N + n] = v;
            }
        }
    }
}

// ---------------- pre-norm + AdaLN modulation (mamba branch) ----------------
// r += h ; hn = rmsnorm(r, norm_w) ; g_hidden = hn ; u = hn*(1+sc_mba)+sh_mba
__global__ void k_prenorm_mod(int l, const float* __restrict__ norm_w) {
    int t = blockIdx.x;              // token 0..B*L-1
    int b = t / LL;
    const float* aff = &g_aff[(l*BB + b)*6*DM];
    float vals[3];
    float ss = 0.f;
    #pragma unroll
    for (int i = 0; i < 3; i++) {
        int d = threadIdx.x + i*256;
        float v = g_resid[t*DM + d] + g_hidden[t*DM + d];
        g_resid[t*DM + d] = v;
        vals[i] = v;
        ss += v*v;
    }
    ss = block_reduce_sum(ss);
    float rstd = rsqrtf(ss * (1.f/DM) + 1e-5f);
    #pragma unroll
    for (int i = 0; i < 3; i++) {
        int d = threadIdx.x + i*256;
        float x = vals[i] * rstd * norm_w[l*DM + d];
        g_hidden[t*DM + d] = x;                       // normalized hidden (add-base)
        g_u[t*DM + d] = x * (1.f + aff[DM + d]) + aff[d];
    }
}

// ---------------- depthwise causal conv(4) + silu on xBC, plus dt/dA ----------------
__global__ void k_conv_dt(int l, const float* __restrict__ conv_w,
                          const float* __restrict__ conv_b,
                          const float* __restrict__ dt_bias,
                          const float* __restrict__ A_log) {
    int t  = blockIdx.x;
    int b  = t / LL, tt = t % LL;
    for (int c = threadIdx.x; c < CONVD; c += 256) {
        const float* wc = conv_w + (l*CONVD + c)*4;
        float acc = conv_b[l*CONVD + c];
        #pragma unroll
        for (int j = 0; j < 4; j++) {
            int ts = tt - 3 + j;
            if (ts >= 0) acc += wc[j] * g_zx[(size_t)(b*LL + ts)*DIP + DI + c];
        }
        g_xBC[(size_t)t*CONVD + c] = siluf(acc);
    }
    if (threadIdx.x < NH) {
        int hh = threadIdx.x;
        float x = g_zx[(size_t)t*DIP + DI + CONVD + hh] + dt_bias[l*NH + hh];
        float dt = (x > 20.f) ? x : log1pf(expf(x));
        g_dt[t*NH + hh] = dt;
        g_dA[t*NH + hh] = expf(-expf(A_log[l*NH + hh]) * dt);
    }
}

// ---------------- SSM selective scan ----------------
// grid (B*NH, 2) : block handles 32 of 64 p's.  256 threads: p_local = tid>>3, 16 n's each.
#define TCH 8
__global__ __launch_bounds__(256) void k_scan(int l, const float* __restrict__ D_ssm) {
    int bh = blockIdx.x;
    int b = bh / NH, hh = bh % NH;
    int ps = blockIdx.y;             // 0 or 1
    int tid = threadIdx.x;
    int pl = tid >> 3;               // 0..31
    int p  = ps*32 + pl;
    int ng = tid & 7;
    int nb = ng * 16;
    float hreg[16];
    #pragma unroll
    for (int i = 0; i < 16; i++) hreg[i] = 0.f;

    __shared__ float sx[TCH][32];
    __shared__ float sB[TCH][DSTATE];
    __shared__ float sC[TCH][DSTATE];
    __shared__ float sdt[TCH], sdA[TCH];
    float Dh = D_ssm[l*NH + hh];

    for (int t0 = 0; t0 < LL; t0 += TCH) {
        __syncthreads();
        for (int idx = tid; idx < TCH*288; idx += 256) {
            int st = idx / 288, off = idx % 288;
            size_t tok = (size_t)(b*LL + t0 + st);
            if (off < 32)
                sx[st][off] = g_xBC[tok*CONVD + hh*HD + ps*32 + off];
            else if (off < 160)
                sB[st][off-32] = g_xBC[tok*CONVD + DI + (off-32)];
            else
                sC[st][off-160] = g_xBC[tok*CONVD + DI + DSTATE + (off-160)];
        }
        if (tid < TCH) {
            int tok = b*LL + t0 + tid;
            sdt[tid] = g_dt[tok*NH + hh];
            sdA[tid] = g_dA[tok*NH + hh];
        }
        __syncthreads();
        #pragma unroll
        for (int st = 0; st < TCH; st++) {
            float dtt = sdt[st], dAt = sdA[st];
            float xp  = sx[st][pl];
            float dbx = dtt * xp;
            float y = 0.f;
            #pragma unroll
            for (int i = 0; i < 16; i++) {
                float hv = hreg[i]*dAt + dbx*sB[st][nb+i];
                hreg[i] = hv;
                y += hv * sC[st][nb+i];
            }
            y += __shfl_xor_sync(0xffffffffu, y, 1);
            y += __shfl_xor_sync(0xffffffffu, y, 2);
            y += __shfl_xor_sync(0xffffffffu, y, 4);
            if (ng == 0) {
                int tok = b*LL + t0 + st;
                g_y[(size_t)tok*DI + hh*HD + p] = y + xp * Dh;
            }
        }
    }
}

// ---------------- gated RMS norm: y = rmsnorm(y * silu(z), ssm_norm_w) ----------------
__global__ void k_gatenorm(int l, const float* __restrict__ ssm_norm_w) {
    int t = blockIdx.x;
    __shared__ float sv[DI];
    float ss = 0.f;
    for (int d = threadIdx.x; d < DI; d += 256) {
        float z = g_zx[(size_t)t*DIP + d];
        float v = g_y[(size_t)t*DI + d] * siluf(z);
        sv[d] = v;
        ss += v*v;
    }
    ss = block_reduce_sum(ss);
    float rstd = rsqrtf(ss * (1.f/DI) + 1e-5f);
    for (int d = threadIdx.x; d < DI; d += 256)
        g_y[(size_t)t*DI + d] = sv[d] * rstd * ssm_norm_w[l*DI + d];
}

// ---------------- hidden += g_mba * tmp ; u = ln_noaffine(hidden)*(1+sc_msa)+sh_msa ----------------
__global__ void k_post_mamba(int l) {
    int t = blockIdx.x;
    int b = t / LL;
    const float* aff = &g_aff[(l*BB + b)*6*DM];
    float vals[3];
    float s1 = 0.f;
    #pragma unroll
    for (int i = 0; i < 3; i++) {
        int d = threadIdx.x + i*256;
        float v = g_hidden[t*DM + d] + aff[2*DM + d] * g_tmp[t*DM + d];
        g_hidden[t*DM + d] = v;
        vals[i] = v;
        s1 += v;
    }
    s1 = block_reduce_sum(s1);
    float mean = s1 * (1.f/DM);
    float s2 = 0.f;
    #pragma unroll
    for (int i = 0; i < 3; i++) { float c = vals[i] - mean; s2 += c*c; }
    s2 = block_reduce_sum(s2);
    float rstd = rsqrtf(s2 * (1.f/DM) + 1e-6f);
    #pragma unroll
    for (int i = 0; i < 3; i++) {
        int d = threadIdx.x + i*256;
        float x = (vals[i] - mean) * rstd;
        g_u[t*DM + d] = x * (1.f + aff[4*DM + d]) + aff[3*DM + d];
    }
}

// ---------------- cross attention core ----------------
// grid (L/16, AH, B), 512 threads (16 warps = 16 queries)
__global__ __launch_bounds__(512) void k_attn() {
    int qt = blockIdx.x, hh = blockIdx.y, b = blockIdx.z;
    int warp = threadIdx.x >> 5, lane = threadIdx.x & 31;
    __shared__ float Ks[64][65];
    __shared__ float Vs[64][64];
    __shared__ float Qs[16][64];
    __shared__ float Ps[16][64];
    for (int idx = threadIdx.x; idx < 64*64; idx += 512) {
        int m = idx >> 6, d = idx & 63;
        Ks[m][d] = g_k[(size_t)(b*LCC + m)*AINNER + hh*ADD + d];
        Vs[m][d] = g_v[(size_t)(b*LCC + m)*AINNER + hh*ADD + d];
    }
    for (int idx = threadIdx.x; idx < 16*64; idx += 512) {
        int q = idx >> 6, d = idx & 63;
        Qs[q][d] = g_q[(size_t)(b*LL + qt*16 + q)*AINNER + hh*ADD + d];
    }
    __syncthreads();
    int q = warp;
    float s0 = 0.f, s1 = 0.f;
    #pragma unroll 8
    for (int d = 0; d < 64; d++) {
        float qd = Qs[q][d];
        s0 += qd * Ks[lane][d];
        s1 += qd * Ks[lane+32][d];
    }
    s0 *= 0.125f; s1 *= 0.125f;
    float mx = fmaxf(s0, s1);
    #pragma unroll
    for (int o = 16; o > 0; o >>= 1) mx = fmaxf(mx, __shfl_xor_sync(0xffffffffu, mx, o));
    float e0 = expf(s0 - mx), e1 = expf(s1 - mx);
    float sum = e0 + e1;
    #pragma unroll
    for (int o = 16; o > 0; o >>= 1) sum += __shfl_xor_sync(0xffffffffu, sum, o);
    float inv = 1.f / sum;
    Ps[q][lane] = e0 * inv;
    Ps[q][lane+32] = e1 * inv;
    __syncwarp();
    float o0 = 0.f, o1 = 0.f;
    #pragma unroll 8
    for (int m = 0; m < 64; m++) {
        float pm = Ps[q][m];
        o0 += pm * Vs[m][lane];
        o1 += pm * Vs[m][lane+32];
    }
    size_t base = (size_t)(b*LL + qt*16 + q)*AINNER + hh*ADD;
    g_ao[base + lane]      = o0;
    g_ao[base + lane + 32] = o1;
}

// ---------------- hidden += g_msa * attn_proj ----------------
__global__ void k_post_attn(int l) {
    int i = blockIdx.x * 256 + threadIdx.x;
    if (i >= BB*LL*DM) return;
    int t = i / DM;
    int b = t / LL;
    int d = i % DM;
    g_hidden[i] += g_aff[(l*BB + b)*6*DM + 5*DM + d] * g_tmp[i];
}

// ---------------- final rmsnorm(h + r, norm_f_w) -> out ----------------
__global__ void k_final(const float* __restrict__ norm_f_w, float* __restrict__ out) {
    int t = blockIdx.x;
    float vals[3];
    float ss = 0.f;
    #pragma unroll
    for (int i = 0; i < 3; i++) {
        int d = threadIdx.x + i*256;
        float v = g_hidden[t*DM + d] + g_resid[t*DM + d];
        vals[i] = v;
        ss += v*v;
    }
    ss = block_reduce_sum(ss);
    float rstd = rsqrtf(ss * (1.f/DM) + 1e-5f);
    #pragma unroll
    for (int i = 0; i < 3; i++) {
        int d = threadIdx.x + i*256;
        out[t*DM + d] = vals[i] * rstd * norm_f_w[d];
    }
}

// ---------------- host ----------------
#define GETSYM(p, s) do { void* tmp_; cudaGetSymbolAddress(&tmp_, s); p = (float*)tmp_; } while(0)

extern "C" void kernel_launch(void* const* d_in, const int* in_sizes, int n_in,
                              void* d_out, int out_size) {
    const float* hs        = (const float*)d_in[0];
    const float* ref       = (const float*)d_in[1];
    const float* norm_w    = (const float*)d_in[2];
    const float* ada_w     = (const float*)d_in[3];
    const float* ada_b     = (const float*)d_in[4];
    const float* in_w      = (const float*)d_in[5];
    const float* conv_w    = (const float*)d_in[6];
    const float* conv_b    = (const float*)d_in[7];
    const float* dt_bias   = (const float*)d_in[8];
    const float* A_log     = (const float*)d_in[9];
    const float* D_ssm     = (const float*)d_in[10];
    const float* ssm_nw    = (const float*)d_in[11];
    const float* out_w     = (const float*)d_in[12];
    const float* out_b     = (const float*)d_in[13];
    const float* q_w       = (const float*)d_in[14];
    const float* k_w       = (const float*)d_in[15];
    const float* v_w       = (const float*)d_in[16];
    const float* o_w       = (const float*)d_in[17];
    const float* o_b       = (const float*)d_in[18];
    const float* norm_f_w  = (const float*)d_in[19];
    float* out = (float*)d_out;

    float *p_u, *p_zx, *p_y, *p_tmp, *p_q, *p_k, *p_v, *p_ao;
    GETSYM(p_u,  g_u);
    GETSYM(p_zx, g_zx);
    GETSYM(p_y,  g_y);
    GETSYM(p_tmp, g_tmp);
    GETSYM(p_q,  g_q);
    GETSYM(p_k,  g_k);
    GETSYM(p_v,  g_v);
    GETSYM(p_ao, g_ao);

    const int M = BB*LL;   // 1024

    k_init<<<(BB*LL*DM + 255)/256, 256>>>(hs);
    k_condsilu<<<(BB*DM + 255)/256, 256>>>(ref);
    k_ada<<<(NLAYER*BB*6*DM + 255)/256, 256>>>(ada_w, ada_b);

    for (int l = 0; l < NLAYER; l++) {
        k_prenorm_mod<<<M, 256>>>(l, norm_w);
        sgemm<<<dim3((DIP+127)/128, M/128), 256>>>(p_u, in_w + (size_t)l*DM*DIP, nullptr,
                                                    p_zx, M, DIP, DM);
        k_conv_dt<<<M, 256>>>(l, conv_w, conv_b, dt_bias, A_log);
        k_scan<<<dim3(BB*NH, 2), 256>>>(l, D_ssm);
        k_gatenorm<<<M, 256>>>(l, ssm_nw);
        sgemm<<<dim3(DM/128, M/128), 256>>>(p_y, out_w + (size_t)l*DI*DM, out_b + l*DM,
                                             p_tmp, M, DM, DI);
        k_post_mamba<<<M, 256>>>(l);
        sgemm<<<dim3(AINNER/128, M/128), 256>>>(p_u, q_w + (size_t)l*DM*AINNER, nullptr,
                                                 p_q, M, AINNER, DM);
        sgemm<<<dim3(AINNER/128, 1), 256>>>(ref, k_w + (size_t)l*DM*AINNER, nullptr,
                                             p_k, BB*LCC, AINNER, DM);
        sgemm<<<dim3(AINNER/128, 1), 256>>>(ref, v_w + (size_t)l*DM*AINNER, nullptr,
                                             p_v, BB*LCC, AINNER, DM);
        k_attn<<<dim3(LL/16, AHH, BB), 512>>>();
        sgemm<<<dim3(DM/128, M/128), 256>>>(p_ao, o_w + (size_t)l*AINNER*DM, o_b + l*DM,
                                             p_tmp, M, DM, AINNER);
        k_post_attn<<<(BB*LL*DM + 255)/256, 256>>>(l);
    }
    k_final<<<M, 256>>>(norm_f_w, out);
}

// round 4
// speedup vs baseline: 1.5362x; 1.5362x over previous
#include <cuda_runtime.h>
#include <cuda_bf16.h>
#include <math.h>
#include <stdint.h>

#define BB 2
#define LL 512
#define LCC 64
#define DM 768
#define DI 1536
#define NH 24
#define HD 64
#define DSTATE 128
#define CONVD 1792
#define DIP 3352
#define NLAYER 8
#define AHH 8
#define ADD 64
#define AINNER 512

// ---------------- scratch (device globals; no allocation allowed) ----------------
__device__ float g_hidden[BB*LL*DM];
__device__ float g_resid [BB*LL*DM];
__device__ float g_u     [BB*LL*DM];
__device__ float g_tmp   [BB*LL*DM];
__device__ float g_zx    [BB*LL*DIP];
__device__ float g_xBC   [BB*LL*CONVD];
__device__ float g_dt    [BB*LL*NH];
__device__ float g_dA    [BB*LL*NH];
__device__ float g_y     [BB*LL*DI];
__device__ float g_q     [BB*LL*AINNER];
__device__ float g_k     [BB*LCC*AINNER];
__device__ float g_v     [BB*LCC*AINNER];
__device__ float g_ao    [BB*LL*AINNER];
__device__ float g_aff   [NLAYER*BB*6*DM];
__device__ float g_csilu [BB*DM];

__device__ __forceinline__ float siluf(float x) { return x / (1.f + expf(-x)); }

__device__ __forceinline__ float block_reduce_sum(float v) {
    __shared__ float red_s[33];
    int lane = threadIdx.x & 31;
    int wid  = threadIdx.x >> 5;
    #pragma unroll
    for (int o = 16; o > 0; o >>= 1) v += __shfl_xor_sync(0xffffffffu, v, o);
    if (lane == 0) red_s[wid] = v;
    __syncthreads();
    int nw = (blockDim.x + 31) >> 5;
    if (wid == 0) {
        float x = (lane < nw) ? red_s[lane] : 0.f;
        #pragma unroll
        for (int o = 16; o > 0; o >>= 1) x += __shfl_xor_sync(0xffffffffu, x, o);
        if (lane == 0) red_s[32] = x;
    }
    __syncthreads();
    float r = red_s[32];
    __syncthreads();
    return r;
}

// ---------------- init ----------------
__global__ void k_init(const float* __restrict__ hs) {
    int i = blockIdx.x * 256 + threadIdx.x;
    if (i < BB*LL*DM) { g_hidden[i] = hs[i]; g_resid[i] = 0.f; }
}

__global__ void k_condsilu(const float* __restrict__ ref) {
    int i = blockIdx.x * 256 + threadIdx.x;
    if (i >= BB*DM) return;
    int b = i / DM, d = i % DM;
    float s = 0.f;
    for (int m = 0; m < LCC; m++) s += ref[(b*LCC + m)*DM + d];
    s *= (1.f / LCC);
    g_csilu[i] = siluf(s);
}

__global__ void k_ada(const float* __restrict__ ada_w, const float* __restrict__ ada_b) {
    int i = blockIdx.x * 256 + threadIdx.x;
    if (i >= NLAYER*BB*6*DM) return;
    int j  = i % (6*DM);
    int lb = i / (6*DM);
    int b  = lb % BB;
    int l  = lb / BB;
    float s = ada_b[l*6*DM + j];
    const float* cs = &g_csilu[b*DM];
    const float* w  = ada_w + (size_t)l*DM*6*DM + j;
    for (int d = 0; d < DM; d++) s += cs[d] * w[(size_t)d*6*DM];
    g_aff[i] = s;
}

// ================= tensor-core split-bf16 GEMM =================
// C[M,N] = A[M,K] @ W[K,N] (+bias), fp32 in/out, 3xBF16 split for accuracy.
// M % 128 == 0, K % 32 == 0; N arbitrary (guarded).

__device__ __forceinline__ void ldsm4(uint32_t* r, uint32_t addr) {
    asm volatile("ldmatrix.sync.aligned.m8n8.x4.shared.b16 {%0,%1,%2,%3}, [%4];"
        : "=r"(r[0]), "=r"(r[1]), "=r"(r[2]), "=r"(r[3]) : "r"(addr));
}
__device__ __forceinline__ void ldsm4t(uint32_t* r, uint32_t addr) {
    asm volatile("ldmatrix.sync.aligned.m8n8.x4.trans.shared.b16 {%0,%1,%2,%3}, [%4];"
        : "=r"(r[0]), "=r"(r[1]), "=r"(r[2]), "=r"(r[3]) : "r"(addr));
}
__device__ __forceinline__ void mma_bf16(float* d, const uint32_t* a, uint32_t b0, uint32_t b1) {
    asm volatile("mma.sync.aligned.m16n8k16.row.col.f32.bf16.bf16.f32 "
        "{%0,%1,%2,%3}, {%4,%5,%6,%7}, {%8,%9}, {%0,%1,%2,%3};"
        : "+f"(d[0]), "+f"(d[1]), "+f"(d[2]), "+f"(d[3])
        : "r"(a[0]), "r"(a[1]), "r"(a[2]), "r"(a[3]), "r"(b0), "r"(b1));
}

#define AP 40   // A smem row pitch (bf16)
#define BP 136  // B smem row pitch (bf16)

__global__ __launch_bounds__(256) void sgemm_tc(const float* __restrict__ A,
                                                const float* __restrict__ W,
                                                const float* __restrict__ bias,
                                                float* __restrict__ C,
                                                int M, int N, int K) {
    __shared__ __nv_bfloat16 As_hi[128*AP];
    __shared__ __nv_bfloat16 As_lo[128*AP];
    __shared__ __nv_bfloat16 Bs_hi[32*BP];
    __shared__ __nv_bfloat16 Bs_lo[32*BP];

    int tid = threadIdx.x;
    int n0 = blockIdx.x * 128, m0 = blockIdx.y * 128;
    int warp = tid >> 5, lane = tid & 31;
    int wm = warp >> 2, wn = warp & 3;

    float acc[4][4][4];
    #pragma unroll
    for (int i = 0; i < 4; i++)
        #pragma unroll
        for (int j = 0; j < 4; j++)
            #pragma unroll
            for (int v = 0; v < 4; v++) acc[i][j][v] = 0.f;

    int ar = tid >> 1, ac0 = (tid & 1) * 16;   // A: row, 16-float chunk
    int br = tid >> 3, bc0 = (tid & 7) * 16;   // B: row, 16-float chunk

    for (int k0 = 0; k0 < K; k0 += 32) {
        // ---- load + split A tile (128 x 32 floats) ----
        {
            const float* ap = A + (size_t)(m0 + ar)*K + k0 + ac0;
            float v[16];
            #pragma unroll
            for (int q = 0; q < 4; q++)
                *reinterpret_cast<float4*>(&v[q*4]) = *reinterpret_cast<const float4*>(ap + q*4);
            __nv_bfloat16 h[16], lo[16];
            #pragma unroll
            for (int i = 0; i < 16; i++) {
                h[i]  = __float2bfloat16(v[i]);
                lo[i] = __float2bfloat16(v[i] - __bfloat162float(h[i]));
            }
            #pragma unroll
            for (int i = 0; i < 16; i++) {
                As_hi[ar*AP + ac0 + i] = h[i];
                As_lo[ar*AP + ac0 + i] = lo[i];
            }
        }
        // ---- load + split B tile (32 x 128 floats), N-guarded ----
        {
            const float* bp = W + (size_t)(k0 + br)*N + n0 + bc0;
            float v[16];
            #pragma unroll
            for (int q = 0; q < 4; q++) {
                int c = bc0 + q*4;
                if (n0 + c + 3 < N) {
                    *reinterpret_cast<float4*>(&v[q*4]) = *reinterpret_cast<const float4*>(bp + q*4);
                } else {
                    #pragma unroll
                    for (int e = 0; e < 4; e++)
                        v[q*4+e] = (n0 + c + e < N) ? bp[q*4+e] : 0.f;
                }
            }
            __nv_bfloat16 h[16], lo[16];
            #pragma unroll
            for (int i = 0; i < 16; i++) {
                h[i]  = __float2bfloat16(v[i]);
                lo[i] = __float2bfloat16(v[i] - __bfloat162float(h[i]));
            }
            #pragma unroll
            for (int i = 0; i < 16; i++) {
                Bs_hi[br*BP + bc0 + i] = h[i];
                Bs_lo[br*BP + bc0 + i] = lo[i];
            }
        }
        __syncthreads();

        // ---- compute ----
        #pragma unroll
        for (int kt = 0; kt < 2; kt++) {
            int kk = kt * 16;
            uint32_t ah[4][4], al[4][4];
            #pragma unroll
            for (int mt = 0; mt < 4; mt++) {
                int r = wm*64 + mt*16 + (lane & 15);
                int c = kk + (lane >> 4)*8;
                ldsm4(ah[mt], (uint32_t)__cvta_generic_to_shared(&As_hi[r*AP + c]));
                ldsm4(al[mt], (uint32_t)__cvta_generic_to_shared(&As_lo[r*AP + c]));
            }
            uint32_t bh[2][4], bl[2][4];
            #pragma unroll
            for (int np = 0; np < 2; np++) {
                int kr = kk + (lane & 15);
                int c  = wn*32 + np*16 + (lane >> 4)*8;
                ldsm4t(bh[np], (uint32_t)__cvta_generic_to_shared(&Bs_hi[kr*BP + c]));
                ldsm4t(bl[np], (uint32_t)__cvta_generic_to_shared(&Bs_lo[kr*BP + c]));
            }
            #pragma unroll
            for (int mt = 0; mt < 4; mt++)
                #pragma unroll
                for (int nt = 0; nt < 4; nt++) {
                    int np = nt >> 1, s = (nt & 1)*2;
                    mma_bf16(acc[mt][nt], ah[mt], bh[np][s], bh[np][s+1]);
                    mma_bf16(acc[mt][nt], ah[mt], bl[np][s], bl[np][s+1]);
                    mma_bf16(acc[mt][nt], al[mt], bh[np][s], bh[np][s+1]);
                }
        }
        __syncthreads();
    }

    // ---- epilogue ----
    int gr = lane >> 2, gc = (lane & 3)*2;
    #pragma unroll
    for (int mt = 0; mt < 4; mt++) {
        #pragma unroll
        for (int nt = 0; nt < 4; nt++) {
            int row0 = m0 + wm*64 + mt*16 + gr;
            int col0 = n0 + wn*32 + nt*8 + gc;
            float b0 = 0.f, b1 = 0.f;
            if (bias) {
                if (col0     < N) b0 = bias[col0];
                if (col0 + 1 < N) b1 = bias[col0+1];
            }
            if (col0 < N) {
                C[(size_t)row0*N + col0]     = acc[mt][nt][0] + b0;
                C[(size_t)(row0+8)*N + col0] = acc[mt][nt][2] + b0;
            }
            if (col0 + 1 < N) {
                C[(size_t)row0*N + col0+1]     = acc[mt][nt][1] + b1;
                C[(size_t)(row0+8)*N + col0+1] = acc[mt][nt][3] + b1;
            }
        }
    }
}

// ---------------- pre-norm + AdaLN modulation (mamba branch) ----------------
__global__ void k_prenorm_mod(int l, const float* __restrict__ norm_w) {
    int t = blockIdx.x;
    int b = t / LL;
    const float* aff = &g_aff[(l*BB + b)*6*DM];
    float vals[3];
    float ss = 0.f;
    #pragma unroll
    for (int i = 0; i < 3; i++) {
        int d = threadIdx.x + i*256;
        float v = g_resid[t*DM + d] + g_hidden[t*DM + d];
        g_resid[t*DM + d] = v;
        vals[i] = v;
        ss += v*v;
    }
    ss = block_reduce_sum(ss);
    float rstd = rsqrtf(ss * (1.f/DM) + 1e-5f);
    #pragma unroll
    for (int i = 0; i < 3; i++) {
        int d = threadIdx.x + i*256;
        float x = vals[i] * rstd * norm_w[l*DM + d];
        g_hidden[t*DM + d] = x;
        g_u[t*DM + d] = x * (1.f + aff[DM + d]) + aff[d];
    }
}

// ---------------- depthwise causal conv(4) + silu, plus dt/dA ----------------
__global__ void k_conv_dt(int l, const float* __restrict__ conv_w,
                          const float* __restrict__ conv_b,
                          const float* __restrict__ dt_bias,
                          const float* __restrict__ A_log) {
    int t  = blockIdx.x;
    int b  = t / LL, tt = t % LL;
    for (int c = threadIdx.x; c < CONVD; c += 256) {
        const float* wc = conv_w + (l*CONVD + c)*4;
        float acc = conv_b[l*CONVD + c];
        #pragma unroll
        for (int j = 0; j < 4; j++) {
            int ts = tt - 3 + j;
            if (ts >= 0) acc += wc[j] * g_zx[(size_t)(b*LL + ts)*DIP + DI + c];
        }
        g_xBC[(size_t)t*CONVD + c] = siluf(acc);
    }
    if (threadIdx.x < NH) {
        int hh = threadIdx.x;
        float x = g_zx[(size_t)t*DIP + DI + CONVD + hh] + dt_bias[l*NH + hh];
        float dt = (x > 20.f) ? x : log1pf(expf(x));
        g_dt[t*NH + hh] = dt;
        g_dA[t*NH + hh] = expf(-expf(A_log[l*NH + hh]) * dt);
    }
}

// ---------------- SSM selective scan ----------------
#define TCH 8
__global__ __launch_bounds__(256) void k_scan(int l, const float* __restrict__ D_ssm) {
    int bh = blockIdx.x;
    int b = bh / NH, hh = bh % NH;
    int ps = blockIdx.y;
    int tid = threadIdx.x;
    int pl = tid >> 3;
    int p  = ps*32 + pl;
    int ng = tid & 7;
    int nb = ng * 16;
    float hreg[16];
    #pragma unroll
    for (int i = 0; i < 16; i++) hreg[i] = 0.f;

    __shared__ float sx[TCH][32];
    __shared__ float sB[TCH][DSTATE];
    __shared__ float sC[TCH][DSTATE];
    __shared__ float sdt[TCH], sdA[TCH];
    float Dh = D_ssm[l*NH + hh];

    for (int t0 = 0; t0 < LL; t0 += TCH) {
        __syncthreads();
        for (int idx = tid; idx < TCH*288; idx += 256) {
            int st = idx / 288, off = idx % 288;
            size_t tok = (size_t)(b*LL + t0 + st);
            if (off < 32)
                sx[st][off] = g_xBC[tok*CONVD + hh*HD + ps*32 + off];
            else if (off < 160)
                sB[st][off-32] = g_xBC[tok*CONVD + DI + (off-32)];
            else
                sC[st][off-160] = g_xBC[tok*CONVD + DI + DSTATE + (off-160)];
        }
        if (tid < TCH) {
            int tok = b*LL + t0 + tid;
            sdt[tid] = g_dt[tok*NH + hh];
            sdA[tid] = g_dA[tok*NH + hh];
        }
        __syncthreads();
        #pragma unroll
        for (int st = 0; st < TCH; st++) {
            float dtt = sdt[st], dAt = sdA[st];
            float xp  = sx[st][pl];
            float dbx = dtt * xp;
            float y = 0.f;
            #pragma unroll
            for (int i = 0; i < 16; i++) {
                float hv = hreg[i]*dAt + dbx*sB[st][nb+i];
                hreg[i] = hv;
                y += hv * sC[st][nb+i];
            }
            y += __shfl_xor_sync(0xffffffffu, y, 1);
            y += __shfl_xor_sync(0xffffffffu, y, 2);
            y += __shfl_xor_sync(0xffffffffu, y, 4);
            if (ng == 0) {
                int tok = b*LL + t0 + st;
                g_y[(size_t)tok*DI + hh*HD + p] = y + xp * Dh;
            }
        }
    }
}

// ---------------- gated RMS norm ----------------
__global__ void k_gatenorm(int l, const float* __restrict__ ssm_norm_w) {
    int t = blockIdx.x;
    __shared__ float sv[DI];
    float ss = 0.f;
    for (int d = threadIdx.x; d < DI; d += 256) {
        float z = g_zx[(size_t)t*DIP + d];
        float v = g_y[(size_t)t*DI + d] * siluf(z);
        sv[d] = v;
        ss += v*v;
    }
    ss = block_reduce_sum(ss);
    float rstd = rsqrtf(ss * (1.f/DI) + 1e-5f);
    for (int d = threadIdx.x; d < DI; d += 256)
        g_y[(size_t)t*DI + d] = sv[d] * rstd * ssm_norm_w[l*DI + d];
}

// ---------------- hidden += g_mba*tmp ; u = ln_noaffine(hidden)*(1+sc)+sh ----------------
__global__ void k_post_mamba(int l) {
    int t = blockIdx.x;
    int b = t / LL;
    const float* aff = &g_aff[(l*BB + b)*6*DM];
    float vals[3];
    float s1 = 0.f;
    #pragma unroll
    for (int i = 0; i < 3; i++) {
        int d = threadIdx.x + i*256;
        float v = g_hidden[t*DM + d] + aff[2*DM + d] * g_tmp[t*DM + d];
        g_hidden[t*DM + d] = v;
        vals[i] = v;
        s1 += v;
    }
    s1 = block_reduce_sum(s1);
    float mean = s1 * (1.f/DM);
    float s2 = 0.f;
    #pragma unroll
    for (int i = 0; i < 3; i++) { float c = vals[i] - mean; s2 += c*c; }
    s2 = block_reduce_sum(s2);
    float rstd = rsqrtf(s2 * (1.f/DM) + 1e-6f);
    #pragma unroll
    for (int i = 0; i < 3; i++) {
        int d = threadIdx.x + i*256;
        float x = (vals[i] - mean) * rstd;
        g_u[t*DM + d] = x * (1.f + aff[4*DM + d]) + aff[3*DM + d];
    }
}

// ---------------- cross attention core ----------------
__global__ __launch_bounds__(512) void k_attn() {
    int qt = blockIdx.x, hh = blockIdx.y, b = blockIdx.z;
    int warp = threadIdx.x >> 5, lane = threadIdx.x & 31;
    __shared__ float Ks[64][65];
    __shared__ float Vs[64][64];
    __shared__ float Qs[16][64];
    __shared__ float Ps[16][64];
    for (int idx = threadIdx.x; idx < 64*64; idx += 512) {
        int m = idx >> 6, d = idx & 63;
        Ks[m][d] = g_k[(size_t)(b*LCC + m)*AINNER + hh*ADD + d];
        Vs[m][d] = g_v[(size_t)(b*LCC + m)*AINNER + hh*ADD + d];
    }
    for (int idx = threadIdx.x; idx < 16*64; idx += 512) {
        int q = idx >> 6, d = idx & 63;
        Qs[q][d] = g_q[(size_t)(b*LL + qt*16 + q)*AINNER + hh*ADD + d];
    }
    __syncthreads();
    int q = warp;
    float s0 = 0.f, s1 = 0.f;
    #pragma unroll 8
    for (int d = 0; d < 64; d++) {
        float qd = Qs[q][d];
        s0 += qd * Ks[lane][d];
        s1 += qd * Ks[lane+32][d];
    }
    s0 *= 0.125f; s1 *= 0.125f;
    float mx = fmaxf(s0, s1);
    #pragma unroll
    for (int o = 16; o > 0; o >>= 1) mx = fmaxf(mx, __shfl_xor_sync(0xffffffffu, mx, o));
    float e0 = expf(s0 - mx), e1 = expf(s1 - mx);
    float sum = e0 + e1;
    #pragma unroll
    for (int o = 16; o > 0; o >>= 1) sum += __shfl_xor_sync(0xffffffffu, sum, o);
    float inv = 1.f / sum;
    Ps[q][lane] = e0 * inv;
    Ps[q][lane+32] = e1 * inv;
    __syncwarp();
    float o0 = 0.f, o1 = 0.f;
    #pragma unroll 8
    for (int m = 0; m < 64; m++) {
        float pm = Ps[q][m];
        o0 += pm * Vs[m][lane];
        o1 += pm * Vs[m][lane+32];
    }
    size_t base = (size_t)(b*LL + qt*16 + q)*AINNER + hh*ADD;
    g_ao[base + lane]      = o0;
    g_ao[base + lane + 32] = o1;
}

// ---------------- hidden += g_msa * attn_proj ----------------
__global__ void k_post_attn(int l) {
    int i = blockIdx.x * 256 + threadIdx.x;
    if (i >= BB*LL*DM) return;
    int t = i / DM;
    int b = t / LL;
    int d = i % DM;
    g_hidden[i] += g_aff[(l*BB + b)*6*DM + 5*DM + d] * g_tmp[i];
}

// ---------------- final rmsnorm ----------------
__global__ void k_final(const float* __restrict__ norm_f_w, float* __restrict__ out) {
    int t = blockIdx.x;
    float vals[3];
    float ss = 0.f;
    #pragma unroll
    for (int i = 0; i < 3; i++) {
        int d = threadIdx.x + i*256;
        float v = g_hidden[t*DM + d] + g_resid[t*DM + d];
        vals[i] = v;
        ss += v*v;
    }
    ss = block_reduce_sum(ss);
    float rstd = rsqrtf(ss * (1.f/DM) + 1e-5f);
    #pragma unroll
    for (int i = 0; i < 3; i++) {
        int d = threadIdx.x + i*256;
        out[t*DM + d] = vals[i] * rstd * norm_f_w[d];
    }
}

// ---------------- host ----------------
#define GETSYM(p, s) do { void* tmp_; cudaGetSymbolAddress(&tmp_, s); p = (float*)tmp_; } while(0)

extern "C" void kernel_launch(void* const* d_in, const int* in_sizes, int n_in,
                              void* d_out, int out_size) {
    const float* hs        = (const float*)d_in[0];
    const float* ref       = (const float*)d_in[1];
    const float* norm_w    = (const float*)d_in[2];
    const float* ada_w     = (const float*)d_in[3];
    const float* ada_b     = (const float*)d_in[4];
    const float* in_w      = (const float*)d_in[5];
    const float* conv_w    = (const float*)d_in[6];
    const float* conv_b    = (const float*)d_in[7];
    const float* dt_bias   = (const float*)d_in[8];
    const float* A_log     = (const float*)d_in[9];
    const float* D_ssm     = (const float*)d_in[10];
    const float* ssm_nw    = (const float*)d_in[11];
    const float* out_w     = (const float*)d_in[12];
    const float* out_b     = (const float*)d_in[13];
    const float* q_w       = (const float*)d_in[14];
    const float* k_w       = (const float*)d_in[15];
    const float* v_w       = (const float*)d_in[16];
    const float* o_w       = (const float*)d_in[17];
    const float* o_b       = (const float*)d_in[18];
    const float* norm_f_w  = (const float*)d_in[19];
    float* out = (float*)d_out;

    float *p_u, *p_zx, *p_y, *p_tmp, *p_q, *p_k, *p_v, *p_ao;
    GETSYM(p_u,  g_u);
    GETSYM(p_zx, g_zx);
    GETSYM(p_y,  g_y);
    GETSYM(p_tmp, g_tmp);
    GETSYM(p_q,  g_q);
    GETSYM(p_k,  g_k);
    GETSYM(p_v,  g_v);
    GETSYM(p_ao, g_ao);

    const int M = BB*LL;   // 1024

    k_init<<<(BB*LL*DM + 255)/256, 256>>>(hs);
    k_condsilu<<<(BB*DM + 255)/256, 256>>>(ref);
    k_ada<<<(NLAYER*BB*6*DM + 255)/256, 256>>>(ada_w, ada_b);

    for (int l = 0; l < NLAYER; l++) {
        k_prenorm_mod<<<M, 256>>>(l, norm_w);
        sgemm_tc<<<dim3((DIP+127)/128, M/128), 256>>>(p_u, in_w + (size_t)l*DM*DIP, nullptr,
                                                      p_zx, M, DIP, DM);
        k_conv_dt<<<M, 256>>>(l, conv_w, conv_b, dt_bias, A_log);
        k_scan<<<dim3(BB*NH, 2), 256>>>(l, D_ssm);
        k_gatenorm<<<M, 256>>>(l, ssm_nw);
        sgemm_tc<<<dim3(DM/128, M/128), 256>>>(p_y, out_w + (size_t)l*DI*DM, out_b + l*DM,
                                               p_tmp, M, DM, DI);
        k_post_mamba<<<M, 256>>>(l);
        sgemm_tc<<<dim3(AINNER/128, M/128), 256>>>(p_u, q_w + (size_t)l*DM*AINNER, nullptr,
                                                   p_q, M, AINNER, DM);
        sgemm_tc<<<dim3(AINNER/128, 1), 256>>>(ref, k_w + (size_t)l*DM*AINNER, nullptr,
                                               p_k, BB*LCC, AINNER, DM);
        sgemm_tc<<<dim3(AINNER/128, 1), 256>>>(ref, v_w + (size_t)l*DM*AINNER, nullptr,
                                               p_v, BB*LCC, AINNER, DM);
        k_attn<<<dim3(LL/16, AHH, BB), 512>>>();
        sgemm_tc<<<dim3(DM/128, M/128), 256>>>(p_ao, o_w + (size_t)l*AINNER*DM, o_b + l*DM,
                                               p_tmp, M, DM, AINNER);
        k_post_attn<<<(BB*LL*DM + 255)/256, 256>>>(l);
    }
    k_final<<<M, 256>>>(norm_f_w, out);
}

// round 5
// speedup vs baseline: 2.0024x; 1.3034x over previous
#include <cuda_runtime.h>
#include <cuda_bf16.h>
#include <math.h>
#include <stdint.h>

#define BB 2
#define LL 512
#define LCC 64
#define DM 768
#define DI 1536
#define NH 24
#define HD 64
#define DSTATE 128
#define CONVD 1792
#define DIP 3352
#define NLAYER 8
#define AHH 8
#define ADD 64
#define AINNER 512

typedef __nv_bfloat16 bf16;

// ---------------- scratch (device globals; no allocation allowed) ----------------
__device__ float g_hidden[BB*LL*DM];
__device__ float g_resid [BB*LL*DM];
__device__ float g_tmp   [BB*LL*DM];
__device__ float g_zx    [BB*LL*DIP];
__device__ float g_xBC   [BB*LL*CONVD];
__device__ float g_dt    [BB*LL*NH];
__device__ float g_dA    [BB*LL*NH];
__device__ float g_y     [BB*LL*DI];
__device__ float g_q     [BB*LL*AINNER];
__device__ float g_kall  [NLAYER*BB*LCC*AINNER];
__device__ float g_vall  [NLAYER*BB*LCC*AINNER];
__device__ float g_aff   [NLAYER*BB*6*DM];
__device__ float g_csilu [BB*DM];

// split activations (GEMM A inputs)
__device__ bf16 g_u_hi[BB*LL*DM],     g_u_lo[BB*LL*DM];
__device__ bf16 g_y_hi[BB*LL*DI],     g_y_lo[BB*LL*DI];
__device__ bf16 g_ao_hi[BB*LL*AINNER], g_ao_lo[BB*LL*AINNER];
__device__ bf16 g_ref_hi[BB*LCC*DM],  g_ref_lo[BB*LCC*DM];

// split weights (GEMM B inputs)
__device__ bf16 g_wi_hi[NLAYER*DM*DIP],     g_wi_lo[NLAYER*DM*DIP];
__device__ bf16 g_wo_hi[NLAYER*DI*DM],      g_wo_lo[NLAYER*DI*DM];
__device__ bf16 g_wq_hi[NLAYER*DM*AINNER],  g_wq_lo[NLAYER*DM*AINNER];
__device__ bf16 g_wk_hi[NLAYER*DM*AINNER],  g_wk_lo[NLAYER*DM*AINNER];
__device__ bf16 g_wv_hi[NLAYER*DM*AINNER],  g_wv_lo[NLAYER*DM*AINNER];
__device__ bf16 g_wp_hi[NLAYER*AINNER*DM],  g_wp_lo[NLAYER*AINNER*DM];

__device__ __forceinline__ float siluf(float x) { return x / (1.f + expf(-x)); }

__device__ __forceinline__ void split2(float v, bf16* hi, bf16* lo) {
    bf16 h = __float2bfloat16(v);
    *hi = h;
    *lo = __float2bfloat16(v - __bfloat162float(h));
}

__device__ __forceinline__ float block_reduce_sum(float v) {
    __shared__ float red_s[33];
    int lane = threadIdx.x & 31;
    int wid  = threadIdx.x >> 5;
    #pragma unroll
    for (int o = 16; o > 0; o >>= 1) v += __shfl_xor_sync(0xffffffffu, v, o);
    if (lane == 0) red_s[wid] = v;
    __syncthreads();
    int nw = (blockDim.x + 31) >> 5;
    if (wid == 0) {
        float x = (lane < nw) ? red_s[lane] : 0.f;
        #pragma unroll
        for (int o = 16; o > 0; o >>= 1) x += __shfl_xor_sync(0xffffffffu, x, o);
        if (lane == 0) red_s[32] = x;
    }
    __syncthreads();
    float r = red_s[32];
    __syncthreads();
    return r;
}

// ---------------- one-time split kernels ----------------
__global__ void k_split(const float* __restrict__ src, bf16* __restrict__ hi,
                        bf16* __restrict__ lo, int n) {
    int i = blockIdx.x * 256 + threadIdx.x;
    if (i < n) split2(src[i], &hi[i], &lo[i]);
}

// ---------------- init ----------------
__global__ void k_init(const float* __restrict__ hs) {
    int i = blockIdx.x * 256 + threadIdx.x;
    if (i < BB*LL*DM) { g_hidden[i] = hs[i]; g_resid[i] = 0.f; }
}

__global__ void k_condsilu(const float* __restrict__ ref) {
    int i = blockIdx.x * 256 + threadIdx.x;
    if (i >= BB*DM) return;
    int b = i / DM, d = i % DM;
    float s = 0.f;
    for (int m = 0; m < LCC; m++) s += ref[(b*LCC + m)*DM + d];
    s *= (1.f / LCC);
    g_csilu[i] = siluf(s);
}

__global__ void k_ada(const float* __restrict__ ada_w, const float* __restrict__ ada_b) {
    int i = blockIdx.x * 256 + threadIdx.x;
    if (i >= NLAYER*BB*6*DM) return;
    int j  = i % (6*DM);
    int lb = i / (6*DM);
    int b  = lb % BB;
    int l  = lb / BB;
    float s = ada_b[l*6*DM + j];
    const float* cs = &g_csilu[b*DM];
    const float* w  = ada_w + (size_t)l*DM*6*DM + j;
    for (int d = 0; d < DM; d++) s += cs[d] * w[(size_t)d*6*DM];
    g_aff[i] = s;
}

// ================= tensor-core split-bf16 GEMM (pre-split inputs) =================
__device__ __forceinline__ void ldsm4(uint32_t* r, uint32_t addr) {
    asm volatile("ldmatrix.sync.aligned.m8n8.x4.shared.b16 {%0,%1,%2,%3}, [%4];"
        : "=r"(r[0]), "=r"(r[1]), "=r"(r[2]), "=r"(r[3]) : "r"(addr));
}
__device__ __forceinline__ void ldsm4t(uint32_t* r, uint32_t addr) {
    asm volatile("ldmatrix.sync.aligned.m8n8.x4.trans.shared.b16 {%0,%1,%2,%3}, [%4];"
        : "=r"(r[0]), "=r"(r[1]), "=r"(r[2]), "=r"(r[3]) : "r"(addr));
}
__device__ __forceinline__ void mma_bf16(float* d, const uint32_t* a, uint32_t b0, uint32_t b1) {
    asm volatile("mma.sync.aligned.m16n8k16.row.col.f32.bf16.bf16.f32 "
        "{%0,%1,%2,%3}, {%4,%5,%6,%7}, {%8,%9}, {%0,%1,%2,%3};"
        : "+f"(d[0]), "+f"(d[1]), "+f"(d[2]), "+f"(d[3])
        : "r"(a[0]), "r"(a[1]), "r"(a[2]), "r"(a[3]), "r"(b0), "r"(b1));
}
__device__ __forceinline__ void cp16(void* smem, const void* gmem) {
    uint32_t s = (uint32_t)__cvta_generic_to_shared(smem);
    asm volatile("cp.async.cg.shared.global [%0], [%1], 16;" :: "r"(s), "l"(gmem));
}
__device__ __forceinline__ void cp_commit_wait() {
    asm volatile("cp.async.commit_group;");
    asm volatile("cp.async.wait_group 0;");
}

#define AP 40   // A smem pitch (bf16): 80B rows, 16B aligned, conflict-free ldmatrix
#define BP 136  // B smem pitch (bf16): 272B rows, 16B aligned, conflict-free ldmatrix

// C[M,N] = A@W (+bias). A as hi/lo bf16 [M,K]; W as hi/lo bf16 [K,N].
// blockIdx.z batches over W/C (strides in elements). M%128==0, K%32==0, N%8==0.
__global__ __launch_bounds__(256) void gemm_bs(const bf16* __restrict__ Ah,
                                               const bf16* __restrict__ Al,
                                               const bf16* __restrict__ Wh,
                                               const bf16* __restrict__ Wl,
                                               const float* __restrict__ bias,
                                               float* __restrict__ C,
                                               int M, int N, int K,
                                               long wz, long cz) {
    __shared__ bf16 As_hi[128*AP];
    __shared__ bf16 As_lo[128*AP];
    __shared__ bf16 Bs_hi[32*BP];
    __shared__ bf16 Bs_lo[32*BP];

    Wh += (size_t)blockIdx.z * wz;
    Wl += (size_t)blockIdx.z * wz;
    C  += (size_t)blockIdx.z * cz;

    int tid = threadIdx.x;
    int n0 = blockIdx.x * 128, m0 = blockIdx.y * 128;
    int warp = tid >> 5, lane = tid & 31;
    int wm = warp >> 2, wn = warp & 3;

    float acc[4][4][4];
    #pragma unroll
    for (int i = 0; i < 4; i++)
        #pragma unroll
        for (int j = 0; j < 4; j++)
            #pragma unroll
            for (int v = 0; v < 4; v++) acc[i][j][v] = 0.f;

    for (int k0 = 0; k0 < K; k0 += 32) {
        // A tile: 128 rows x 32 cols, 4 x 16B chunks/row, 512 chunks/buffer
        #pragma unroll
        for (int s = 0; s < 2; s++) {
            int c = tid + s*256;
            int row = c >> 2, off = (c & 3) * 8;
            const bf16* src = Ah + (size_t)(m0 + row)*K + k0 + off;
            cp16(&As_hi[row*AP + off], src);
            cp16(&As_lo[row*AP + off], Al + (size_t)(m0 + row)*K + k0 + off);
        }
        // B tile: 32 rows x 128 cols, 16 x 16B chunks/row
        #pragma unroll
        for (int s = 0; s < 2; s++) {
            int c = tid + s*256;
            int row = c >> 4, off = (c & 15) * 8;
            int col = n0 + off;
            if (col < N) {
                cp16(&Bs_hi[row*BP + off], Wh + (size_t)(k0 + row)*N + col);
                cp16(&Bs_lo[row*BP + off], Wl + (size_t)(k0 + row)*N + col);
            } else {
                *reinterpret_cast<uint4*>(&Bs_hi[row*BP + off]) = make_uint4(0,0,0,0);
                *reinterpret_cast<uint4*>(&Bs_lo[row*BP + off]) = make_uint4(0,0,0,0);
            }
        }
        cp_commit_wait();
        __syncthreads();

        #pragma unroll
        for (int kt = 0; kt < 2; kt++) {
            int kk = kt * 16;
            uint32_t ah[4][4], al[4][4];
            #pragma unroll
            for (int mt = 0; mt < 4; mt++) {
                int r = wm*64 + mt*16 + (lane & 15);
                int c = kk + (lane >> 4)*8;
                ldsm4(ah[mt], (uint32_t)__cvta_generic_to_shared(&As_hi[r*AP + c]));
                ldsm4(al[mt], (uint32_t)__cvta_generic_to_shared(&As_lo[r*AP + c]));
            }
            uint32_t bh[2][4], bl[2][4];
            #pragma unroll
            for (int np = 0; np < 2; np++) {
                int kr = kk + (lane & 15);
                int c  = wn*32 + np*16 + (lane >> 4)*8;
                ldsm4t(bh[np], (uint32_t)__cvta_generic_to_shared(&Bs_hi[kr*BP + c]));
                ldsm4t(bl[np], (uint32_t)__cvta_generic_to_shared(&Bs_lo[kr*BP + c]));
            }
            #pragma unroll
            for (int mt = 0; mt < 4; mt++)
                #pragma unroll
                for (int nt = 0; nt < 4; nt++) {
                    int np = nt >> 1, s = (nt & 1)*2;
                    mma_bf16(acc[mt][nt], ah[mt], bh[np][s], bh[np][s+1]);
                    mma_bf16(acc[mt][nt], ah[mt], bl[np][s], bl[np][s+1]);
                    mma_bf16(acc[mt][nt], al[mt], bh[np][s], bh[np][s+1]);
                }
        }
        __syncthreads();
    }

    int gr = lane >> 2, gc = (lane & 3)*2;
    #pragma unroll
    for (int mt = 0; mt < 4; mt++) {
        #pragma unroll
        for (int nt = 0; nt < 4; nt++) {
            int row0 = m0 + wm*64 + mt*16 + gr;
            int col0 = n0 + wn*32 + nt*8 + gc;
            float b0 = 0.f, b1 = 0.f;
            if (bias) {
                if (col0     < N) b0 = bias[col0];
                if (col0 + 1 < N) b1 = bias[col0+1];
            }
            if (col0 < N) {
                C[(size_t)row0*N + col0]     = acc[mt][nt][0] + b0;
                C[(size_t)(row0+8)*N + col0] = acc[mt][nt][2] + b0;
            }
            if (col0 + 1 < N) {
                C[(size_t)row0*N + col0+1]     = acc[mt][nt][1] + b1;
                C[(size_t)(row0+8)*N + col0+1] = acc[mt][nt][3] + b1;
            }
        }
    }
}

// ---------------- pre-norm + AdaLN modulation (mamba branch) ----------------
__global__ void k_prenorm_mod(int l, const float* __restrict__ norm_w) {
    int t = blockIdx.x;
    int b = t / LL;
    const float* aff = &g_aff[(l*BB + b)*6*DM];
    float vals[3];
    float ss = 0.f;
    #pragma unroll
    for (int i = 0; i < 3; i++) {
        int d = threadIdx.x + i*256;
        float v = g_resid[t*DM + d] + g_hidden[t*DM + d];
        g_resid[t*DM + d] = v;
        vals[i] = v;
        ss += v*v;
    }
    ss = block_reduce_sum(ss);
    float rstd = rsqrtf(ss * (1.f/DM) + 1e-5f);
    #pragma unroll
    for (int i = 0; i < 3; i++) {
        int d = threadIdx.x + i*256;
        float x = vals[i] * rstd * norm_w[l*DM + d];
        g_hidden[t*DM + d] = x;
        float u = x * (1.f + aff[DM + d]) + aff[d];
        split2(u, &g_u_hi[t*DM + d], &g_u_lo[t*DM + d]);
    }
}

// ---------------- depthwise causal conv(4) + silu, plus dt/dA ----------------
__global__ void k_conv_dt(int l, const float* __restrict__ conv_w,
                          const float* __restrict__ conv_b,
                          const float* __restrict__ dt_bias,
                          const float* __restrict__ A_log) {
    int t  = blockIdx.x;
    int b  = t / LL, tt = t % LL;
    for (int c = threadIdx.x; c < CONVD; c += 256) {
        const float* wc = conv_w + (l*CONVD + c)*4;
        float acc = conv_b[l*CONVD + c];
        #pragma unroll
        for (int j = 0; j < 4; j++) {
            int ts = tt - 3 + j;
            if (ts >= 0) acc += wc[j] * g_zx[(size_t)(b*LL + ts)*DIP + DI + c];
        }
        g_xBC[(size_t)t*CONVD + c] = siluf(acc);
    }
    if (threadIdx.x < NH) {
        int hh = threadIdx.x;
        float x = g_zx[(size_t)t*DIP + DI + CONVD + hh] + dt_bias[l*NH + hh];
        float dt = (x > 20.f) ? x : log1pf(expf(x));
        g_dt[t*NH + hh] = dt;
        g_dA[t*NH + hh] = expf(-expf(A_log[l*NH + hh]) * dt);
    }
}

// ---------------- SSM selective scan ----------------
#define TCH 8
__global__ __launch_bounds__(256) void k_scan(int l, const float* __restrict__ D_ssm) {
    int bh = blockIdx.x;
    int b = bh / NH, hh = bh % NH;
    int ps = blockIdx.y;
    int tid = threadIdx.x;
    int pl = tid >> 3;
    int p  = ps*32 + pl;
    int ng = tid & 7;
    int nb = ng * 16;
    float hreg[16];
    #pragma unroll
    for (int i = 0; i < 16; i++) hreg[i] = 0.f;

    __shared__ float sx[TCH][32];
    __shared__ float sB[TCH][DSTATE];
    __shared__ float sC[TCH][DSTATE];
    __shared__ float sdt[TCH], sdA[TCH];
    float Dh = D_ssm[l*NH + hh];

    for (int t0 = 0; t0 < LL; t0 += TCH) {
        __syncthreads();
        for (int idx = tid; idx < TCH*288; idx += 256) {
            int st = idx / 288, off = idx % 288;
            size_t tok = (size_t)(b*LL + t0 + st);
            if (off < 32)
                sx[st][off] = g_xBC[tok*CONVD + hh*HD + ps*32 + off];
            else if (off < 160)
                sB[st][off-32] = g_xBC[tok*CONVD + DI + (off-32)];
            else
                sC[st][off-160] = g_xBC[tok*CONVD + DI + DSTATE + (off-160)];
        }
        if (tid < TCH) {
            int tok = b*LL + t0 + tid;
            sdt[tid] = g_dt[tok*NH + hh];
            sdA[tid] = g_dA[tok*NH + hh];
        }
        __syncthreads();
        #pragma unroll
        for (int st = 0; st < TCH; st++) {
            float dtt = sdt[st], dAt = sdA[st];
            float xp  = sx[st][pl];
            float dbx = dtt * xp;
            float y = 0.f;
            #pragma unroll
            for (int i = 0; i < 16; i++) {
                float hv = hreg[i]*dAt + dbx*sB[st][nb+i];
                hreg[i] = hv;
                y += hv * sC[st][nb+i];
            }
            y += __shfl_xor_sync(0xffffffffu, y, 1);
            y += __shfl_xor_sync(0xffffffffu, y, 2);
            y += __shfl_xor_sync(0xffffffffu, y, 4);
            if (ng == 0) {
                int tok = b*LL + t0 + st;
                g_y[(size_t)tok*DI + hh*HD + p] = y + xp * Dh;
            }
        }
    }
}

// ---------------- gated RMS norm -> y hi/lo ----------------
__global__ void k_gatenorm(int l, const float* __restrict__ ssm_norm_w) {
    int t = blockIdx.x;
    __shared__ float sv[DI];
    float ss = 0.f;
    for (int d = threadIdx.x; d < DI; d += 256) {
        float z = g_zx[(size_t)t*DIP + d];
        float v = g_y[(size_t)t*DI + d] * siluf(z);
        sv[d] = v;
        ss += v*v;
    }
    ss = block_reduce_sum(ss);
    float rstd = rsqrtf(ss * (1.f/DI) + 1e-5f);
    for (int d = threadIdx.x; d < DI; d += 256) {
        float v = sv[d] * rstd * ssm_norm_w[l*DI + d];
        split2(v, &g_y_hi[(size_t)t*DI + d], &g_y_lo[(size_t)t*DI + d]);
    }
}

// ---------------- hidden += g_mba*tmp ; u = ln_noaffine(hidden)*(1+sc)+sh ----------------
__global__ void k_post_mamba(int l) {
    int t = blockIdx.x;
    int b = t / LL;
    const float* aff = &g_aff[(l*BB + b)*6*DM];
    float vals[3];
    float s1 = 0.f;
    #pragma unroll
    for (int i = 0; i < 3; i++) {
        int d = threadIdx.x + i*256;
        float v = g_hidden[t*DM + d] + aff[2*DM + d] * g_tmp[t*DM + d];
        g_hidden[t*DM + d] = v;
        vals[i] = v;
        s1 += v;
    }
    s1 = block_reduce_sum(s1);
    float mean = s1 * (1.f/DM);
    float s2 = 0.f;
    #pragma unroll
    for (int i = 0; i < 3; i++) { float c = vals[i] - mean; s2 += c*c; }
    s2 = block_reduce_sum(s2);
    float rstd = rsqrtf(s2 * (1.f/DM) + 1e-6f);
    #pragma unroll
    for (int i = 0; i < 3; i++) {
        int d = threadIdx.x + i*256;
        float x = (vals[i] - mean) * rstd;
        float u = x * (1.f + aff[4*DM + d]) + aff[3*DM + d];
        split2(u, &g_u_hi[t*DM + d], &g_u_lo[t*DM + d]);
    }
}

// ---------------- cross attention core ----------------
__global__ __launch_bounds__(512) void k_attn(int l) {
    int qt = blockIdx.x, hh = blockIdx.y, b = blockIdx.z;
    int warp = threadIdx.x >> 5, lane = threadIdx.x & 31;
    const float* kp = g_kall + (size_t)l*BB*LCC*AINNER;
    const float* vp = g_vall + (size_t)l*BB*LCC*AINNER;
    __shared__ float Ks[64][65];
    __shared__ float Vs[64][64];
    __shared__ float Qs[16][64];
    __shared__ float Ps[16][64];
    for (int idx = threadIdx.x; idx < 64*64; idx += 512) {
        int m = idx >> 6, d = idx & 63;
        Ks[m][d] = kp[(size_t)(b*LCC + m)*AINNER + hh*ADD + d];
        Vs[m][d] = vp[(size_t)(b*LCC + m)*AINNER + hh*ADD + d];
    }
    for (int idx = threadIdx.x; idx < 16*64; idx += 512) {
        int q = idx >> 6, d = idx & 63;
        Qs[q][d] = g_q[(size_t)(b*LL + qt*16 + q)*AINNER + hh*ADD + d];
    }
    __syncthreads();
    int q = warp;
    float s0 = 0.f, s1 = 0.f;
    #pragma unroll 8
    for (int d = 0; d < 64; d++) {
        float qd = Qs[q][d];
        s0 += qd * Ks[lane][d];
        s1 += qd * Ks[lane+32][d];
    }
    s0 *= 0.125f; s1 *= 0.125f;
    float mx = fmaxf(s0, s1);
    #pragma unroll
    for (int o = 16; o > 0; o >>= 1) mx = fmaxf(mx, __shfl_xor_sync(0xffffffffu, mx, o));
    float e0 = expf(s0 - mx), e1 = expf(s1 - mx);
    float sum = e0 + e1;
    #pragma unroll
    for (int o = 16; o > 0; o >>= 1) sum += __shfl_xor_sync(0xffffffffu, sum, o);
    float inv = 1.f / sum;
    Ps[q][lane] = e0 * inv;
    Ps[q][lane+32] = e1 * inv;
    __syncwarp();
    float o0 = 0.f, o1 = 0.f;
    #pragma unroll 8
    for (int m = 0; m < 64; m++) {
        float pm = Ps[q][m];
        o0 += pm * Vs[m][lane];
        o1 += pm * Vs[m][lane+32];
    }
    size_t base = (size_t)(b*LL + qt*16 + q)*AINNER + hh*ADD;
    split2(o0, &g_ao_hi[base + lane],      &g_ao_lo[base + lane]);
    split2(o1, &g_ao_hi[base + lane + 32], &g_ao_lo[base + lane + 32]);
}

// ---------------- hidden += g_msa * attn_proj ----------------
__global__ void k_post_attn(int l) {
    int i = blockIdx.x * 256 + threadIdx.x;
    if (i >= BB*LL*DM) return;
    int t = i / DM;
    int b = t / LL;
    int d = i % DM;
    g_hidden[i] += g_aff[(l*BB + b)*6*DM + 5*DM + d] * g_tmp[i];
}

// ---------------- final rmsnorm ----------------
__global__ void k_final(const float* __restrict__ norm_f_w, float* __restrict__ out) {
    int t = blockIdx.x;
    float vals[3];
    float ss = 0.f;
    #pragma unroll
    for (int i = 0; i < 3; i++) {
        int d = threadIdx.x + i*256;
        float v = g_hidden[t*DM + d] + g_resid[t*DM + d];
        vals[i] = v;
        ss += v*v;
    }
    ss = block_reduce_sum(ss);
    float rstd = rsqrtf(ss * (1.f/DM) + 1e-5f);
    #pragma unroll
    for (int i = 0; i < 3; i++) {
        int d = threadIdx.x + i*256;
        out[t*DM + d] = vals[i] * rstd * norm_f_w[d];
    }
}

// ---------------- host ----------------
#define GETSYM(p, T, s) do { void* tmp_; cudaGetSymbolAddress(&tmp_, s); p = (T*)tmp_; } while(0)

extern "C" void kernel_launch(void* const* d_in, const int* in_sizes, int n_in,
                              void* d_out, int out_size) {
    const float* hs        = (const float*)d_in[0];
    const float* ref       = (const float*)d_in[1];
    const float* norm_w    = (const float*)d_in[2];
    const float* ada_w     = (const float*)d_in[3];
    const float* ada_b     = (const float*)d_in[4];
    const float* in_w      = (const float*)d_in[5];
    const float* conv_w    = (const float*)d_in[6];
    const float* conv_b    = (const float*)d_in[7];
    const float* dt_bias   = (const float*)d_in[8];
    const float* A_log     = (const float*)d_in[9];
    const float* D_ssm     = (const float*)d_in[10];
    const float* ssm_nw    = (const float*)d_in[11];
    const float* out_w     = (const float*)d_in[12];
    const float* out_b     = (const float*)d_in[13];
    const float* q_w       = (const float*)d_in[14];
    const float* k_w       = (const float*)d_in[15];
    const float* v_w       = (const float*)d_in[16];
    const float* o_w       = (const float*)d_in[17];
    const float* o_b       = (const float*)d_in[18];
    const float* norm_f_w  = (const float*)d_in[19];
    float* out = (float*)d_out;

    float *p_zx, *p_y_dummy, *p_tmp, *p_q, *p_kall, *p_vall;
    GETSYM(p_zx,  float, g_zx);
    GETSYM(p_tmp, float, g_tmp);
    GETSYM(p_q,   float, g_q);
    GETSYM(p_kall,float, g_kall);
    GETSYM(p_vall,float, g_vall);
    (void)p_y_dummy;

    bf16 *u_hi,*u_lo,*y_hi,*y_lo,*ao_hi,*ao_lo,*ref_hi,*ref_lo;
    bf16 *wi_hi,*wi_lo,*wo_hi,*wo_lo,*wq_hi,*wq_lo,*wk_hi,*wk_lo,*wv_hi,*wv_lo,*wp_hi,*wp_lo;
    GETSYM(u_hi,  bf16, g_u_hi);   GETSYM(u_lo,  bf16, g_u_lo);
    GETSYM(y_hi,  bf16, g_y_hi);   GETSYM(y_lo,  bf16, g_y_lo);
    GETSYM(ao_hi, bf16, g_ao_hi);  GETSYM(ao_lo, bf16, g_ao_lo);
    GETSYM(ref_hi,bf16, g_ref_hi); GETSYM(ref_lo,bf16, g_ref_lo);
    GETSYM(wi_hi, bf16, g_wi_hi);  GETSYM(wi_lo, bf16, g_wi_lo);
    GETSYM(wo_hi, bf16, g_wo_hi);  GETSYM(wo_lo, bf16, g_wo_lo);
    GETSYM(wq_hi, bf16, g_wq_hi);  GETSYM(wq_lo, bf16, g_wq_lo);
    GETSYM(wk_hi, bf16, g_wk_hi);  GETSYM(wk_lo, bf16, g_wk_lo);
    GETSYM(wv_hi, bf16, g_wv_hi);  GETSYM(wv_lo, bf16, g_wv_lo);
    GETSYM(wp_hi, bf16, g_wp_hi);  GETSYM(wp_lo, bf16, g_wp_lo);

    const int M = BB*LL;   // 1024

    // one-time splits (weights + ref)
    #define SPLIT(src, hi, lo, n) k_split<<<((n)+255)/256, 256>>>(src, hi, lo, n)
    SPLIT(in_w,  wi_hi, wi_lo, NLAYER*DM*DIP);
    SPLIT(out_w, wo_hi, wo_lo, NLAYER*DI*DM);
    SPLIT(q_w,   wq_hi, wq_lo, NLAYER*DM*AINNER);
    SPLIT(k_w,   wk_hi, wk_lo, NLAYER*DM*AINNER);
    SPLIT(v_w,   wv_hi, wv_lo, NLAYER*DM*AINNER);
    SPLIT(o_w,   wp_hi, wp_lo, NLAYER*AINNER*DM);
    SPLIT(ref,   ref_hi, ref_lo, BB*LCC*DM);

    k_init<<<(BB*LL*DM + 255)/256, 256>>>(hs);
    k_condsilu<<<(BB*DM + 255)/256, 256>>>(ref);
    k_ada<<<(NLAYER*BB*6*DM + 255)/256, 256>>>(ada_w, ada_b);

    // batched k/v projections for ALL layers (depend only on ref)
    gemm_bs<<<dim3(AINNER/128, 1, NLAYER), 256>>>(ref_hi, ref_lo, wk_hi, wk_lo, nullptr,
        p_kall, BB*LCC, AINNER, DM, (long)DM*AINNER, (long)BB*LCC*AINNER);
    gemm_bs<<<dim3(AINNER/128, 1, NLAYER), 256>>>(ref_hi, ref_lo, wv_hi, wv_lo, nullptr,
        p_vall, BB*LCC, AINNER, DM, (long)DM*AINNER, (long)BB*LCC*AINNER);

    for (int l = 0; l < NLAYER; l++) {
        k_prenorm_mod<<<M, 256>>>(l, norm_w);
        gemm_bs<<<dim3((DIP+127)/128, M/128), 256>>>(u_hi, u_lo,
            wi_hi + (size_t)l*DM*DIP, wi_lo + (size_t)l*DM*DIP, nullptr,
            p_zx, M, DIP, DM, 0, 0);
        k_conv_dt<<<M, 256>>>(l, conv_w, conv_b, dt_bias, A_log);
        k_scan<<<dim3(BB*NH, 2), 256>>>(l, D_ssm);
        k_gatenorm<<<M, 256>>>(l, ssm_nw);
        gemm_bs<<<dim3(DM/128, M/128), 256>>>(y_hi, y_lo,
            wo_hi + (size_t)l*DI*DM, wo_lo + (size_t)l*DI*DM, out_b + l*DM,
            p_tmp, M, DM, DI, 0, 0);
        k_post_mamba<<<M, 256>>>(l);
        gemm_bs<<<dim3(AINNER/128, M/128), 256>>>(u_hi, u_lo,
            wq_hi + (size_t)l*DM*AINNER, wq_lo + (size_t)l*DM*AINNER, nullptr,
            p_q, M, AINNER, DM, 0, 0);
        k_attn<<<dim3(LL/16, AHH, BB), 512>>>(l);
        gemm_bs<<<dim3(DM/128, M/128), 256>>>(ao_hi, ao_lo,
            wp_hi + (size_t)l*AINNER*DM, wp_lo + (size_t)l*AINNER*DM, o_b + l*DM,
            p_tmp, M, DM, AINNER, 0, 0);
        k_post_attn<<<(BB*LL*DM + 255)/256, 256>>>(l);
    }
    k_final<<<M, 256>>>(norm_f_w, out);
}

// round 6
// speedup vs baseline: 2.1110x; 1.0543x over previous
#include <cuda_runtime.h>
#include <cuda_bf16.h>
#include <math.h>
#include <stdint.h>

#define BB 2
#define LL 512
#define LCC 64
#define DM 768
#define DI 1536
#define NH 24
#define HD 64
#define DSTATE 128
#define CONVD 1792
#define DIP 3352
#define NLAYER 8
#define AHH 8
#define ADD 64
#define AINNER 512

typedef __nv_bfloat16 bf16;

// ---------------- scratch (device globals; no allocation allowed) ----------------
__device__ float g_hidden[BB*LL*DM];
__device__ float g_resid [BB*LL*DM];
__device__ float g_tmp   [BB*LL*DM];
__device__ float g_zx    [BB*LL*DIP];
__device__ float g_xBC   [BB*LL*CONVD];
__device__ float g_dt    [BB*LL*NH];
__device__ float g_dA    [BB*LL*NH];
__device__ float g_y     [BB*LL*DI];
__device__ float g_q     [BB*LL*AINNER];
__device__ float g_kall  [NLAYER*BB*LCC*AINNER];
__device__ float g_vall  [NLAYER*BB*LCC*AINNER];
__device__ float g_aff   [NLAYER*BB*6*DM];
__device__ float g_csilu [BB*DM];

// split activations (GEMM A inputs)
__device__ bf16 g_u_hi[BB*LL*DM],      g_u_lo[BB*LL*DM];
__device__ bf16 g_y_hi[BB*LL*DI],      g_y_lo[BB*LL*DI];
__device__ bf16 g_ao_hi[BB*LL*AINNER], g_ao_lo[BB*LL*AINNER];
__device__ bf16 g_ref_hi[BB*LCC*DM],   g_ref_lo[BB*LCC*DM];

// split weights (GEMM B inputs)
__device__ bf16 g_wi_hi[NLAYER*DM*DIP],     g_wi_lo[NLAYER*DM*DIP];
__device__ bf16 g_wo_hi[NLAYER*DI*DM],      g_wo_lo[NLAYER*DI*DM];
__device__ bf16 g_wq_hi[NLAYER*DM*AINNER],  g_wq_lo[NLAYER*DM*AINNER];
__device__ bf16 g_wk_hi[NLAYER*DM*AINNER],  g_wk_lo[NLAYER*DM*AINNER];
__device__ bf16 g_wv_hi[NLAYER*DM*AINNER],  g_wv_lo[NLAYER*DM*AINNER];
__device__ bf16 g_wp_hi[NLAYER*AINNER*DM],  g_wp_lo[NLAYER*AINNER*DM];

__device__ __forceinline__ float siluf(float x) { return x / (1.f + expf(-x)); }

__device__ __forceinline__ void split2(float v, bf16* hi, bf16* lo) {
    bf16 h = __float2bfloat16(v);
    *hi = h;
    *lo = __float2bfloat16(v - __bfloat162float(h));
}

__device__ __forceinline__ float block_reduce_sum(float v) {
    __shared__ float red_s[33];
    int lane = threadIdx.x & 31;
    int wid  = threadIdx.x >> 5;
    #pragma unroll
    for (int o = 16; o > 0; o >>= 1) v += __shfl_xor_sync(0xffffffffu, v, o);
    if (lane == 0) red_s[wid] = v;
    __syncthreads();
    int nw = (blockDim.x + 31) >> 5;
    if (wid == 0) {
        float x = (lane < nw) ? red_s[lane] : 0.f;
        #pragma unroll
        for (int o = 16; o > 0; o >>= 1) x += __shfl_xor_sync(0xffffffffu, x, o);
        if (lane == 0) red_s[32] = x;
    }
    __syncthreads();
    float r = red_s[32];
    __syncthreads();
    return r;
}

// ---------------- one-time split kernels ----------------
__global__ void k_split(const float* __restrict__ src, bf16* __restrict__ hi,
                        bf16* __restrict__ lo, int n) {
    int i = blockIdx.x * 256 + threadIdx.x;
    if (i < n) split2(src[i], &hi[i], &lo[i]);
}

// ---------------- init ----------------
__global__ void k_init(const float* __restrict__ hs) {
    int i = blockIdx.x * 256 + threadIdx.x;
    if (i < BB*LL*DM) { g_hidden[i] = hs[i]; g_resid[i] = 0.f; }
}

__global__ void k_condsilu(const float* __restrict__ ref) {
    int i = blockIdx.x * 256 + threadIdx.x;
    if (i >= BB*DM) return;
    int b = i / DM, d = i % DM;
    float s = 0.f;
    for (int m = 0; m < LCC; m++) s += ref[(b*LCC + m)*DM + d];
    s *= (1.f / LCC);
    g_csilu[i] = siluf(s);
}

__global__ void k_ada(const float* __restrict__ ada_w, const float* __restrict__ ada_b) {
    int i = blockIdx.x * 256 + threadIdx.x;
    if (i >= NLAYER*BB*6*DM) return;
    int j  = i % (6*DM);
    int lb = i / (6*DM);
    int b  = lb % BB;
    int l  = lb / BB;
    float s = ada_b[l*6*DM + j];
    const float* cs = &g_csilu[b*DM];
    const float* w  = ada_w + (size_t)l*DM*6*DM + j;
    for (int d = 0; d < DM; d++) s += cs[d] * w[(size_t)d*6*DM];
    g_aff[i] = s;
}

// ================= tensor-core split-bf16 GEMM, 2-stage cp.async pipeline =================
__device__ __forceinline__ void ldsm4(uint32_t* r, uint32_t addr) {
    asm volatile("ldmatrix.sync.aligned.m8n8.x4.shared.b16 {%0,%1,%2,%3}, [%4];"
        : "=r"(r[0]), "=r"(r[1]), "=r"(r[2]), "=r"(r[3]) : "r"(addr));
}
__device__ __forceinline__ void ldsm4t(uint32_t* r, uint32_t addr) {
    asm volatile("ldmatrix.sync.aligned.m8n8.x4.trans.shared.b16 {%0,%1,%2,%3}, [%4];"
        : "=r"(r[0]), "=r"(r[1]), "=r"(r[2]), "=r"(r[3]) : "r"(addr));
}
__device__ __forceinline__ void mma_bf16(float* d, const uint32_t* a, uint32_t b0, uint32_t b1) {
    asm volatile("mma.sync.aligned.m16n8k16.row.col.f32.bf16.bf16.f32 "
        "{%0,%1,%2,%3}, {%4,%5,%6,%7}, {%8,%9}, {%0,%1,%2,%3};"
        : "+f"(d[0]), "+f"(d[1]), "+f"(d[2]), "+f"(d[3])
        : "r"(a[0]), "r"(a[1]), "r"(a[2]), "r"(a[3]), "r"(b0), "r"(b1));
}
__device__ __forceinline__ void cp16(void* smem, const void* gmem) {
    uint32_t s = (uint32_t)__cvta_generic_to_shared(smem);
    asm volatile("cp.async.cg.shared.global [%0], [%1], 16;" :: "r"(s), "l"(gmem));
}

#define AP 40    // A smem pitch (bf16)
#define BP 136   // B smem pitch (bf16)
#define OFF_AL (128*AP)           // 5120
#define OFF_BH (2*128*AP)         // 10240
#define OFF_BL (2*128*AP + 32*BP) // 14592
#define STG    (2*128*AP + 2*32*BP) // 18944 bf16 elems per stage
#define GEMM_SMEM_BYTES (2*STG*2)   // 75776 bytes

// C[M,N] = A@W (+bias). A as hi/lo bf16 [M,K]; W as hi/lo bf16 [K,N].
// blockIdx.z batches over W/C. M%128==0, K%32==0, N%8==0.
__global__ __launch_bounds__(256, 2) void gemm_bs(const bf16* __restrict__ Ah,
                                                  const bf16* __restrict__ Al,
                                                  const bf16* __restrict__ Wh,
                                                  const bf16* __restrict__ Wl,
                                                  const float* __restrict__ bias,
                                                  float* __restrict__ C,
                                                  int M, int N, int K,
                                                  long wz, long cz) {
    extern __shared__ bf16 sm[];

    Wh += (size_t)blockIdx.z * wz;
    Wl += (size_t)blockIdx.z * wz;
    C  += (size_t)blockIdx.z * cz;

    int tid = threadIdx.x;
    int n0 = blockIdx.x * 128, m0 = blockIdx.y * 128;
    int warp = tid >> 5, lane = tid & 31;
    int wm = warp >> 2, wn = warp & 3;

    // precompute per-thread load coords
    int a_row = tid >> 1;             // 2 chunks per A row pair... (tid>>1 in 0..127)
    int a_off = (tid & 1) * 16;       // covers cols 0..31 in two 8-elem chunks
    int b_row0 = tid >> 4, b_off = (tid & 15) * 8;

    float acc[4][4][4];
    #pragma unroll
    for (int i = 0; i < 4; i++)
        #pragma unroll
        for (int j = 0; j < 4; j++)
            #pragma unroll
            for (int v = 0; v < 4; v++) acc[i][j][v] = 0.f;

    int nt = K >> 5;

    auto load_tile = [&](int it, int st) {
        bf16* base = sm + st*STG;
        // A tile: 128 x 32, each thread: 2 x 8-elem chunks hi + lo
        {
            const bf16* srch = Ah + (size_t)(m0 + a_row)*K + it*32 + a_off;
            const bf16* srcl = Al + (size_t)(m0 + a_row)*K + it*32 + a_off;
            cp16(&base[a_row*AP + a_off],          srch);
            cp16(&base[a_row*AP + a_off + 8],      srch + 8);
            cp16(&base[OFF_AL + a_row*AP + a_off], srcl);
            cp16(&base[OFF_AL + a_row*AP + a_off + 8], srcl + 8);
        }
        // B tile: 32 x 128, 512 chunks total (2 per thread) hi + lo
        #pragma unroll
        for (int s = 0; s < 2; s++) {
            int row = b_row0 + s*16;
            int col = n0 + b_off;
            if (col < N) {
                cp16(&base[OFF_BH + row*BP + b_off], Wh + (size_t)(it*32 + row)*N + col);
                cp16(&base[OFF_BL + row*BP + b_off], Wl + (size_t)(it*32 + row)*N + col);
            } else {
                *reinterpret_cast<uint4*>(&base[OFF_BH + row*BP + b_off]) = make_uint4(0,0,0,0);
                *reinterpret_cast<uint4*>(&base[OFF_BL + row*BP + b_off]) = make_uint4(0,0,0,0);
            }
        }
        asm volatile("cp.async.commit_group;");
    };

    load_tile(0, 0);

    for (int it = 0; it < nt; it++) {
        if (it + 1 < nt) {
            load_tile(it + 1, (it + 1) & 1);
            asm volatile("cp.async.wait_group 1;");
        } else {
            asm volatile("cp.async.wait_group 0;");
        }
        __syncthreads();

        bf16* base = sm + (it & 1)*STG;
        #pragma unroll
        for (int kt = 0; kt < 2; kt++) {
            int kk = kt * 16;
            uint32_t ah[4][4], al[4][4];
            #pragma unroll
            for (int mt = 0; mt < 4; mt++) {
                int r = wm*64 + mt*16 + (lane & 15);
                int c = kk + (lane >> 4)*8;
                ldsm4(ah[mt], (uint32_t)__cvta_generic_to_shared(&base[r*AP + c]));
                ldsm4(al[mt], (uint32_t)__cvta_generic_to_shared(&base[OFF_AL + r*AP + c]));
            }
            uint32_t bh[2][4], bl[2][4];
            #pragma unroll
            for (int np = 0; np < 2; np++) {
                int kr = kk + (lane & 15);
                int c  = wn*32 + np*16 + (lane >> 4)*8;
                ldsm4t(bh[np], (uint32_t)__cvta_generic_to_shared(&base[OFF_BH + kr*BP + c]));
                ldsm4t(bl[np], (uint32_t)__cvta_generic_to_shared(&base[OFF_BL + kr*BP + c]));
            }
            #pragma unroll
            for (int mt = 0; mt < 4; mt++)
                #pragma unroll
                for (int nt2 = 0; nt2 < 4; nt2++) {
                    int np = nt2 >> 1, s = (nt2 & 1)*2;
                    mma_bf16(acc[mt][nt2], ah[mt], bh[np][s], bh[np][s+1]);
                    mma_bf16(acc[mt][nt2], ah[mt], bl[np][s], bl[np][s+1]);
                    mma_bf16(acc[mt][nt2], al[mt], bh[np][s], bh[np][s+1]);
                }
        }
        __syncthreads();
    }

    int gr = lane >> 2, gc = (lane & 3)*2;
    #pragma unroll
    for (int mt = 0; mt < 4; mt++) {
        #pragma unroll
        for (int nt2 = 0; nt2 < 4; nt2++) {
            int row0 = m0 + wm*64 + mt*16 + gr;
            int col0 = n0 + wn*32 + nt2*8 + gc;
            float b0 = 0.f, b1 = 0.f;
            if (bias) {
                if (col0     < N) b0 = bias[col0];
                if (col0 + 1 < N) b1 = bias[col0+1];
            }
            if (col0 < N) {
                C[(size_t)row0*N + col0]     = acc[mt][nt2][0] + b0;
                C[(size_t)(row0+8)*N + col0] = acc[mt][nt2][2] + b0;
            }
            if (col0 + 1 < N) {
                C[(size_t)row0*N + col0+1]     = acc[mt][nt2][1] + b1;
                C[(size_t)(row0+8)*N + col0+1] = acc[mt][nt2][3] + b1;
            }
        }
    }
}

// ---------------- pre-norm + AdaLN modulation (mamba branch) ----------------
__global__ void k_prenorm_mod(int l, const float* __restrict__ norm_w) {
    int t = blockIdx.x;
    int b = t / LL;
    const float* aff = &g_aff[(l*BB + b)*6*DM];
    float vals[3];
    float ss = 0.f;
    #pragma unroll
    for (int i = 0; i < 3; i++) {
        int d = threadIdx.x + i*256;
        float v = g_resid[t*DM + d] + g_hidden[t*DM + d];
        g_resid[t*DM + d] = v;
        vals[i] = v;
        ss += v*v;
    }
    ss = block_reduce_sum(ss);
    float rstd = rsqrtf(ss * (1.f/DM) + 1e-5f);
    #pragma unroll
    for (int i = 0; i < 3; i++) {
        int d = threadIdx.x + i*256;
        float x = vals[i] * rstd * norm_w[l*DM + d];
        g_hidden[t*DM + d] = x;
        float u = x * (1.f + aff[DM + d]) + aff[d];
        split2(u, &g_u_hi[t*DM + d], &g_u_lo[t*DM + d]);
    }
}

// ---------------- depthwise causal conv(4) + silu, plus dt/dA ----------------
__global__ void k_conv_dt(int l, const float* __restrict__ conv_w,
                          const float* __restrict__ conv_b,
                          const float* __restrict__ dt_bias,
                          const float* __restrict__ A_log) {
    int t  = blockIdx.x;
    int b  = t / LL, tt = t % LL;
    for (int c = threadIdx.x; c < CONVD; c += 256) {
        const float* wc = conv_w + (l*CONVD + c)*4;
        float acc = conv_b[l*CONVD + c];
        #pragma unroll
        for (int j = 0; j < 4; j++) {
            int ts = tt - 3 + j;
            if (ts >= 0) acc += wc[j] * g_zx[(size_t)(b*LL + ts)*DIP + DI + c];
        }
        g_xBC[(size_t)t*CONVD + c] = siluf(acc);
    }
    if (threadIdx.x < NH) {
        int hh = threadIdx.x;
        float x = g_zx[(size_t)t*DIP + DI + CONVD + hh] + dt_bias[l*NH + hh];
        float dt = (x > 20.f) ? x : log1pf(expf(x));
        g_dt[t*NH + hh] = dt;
        g_dA[t*NH + hh] = expf(-expf(A_log[l*NH + hh]) * dt);
    }
}

// ---------------- SSM selective scan ----------------
#define TCH 8
__global__ __launch_bounds__(256) void k_scan(int l, const float* __restrict__ D_ssm) {
    int bh = blockIdx.x;
    int b = bh / NH, hh = bh % NH;
    int ps = blockIdx.y;
    int tid = threadIdx.x;
    int pl = tid >> 3;
    int p  = ps*32 + pl;
    int ng = tid & 7;
    int nb = ng * 16;
    float hreg[16];
    #pragma unroll
    for (int i = 0; i < 16; i++) hreg[i] = 0.f;

    __shared__ float sx[TCH][32];
    __shared__ float sB[TCH][DSTATE];
    __shared__ float sC[TCH][DSTATE];
    __shared__ float sdt[TCH], sdA[TCH];
    float Dh = D_ssm[l*NH + hh];

    for (int t0 = 0; t0 < LL; t0 += TCH) {
        __syncthreads();
        for (int idx = tid; idx < TCH*288; idx += 256) {
            int st = idx / 288, off = idx % 288;
            size_t tok = (size_t)(b*LL + t0 + st);
            if (off < 32)
                sx[st][off] = g_xBC[tok*CONVD + hh*HD + ps*32 + off];
            else if (off < 160)
                sB[st][off-32] = g_xBC[tok*CONVD + DI + (off-32)];
            else
                sC[st][off-160] = g_xBC[tok*CONVD + DI + DSTATE + (off-160)];
        }
        if (tid < TCH) {
            int tok = b*LL + t0 + tid;
            sdt[tid] = g_dt[tok*NH + hh];
            sdA[tid] = g_dA[tok*NH + hh];
        }
        __syncthreads();
        #pragma unroll
        for (int st = 0; st < TCH; st++) {
            float dtt = sdt[st], dAt = sdA[st];
            float xp  = sx[st][pl];
            float dbx = dtt * xp;
            float y = 0.f;
            #pragma unroll
            for (int i = 0; i < 16; i++) {
                float hv = hreg[i]*dAt + dbx*sB[st][nb+i];
                hreg[i] = hv;
                y += hv * sC[st][nb+i];
            }
            y += __shfl_xor_sync(0xffffffffu, y, 1);
            y += __shfl_xor_sync(0xffffffffu, y, 2);
            y += __shfl_xor_sync(0xffffffffu, y, 4);
            if (ng == 0) {
                int tok = b*LL + t0 + st;
                g_y[(size_t)tok*DI + hh*HD + p] = y + xp * Dh;
            }
        }
    }
}

// ---------------- gated RMS norm -> y hi/lo ----------------
__global__ void k_gatenorm(int l, const float* __restrict__ ssm_norm_w) {
    int t = blockIdx.x;
    __shared__ float sv[DI];
    float ss = 0.f;
    for (int d = threadIdx.x; d < DI; d += 256) {
        float z = g_zx[(size_t)t*DIP + d];
        float v = g_y[(size_t)t*DI + d] * siluf(z);
        sv[d] = v;
        ss += v*v;
    }
    ss = block_reduce_sum(ss);
    float rstd = rsqrtf(ss * (1.f/DI) + 1e-5f);
    for (int d = threadIdx.x; d < DI; d += 256) {
        float v = sv[d] * rstd * ssm_norm_w[l*DI + d];
        split2(v, &g_y_hi[(size_t)t*DI + d], &g_y_lo[(size_t)t*DI + d]);
    }
}

// ---------------- hidden += g_mba*tmp ; u = ln_noaffine(hidden)*(1+sc)+sh ----------------
__global__ void k_post_mamba(int l) {
    int t = blockIdx.x;
    int b = t / LL;
    const float* aff = &g_aff[(l*BB + b)*6*DM];
    float vals[3];
    float s1 = 0.f;
    #pragma unroll
    for (int i = 0; i < 3; i++) {
        int d = threadIdx.x + i*256;
        float v = g_hidden[t*DM + d] + aff[2*DM + d] * g_tmp[t*DM + d];
        g_hidden[t*DM + d] = v;
        vals[i] = v;
        s1 += v;
    }
    s1 = block_reduce_sum(s1);
    float mean = s1 * (1.f/DM);
    float s2 = 0.f;
    #pragma unroll
    for (int i = 0; i < 3; i++) { float c = vals[i] - mean; s2 += c*c; }
    s2 = block_reduce_sum(s2);
    float rstd = rsqrtf(s2 * (1.f/DM) + 1e-6f);
    #pragma unroll
    for (int i = 0; i < 3; i++) {
        int d = threadIdx.x + i*256;
        float x = (vals[i] - mean) * rstd;
        float u = x * (1.f + aff[4*DM + d]) + aff[3*DM + d];
        split2(u, &g_u_hi[t*DM + d], &g_u_lo[t*DM + d]);
    }
}

// ---------------- cross attention core ----------------
__global__ __launch_bounds__(512) void k_attn(int l) {
    int qt = blockIdx.x, hh = blockIdx.y, b = blockIdx.z;
    int warp = threadIdx.x >> 5, lane = threadIdx.x & 31;
    const float* kp = g_kall + (size_t)l*BB*LCC*AINNER;
    const float* vp = g_vall + (size_t)l*BB*LCC*AINNER;
    __shared__ float Ks[64][65];
    __shared__ float Vs[64][64];
    __shared__ float Qs[16][64];
    __shared__ float Ps[16][64];
    for (int idx = threadIdx.x; idx < 64*64; idx += 512) {
        int m = idx >> 6, d = idx & 63;
        Ks[m][d] = kp[(size_t)(b*LCC + m)*AINNER + hh*ADD + d];
        Vs[m][d] = vp[(size_t)(b*LCC + m)*AINNER + hh*ADD + d];
    }
    for (int idx = threadIdx.x; idx < 16*64; idx += 512) {
        int q = idx >> 6, d = idx & 63;
        Qs[q][d] = g_q[(size_t)(b*LL + qt*16 + q)*AINNER + hh*ADD + d];
    }
    __syncthreads();
    int q = warp;
    float s0 = 0.f, s1 = 0.f;
    #pragma unroll 8
    for (int d = 0; d < 64; d++) {
        float qd = Qs[q][d];
        s0 += qd * Ks[lane][d];
        s1 += qd * Ks[lane+32][d];
    }
    s0 *= 0.125f; s1 *= 0.125f;
    float mx = fmaxf(s0, s1);
    #pragma unroll
    for (int o = 16; o > 0; o >>= 1) mx = fmaxf(mx, __shfl_xor_sync(0xffffffffu, mx, o));
    float e0 = expf(s0 - mx), e1 = expf(s1 - mx);
    float sum = e0 + e1;
    #pragma unroll
    for (int o = 16; o > 0; o >>= 1) sum += __shfl_xor_sync(0xffffffffu, sum, o);
    float inv = 1.f / sum;
    Ps[q][lane] = e0 * inv;
    Ps[q][lane+32] = e1 * inv;
    __syncwarp();
    float o0 = 0.f, o1 = 0.f;
    #pragma unroll 8
    for (int m = 0; m < 64; m++) {
        float pm = Ps[q][m];
        o0 += pm * Vs[m][lane];
        o1 += pm * Vs[m][lane+32];
    }
    size_t base = (size_t)(b*LL + qt*16 + q)*AINNER + hh*ADD;
    split2(o0, &g_ao_hi[base + lane],      &g_ao_lo[base + lane]);
    split2(o1, &g_ao_hi[base + lane + 32], &g_ao_lo[base + lane + 32]);
}

// ---------------- hidden += g_msa * attn_proj ----------------
__global__ void k_post_attn(int l) {
    int i = blockIdx.x * 256 + threadIdx.x;
    if (i >= BB*LL*DM) return;
    int t = i / DM;
    int b = t / LL;
    int d = i % DM;
    g_hidden[i] += g_aff[(l*BB + b)*6*DM + 5*DM + d] * g_tmp[i];
}

// ---------------- final rmsnorm ----------------
__global__ void k_final(const float* __restrict__ norm_f_w, float* __restrict__ out) {
    int t = blockIdx.x;
    float vals[3];
    float ss = 0.f;
    #pragma unroll
    for (int i = 0; i < 3; i++) {
        int d = threadIdx.x + i*256;
        float v = g_hidden[t*DM + d] + g_resid[t*DM + d];
        vals[i] = v;
        ss += v*v;
    }
    ss = block_reduce_sum(ss);
    float rstd = rsqrtf(ss * (1.f/DM) + 1e-5f);
    #pragma unroll
    for (int i = 0; i < 3; i++) {
        int d = threadIdx.x + i*256;
        out[t*DM + d] = vals[i] * rstd * norm_f_w[d];
    }
}

// ---------------- host ----------------
#define GETSYM(p, T, s) do { void* tmp_; cudaGetSymbolAddress(&tmp_, s); p = (T*)tmp_; } while(0)

extern "C" void kernel_launch(void* const* d_in, const int* in_sizes, int n_in,
                              void* d_out, int out_size) {
    const float* hs        = (const float*)d_in[0];
    const float* ref       = (const float*)d_in[1];
    const float* norm_w    = (const float*)d_in[2];
    const float* ada_w     = (const float*)d_in[3];
    const float* ada_b     = (const float*)d_in[4];
    const float* in_w      = (const float*)d_in[5];
    const float* conv_w    = (const float*)d_in[6];
    const float* conv_b    = (const float*)d_in[7];
    const float* dt_bias   = (const float*)d_in[8];
    const float* A_log     = (const float*)d_in[9];
    const float* D_ssm     = (const float*)d_in[10];
    const float* ssm_nw    = (const float*)d_in[11];
    const float* out_w     = (const float*)d_in[12];
    const float* out_b     = (const float*)d_in[13];
    const float* q_w       = (const float*)d_in[14];
    const float* k_w       = (const float*)d_in[15];
    const float* v_w       = (const float*)d_in[16];
    const float* o_w       = (const float*)d_in[17];
    const float* o_b       = (const float*)d_in[18];
    const float* norm_f_w  = (const float*)d_in[19];
    float* out = (float*)d_out;

    static int smem_set = 0;
    if (!smem_set) {
        cudaFuncSetAttribute(gemm_bs, cudaFuncAttributeMaxDynamicSharedMemorySize,
                             GEMM_SMEM_BYTES);
        smem_set = 1;
    }

    float *p_zx, *p_tmp, *p_q, *p_kall, *p_vall;
    GETSYM(p_zx,  float, g_zx);
    GETSYM(p_tmp, float, g_tmp);
    GETSYM(p_q,   float, g_q);
    GETSYM(p_kall,float, g_kall);
    GETSYM(p_vall,float, g_vall);

    bf16 *u_hi,*u_lo,*y_hi,*y_lo,*ao_hi,*ao_lo,*ref_hi,*ref_lo;
    bf16 *wi_hi,*wi_lo,*wo_hi,*wo_lo,*wq_hi,*wq_lo,*wk_hi,*wk_lo,*wv_hi,*wv_lo,*wp_hi,*wp_lo;
    GETSYM(u_hi,  bf16, g_u_hi);   GETSYM(u_lo,  bf16, g_u_lo);
    GETSYM(y_hi,  bf16, g_y_hi);   GETSYM(y_lo,  bf16, g_y_lo);
    GETSYM(ao_hi, bf16, g_ao_hi);  GETSYM(ao_lo, bf16, g_ao_lo);
    GETSYM(ref_hi,bf16, g_ref_hi); GETSYM(ref_lo,bf16, g_ref_lo);
    GETSYM(wi_hi, bf16, g_wi_hi);  GETSYM(wi_lo, bf16, g_wi_lo);
    GETSYM(wo_hi, bf16, g_wo_hi);  GETSYM(wo_lo, bf16, g_wo_lo);
    GETSYM(wq_hi, bf16, g_wq_hi);  GETSYM(wq_lo, bf16, g_wq_lo);
    GETSYM(wk_hi, bf16, g_wk_hi);  GETSYM(wk_lo, bf16, g_wk_lo);
    GETSYM(wv_hi, bf16, g_wv_hi);  GETSYM(wv_lo, bf16, g_wv_lo);
    GETSYM(wp_hi, bf16, g_wp_hi);  GETSYM(wp_lo, bf16, g_wp_lo);

    const int M = BB*LL;   // 1024

    #define SPLIT(src, hi, lo, n) k_split<<<((n)+255)/256, 256>>>(src, hi, lo, n)
    SPLIT(in_w,  wi_hi, wi_lo, NLAYER*DM*DIP);
    SPLIT(out_w, wo_hi, wo_lo, NLAYER*DI*DM);
    SPLIT(q_w,   wq_hi, wq_lo, NLAYER*DM*AINNER);
    SPLIT(k_w,   wk_hi, wk_lo, NLAYER*DM*AINNER);
    SPLIT(v_w,   wv_hi, wv_lo, NLAYER*DM*AINNER);
    SPLIT(o_w,   wp_hi, wp_lo, NLAYER*AINNER*DM);
    SPLIT(ref,   ref_hi, ref_lo, BB*LCC*DM);

    k_init<<<(BB*LL*DM + 255)/256, 256>>>(hs);
    k_condsilu<<<(BB*DM + 255)/256, 256>>>(ref);
    k_ada<<<(NLAYER*BB*6*DM + 255)/256, 256>>>(ada_w, ada_b);

    gemm_bs<<<dim3(AINNER/128, 1, NLAYER), 256, GEMM_SMEM_BYTES>>>(ref_hi, ref_lo,
        wk_hi, wk_lo, nullptr, p_kall, BB*LCC, AINNER, DM,
        (long)DM*AINNER, (long)BB*LCC*AINNER);
    gemm_bs<<<dim3(AINNER/128, 1, NLAYER), 256, GEMM_SMEM_BYTES>>>(ref_hi, ref_lo,
        wv_hi, wv_lo, nullptr, p_vall, BB*LCC, AINNER, DM,
        (long)DM*AINNER, (long)BB*LCC*AINNER);

    for (int l = 0; l < NLAYER; l++) {
        k_prenorm_mod<<<M, 256>>>(l, norm_w);
        gemm_bs<<<dim3((DIP+127)/128, M/128), 256, GEMM_SMEM_BYTES>>>(u_hi, u_lo,
            wi_hi + (size_t)l*DM*DIP, wi_lo + (size_t)l*DM*DIP, nullptr,
            p_zx, M, DIP, DM, 0, 0);
        k_conv_dt<<<M, 256>>>(l, conv_w, conv_b, dt_bias, A_log);
        k_scan<<<dim3(BB*NH, 2), 256>>>(l, D_ssm);
        k_gatenorm<<<M, 256>>>(l, ssm_nw);
        gemm_bs<<<dim3(DM/128, M/128), 256, GEMM_SMEM_BYTES>>>(y_hi, y_lo,
            wo_hi + (size_t)l*DI*DM, wo_lo + (size_t)l*DI*DM, out_b + l*DM,
            p_tmp, M, DM, DI, 0, 0);
        k_post_mamba<<<M, 256>>>(l);
        gemm_bs<<<dim3(AINNER/128, M/128), 256, GEMM_SMEM_BYTES>>>(u_hi, u_lo,
            wq_hi + (size_t)l*DM*AINNER, wq_lo + (size_t)l*DM*AINNER, nullptr,
            p_q, M, AINNER, DM, 0, 0);
        k_attn<<<dim3(LL/16, AHH, BB), 512>>>(l);
        gemm_bs<<<dim3(DM/128, M/128), 256, GEMM_SMEM_BYTES>>>(ao_hi, ao_lo,
            wp_hi + (size_t)l*AINNER*DM, wp_lo + (size_t)l*AINNER*DM, o_b + l*DM,
            p_tmp, M, DM, AINNER, 0, 0);
        k_post_attn<<<(BB*LL*DM + 255)/256, 256>>>(l);
    }
    k_final<<<M, 256>>>(norm_f_w, out);
}

// round 7
// speedup vs baseline: 2.3377x; 1.1074x over previous
#include <cuda_runtime.h>
#include <cuda_bf16.h>
#include <math.h>
#include <stdint.h>

#define BB 2
#define LL 512
#define LCC 64
#define DM 768
#define DI 1536
#define NH 24
#define HD 64
#define DSTATE 128
#define CONVD 1792
#define DIP 3352
#define NLAYER 8
#define AHH 8
#define ADD 64
#define AINNER 512

typedef __nv_bfloat16 bf16;

// ---------------- scratch ----------------
__device__ float g_hidden[BB*LL*DM];
__device__ float g_resid [BB*LL*DM];
__device__ float g_zx    [BB*LL*DIP];
__device__ float g_xBC   [BB*LL*CONVD];
__device__ float g_dt    [BB*LL*NH];
__device__ float g_dA    [BB*LL*NH];
__device__ float g_y     [BB*LL*DI];
__device__ float g_q     [BB*LL*AINNER];
__device__ float g_kall  [NLAYER*BB*LCC*AINNER];
__device__ float g_vall  [NLAYER*BB*LCC*AINNER];
__device__ float g_aff   [NLAYER*BB*6*DM];
__device__ float g_csilu [BB*DM];

__device__ bf16 g_u_hi[BB*LL*DM],      g_u_lo[BB*LL*DM];
__device__ bf16 g_y_hi[BB*LL*DI],      g_y_lo[BB*LL*DI];
__device__ bf16 g_ao_hi[BB*LL*AINNER], g_ao_lo[BB*LL*AINNER];
__device__ bf16 g_ref_hi[BB*LCC*DM],   g_ref_lo[BB*LCC*DM];

__device__ bf16 g_wi_hi[NLAYER*DM*DIP],     g_wi_lo[NLAYER*DM*DIP];
__device__ bf16 g_wo_hi[NLAYER*DI*DM],      g_wo_lo[NLAYER*DI*DM];
__device__ bf16 g_wq_hi[NLAYER*DM*AINNER],  g_wq_lo[NLAYER*DM*AINNER];
__device__ bf16 g_wk_hi[NLAYER*DM*AINNER],  g_wk_lo[NLAYER*DM*AINNER];
__device__ bf16 g_wv_hi[NLAYER*DM*AINNER],  g_wv_lo[NLAYER*DM*AINNER];
__device__ bf16 g_wp_hi[NLAYER*AINNER*DM],  g_wp_lo[NLAYER*AINNER*DM];

__device__ __forceinline__ float siluf(float x) { return x / (1.f + expf(-x)); }

__device__ __forceinline__ void split2(float v, bf16* hi, bf16* lo) {
    bf16 h = __float2bfloat16(v);
    *hi = h;
    *lo = __float2bfloat16(v - __bfloat162float(h));
}

__device__ __forceinline__ float block_reduce_sum(float v) {
    __shared__ float red_s[33];
    int lane = threadIdx.x & 31;
    int wid  = threadIdx.x >> 5;
    #pragma unroll
    for (int o = 16; o > 0; o >>= 1) v += __shfl_xor_sync(0xffffffffu, v, o);
    if (lane == 0) red_s[wid] = v;
    __syncthreads();
    int nw = (blockDim.x + 31) >> 5;
    if (wid == 0) {
        float x = (lane < nw) ? red_s[lane] : 0.f;
        #pragma unroll
        for (int o = 16; o > 0; o >>= 1) x += __shfl_xor_sync(0xffffffffu, x, o);
        if (lane == 0) red_s[32] = x;
    }
    __syncthreads();
    float r = red_s[32];
    __syncthreads();
    return r;
}

__global__ void k_split(const float* __restrict__ src, bf16* __restrict__ hi,
                        bf16* __restrict__ lo, int n) {
    int i = blockIdx.x * 256 + threadIdx.x;
    if (i < n) split2(src[i], &hi[i], &lo[i]);
}

__global__ void k_init(const float* __restrict__ hs) {
    int i = blockIdx.x * 256 + threadIdx.x;
    if (i < BB*LL*DM) { g_hidden[i] = hs[i]; g_resid[i] = 0.f; }
}

__global__ void k_condsilu(const float* __restrict__ ref) {
    int i = blockIdx.x * 256 + threadIdx.x;
    if (i >= BB*DM) return;
    int b = i / DM, d = i % DM;
    float s = 0.f;
    for (int m = 0; m < LCC; m++) s += ref[(b*LCC + m)*DM + d];
    s *= (1.f / LCC);
    g_csilu[i] = siluf(s);
}

__global__ void k_ada(const float* __restrict__ ada_w, const float* __restrict__ ada_b) {
    int i = blockIdx.x * 256 + threadIdx.x;
    if (i >= NLAYER*BB*6*DM) return;
    int j  = i % (6*DM);
    int lb = i / (6*DM);
    int b  = lb % BB;
    int l  = lb / BB;
    float s = ada_b[l*6*DM + j];
    const float* cs = &g_csilu[b*DM];
    const float* w  = ada_w + (size_t)l*DM*6*DM + j;
    for (int d = 0; d < DM; d++) s += cs[d] * w[(size_t)d*6*DM];
    g_aff[i] = s;
}

// ================= tensor-core split-bf16 GEMM primitives =================
__device__ __forceinline__ void ldsm4(uint32_t* r, uint32_t addr) {
    asm volatile("ldmatrix.sync.aligned.m8n8.x4.shared.b16 {%0,%1,%2,%3}, [%4];"
        : "=r"(r[0]), "=r"(r[1]), "=r"(r[2]), "=r"(r[3]) : "r"(addr));
}
__device__ __forceinline__ void ldsm4t(uint32_t* r, uint32_t addr) {
    asm volatile("ldmatrix.sync.aligned.m8n8.x4.trans.shared.b16 {%0,%1,%2,%3}, [%4];"
        : "=r"(r[0]), "=r"(r[1]), "=r"(r[2]), "=r"(r[3]) : "r"(addr));
}
__device__ __forceinline__ void mma_bf16(float* d, const uint32_t* a, uint32_t b0, uint32_t b1) {
    asm volatile("mma.sync.aligned.m16n8k16.row.col.f32.bf16.bf16.f32 "
        "{%0,%1,%2,%3}, {%4,%5,%6,%7}, {%8,%9}, {%0,%1,%2,%3};"
        : "+f"(d[0]), "+f"(d[1]), "+f"(d[2]), "+f"(d[3])
        : "r"(a[0]), "r"(a[1]), "r"(a[2]), "r"(a[3]), "r"(b0), "r"(b1));
}
__device__ __forceinline__ void cp16(void* smem, const void* gmem) {
    uint32_t s = (uint32_t)__cvta_generic_to_shared(smem);
    asm volatile("cp.async.cg.shared.global [%0], [%1], 16;" :: "r"(s), "l"(gmem));
}

// ---------------- 128x128 tile kernel (large GEMM: in_proj) ----------------
#define AP 40
#define BP 136
#define OFF_AL (128*AP)
#define OFF_BH (2*128*AP)
#define OFF_BL (2*128*AP + 32*BP)
#define STG    (2*128*AP + 2*32*BP)
#define GEMM_SMEM_BYTES (2*STG*2)

__global__ __launch_bounds__(256, 2) void gemm_bs(const bf16* __restrict__ Ah,
                                                  const bf16* __restrict__ Al,
                                                  const bf16* __restrict__ Wh,
                                                  const bf16* __restrict__ Wl,
                                                  float* __restrict__ C,
                                                  int M, int N, int K) {
    extern __shared__ bf16 sm[];
    int tid = threadIdx.x;
    int n0 = blockIdx.x * 128, m0 = blockIdx.y * 128;
    int warp = tid >> 5, lane = tid & 31;
    int wm = warp >> 2, wn = warp & 3;

    int a_row = tid >> 1, a_off = (tid & 1) * 16;
    int b_row0 = tid >> 4, b_off = (tid & 15) * 8;

    float acc[4][4][4];
    #pragma unroll
    for (int i = 0; i < 4; i++)
        #pragma unroll
        for (int j = 0; j < 4; j++)
            #pragma unroll
            for (int v = 0; v < 4; v++) acc[i][j][v] = 0.f;

    int nt = K >> 5;

    auto load_tile = [&](int it, int st) {
        bf16* base = sm + st*STG;
        const bf16* srch = Ah + (size_t)(m0 + a_row)*K + it*32 + a_off;
        const bf16* srcl = Al + (size_t)(m0 + a_row)*K + it*32 + a_off;
        cp16(&base[a_row*AP + a_off],          srch);
        cp16(&base[a_row*AP + a_off + 8],      srch + 8);
        cp16(&base[OFF_AL + a_row*AP + a_off], srcl);
        cp16(&base[OFF_AL + a_row*AP + a_off + 8], srcl + 8);
        #pragma unroll
        for (int s = 0; s < 2; s++) {
            int row = b_row0 + s*16;
            int col = n0 + b_off;
            if (col < N) {
                cp16(&base[OFF_BH + row*BP + b_off], Wh + (size_t)(it*32 + row)*N + col);
                cp16(&base[OFF_BL + row*BP + b_off], Wl + (size_t)(it*32 + row)*N + col);
            } else {
                *reinterpret_cast<uint4*>(&base[OFF_BH + row*BP + b_off]) = make_uint4(0,0,0,0);
                *reinterpret_cast<uint4*>(&base[OFF_BL + row*BP + b_off]) = make_uint4(0,0,0,0);
            }
        }
        asm volatile("cp.async.commit_group;");
    };

    load_tile(0, 0);

    for (int it = 0; it < nt; it++) {
        if (it + 1 < nt) {
            load_tile(it + 1, (it + 1) & 1);
            asm volatile("cp.async.wait_group 1;");
        } else {
            asm volatile("cp.async.wait_group 0;");
        }
        __syncthreads();

        bf16* base = sm + (it & 1)*STG;
        #pragma unroll
        for (int kt = 0; kt < 2; kt++) {
            int kk = kt * 16;
            uint32_t ah[4][4], al[4][4];
            #pragma unroll
            for (int mt = 0; mt < 4; mt++) {
                int r = wm*64 + mt*16 + (lane & 15);
                int c = kk + (lane >> 4)*8;
                ldsm4(ah[mt], (uint32_t)__cvta_generic_to_shared(&base[r*AP + c]));
                ldsm4(al[mt], (uint32_t)__cvta_generic_to_shared(&base[OFF_AL + r*AP + c]));
            }
            uint32_t bh[2][4], bl[2][4];
            #pragma unroll
            for (int np = 0; np < 2; np++) {
                int kr = kk + (lane & 15);
                int c  = wn*32 + np*16 + (lane >> 4)*8;
                ldsm4t(bh[np], (uint32_t)__cvta_generic_to_shared(&base[OFF_BH + kr*BP + c]));
                ldsm4t(bl[np], (uint32_t)__cvta_generic_to_shared(&base[OFF_BL + kr*BP + c]));
            }
            #pragma unroll
            for (int mt = 0; mt < 4; mt++)
                #pragma unroll
                for (int nt2 = 0; nt2 < 4; nt2++) {
                    int np = nt2 >> 1, s = (nt2 & 1)*2;
                    mma_bf16(acc[mt][nt2], ah[mt], bh[np][s], bh[np][s+1]);
                    mma_bf16(acc[mt][nt2], ah[mt], bl[np][s], bl[np][s+1]);
                    mma_bf16(acc[mt][nt2], al[mt], bh[np][s], bh[np][s+1]);
                }
        }
        __syncthreads();
    }

    int gr = lane >> 2, gc = (lane & 3)*2;
    #pragma unroll
    for (int mt = 0; mt < 4; mt++) {
        #pragma unroll
        for (int nt2 = 0; nt2 < 4; nt2++) {
            int row0 = m0 + wm*64 + mt*16 + gr;
            int col0 = n0 + wn*32 + nt2*8 + gc;
            if (col0 < N) {
                C[(size_t)row0*N + col0]     = acc[mt][nt2][0];
                C[(size_t)(row0+8)*N + col0] = acc[mt][nt2][2];
            }
            if (col0 + 1 < N) {
                C[(size_t)row0*N + col0+1]     = acc[mt][nt2][1];
                C[(size_t)(row0+8)*N + col0+1] = acc[mt][nt2][3];
            }
        }
    }
}

// ---------------- 64x64 tile kernel (small GEMMs; optional gate-accum epilogue) ----------------
#define AP64 40
#define BP64 72
#define S64_OFF_AL (64*AP64)
#define S64_OFF_BH (2*64*AP64)
#define S64_OFF_BL (2*64*AP64 + 32*BP64)
#define S64_STG    (2*64*AP64 + 2*32*BP64)
#define S64_BYTES  (2*S64_STG*2)

// If gate != nullptr: C[row,col] += gate[(row/LL)*6*DM + col] * (acc + bias[col])
// else               C[row,col]  = acc + (bias ? bias[col] : 0)
__global__ __launch_bounds__(256) void gemm_bs64(const bf16* __restrict__ Ah,
                                                 const bf16* __restrict__ Al,
                                                 const bf16* __restrict__ Wh,
                                                 const bf16* __restrict__ Wl,
                                                 const float* __restrict__ bias,
                                                 const float* __restrict__ gate,
                                                 float* __restrict__ C,
                                                 int M, int N, int K,
                                                 long wz, long cz) {
    extern __shared__ bf16 sm[];

    Wh += (size_t)blockIdx.z * wz;
    Wl += (size_t)blockIdx.z * wz;
    C  += (size_t)blockIdx.z * cz;

    int tid = threadIdx.x;
    int n0 = blockIdx.x * 64, m0 = blockIdx.y * 64;
    int warp = tid >> 5, lane = tid & 31;
    int wm = warp >> 2, wn = warp & 3;

    int a_row = tid >> 2, a_off = (tid & 3) * 8;
    int b_row = tid >> 3, b_off = (tid & 7) * 8;

    float acc[2][2][4];
    #pragma unroll
    for (int i = 0; i < 2; i++)
        #pragma unroll
        for (int j = 0; j < 2; j++)
            #pragma unroll
            for (int v = 0; v < 4; v++) acc[i][j][v] = 0.f;

    int nt = K >> 5;

    auto load_tile = [&](int it, int st) {
        bf16* base = sm + st*S64_STG;
        cp16(&base[a_row*AP64 + a_off],              Ah + (size_t)(m0 + a_row)*K + it*32 + a_off);
        cp16(&base[S64_OFF_AL + a_row*AP64 + a_off], Al + (size_t)(m0 + a_row)*K + it*32 + a_off);
        int col = n0 + b_off;
        if (col < N) {
            cp16(&base[S64_OFF_BH + b_row*BP64 + b_off], Wh + (size_t)(it*32 + b_row)*N + col);
            cp16(&base[S64_OFF_BL + b_row*BP64 + b_off], Wl + (size_t)(it*32 + b_row)*N + col);
        } else {
            *reinterpret_cast<uint4*>(&base[S64_OFF_BH + b_row*BP64 + b_off]) = make_uint4(0,0,0,0);
            *reinterpret_cast<uint4*>(&base[S64_OFF_BL + b_row*BP64 + b_off]) = make_uint4(0,0,0,0);
        }
        asm volatile("cp.async.commit_group;");
    };

    load_tile(0, 0);

    for (int it = 0; it < nt; it++) {
        if (it + 1 < nt) {
            load_tile(it + 1, (it + 1) & 1);
            asm volatile("cp.async.wait_group 1;");
        } else {
            asm volatile("cp.async.wait_group 0;");
        }
        __syncthreads();

        bf16* base = sm + (it & 1)*S64_STG;
        #pragma unroll
        for (int kt = 0; kt < 2; kt++) {
            int kk = kt * 16;
            uint32_t ah[2][4], al[2][4];
            #pragma unroll
            for (int mt = 0; mt < 2; mt++) {
                int r = wm*32 + mt*16 + (lane & 15);
                int c = kk + (lane >> 4)*8;
                ldsm4(ah[mt], (uint32_t)__cvta_generic_to_shared(&base[r*AP64 + c]));
                ldsm4(al[mt], (uint32_t)__cvta_generic_to_shared(&base[S64_OFF_AL + r*AP64 + c]));
            }
            uint32_t bh[4], bl[4];
            {
                int kr = kk + (lane & 15);
                int c  = wn*16 + (lane >> 4)*8;
                ldsm4t(bh, (uint32_t)__cvta_generic_to_shared(&base[S64_OFF_BH + kr*BP64 + c]));
                ldsm4t(bl, (uint32_t)__cvta_generic_to_shared(&base[S64_OFF_BL + kr*BP64 + c]));
            }
            #pragma unroll
            for (int mt = 0; mt < 2; mt++)
                #pragma unroll
                for (int nt2 = 0; nt2 < 2; nt2++) {
                    int s = nt2*2;
                    mma_bf16(acc[mt][nt2], ah[mt], bh[s], bh[s+1]);
                    mma_bf16(acc[mt][nt2], ah[mt], bl[s], bl[s+1]);
                    mma_bf16(acc[mt][nt2], al[mt], bh[s], bh[s+1]);
                }
        }
        __syncthreads();
    }

    int gr = lane >> 2, gc = (lane & 3)*2;
    #pragma unroll
    for (int mt = 0; mt < 2; mt++) {
        int row0 = m0 + wm*32 + mt*16 + gr;
        int bidx = row0 / LL;
        #pragma unroll
        for (int nt2 = 0; nt2 < 2; nt2++) {
            int col0 = n0 + wn*16 + nt2*8 + gc;
            float b0 = bias ? bias[col0] : 0.f;
            float b1 = bias ? bias[col0+1] : 0.f;
            float v00 = acc[mt][nt2][0] + b0, v01 = acc[mt][nt2][1] + b1;
            float v10 = acc[mt][nt2][2] + b0, v11 = acc[mt][nt2][3] + b1;
            if (col0 < N) {
                if (gate) {
                    float gv0 = gate[bidx*6*DM + col0];
                    float gv1 = gate[bidx*6*DM + col0 + 1];
                    C[(size_t)row0*N + col0]       += gv0 * v00;
                    C[(size_t)row0*N + col0+1]     += gv1 * v01;
                    C[(size_t)(row0+8)*N + col0]   += gv0 * v10;
                    C[(size_t)(row0+8)*N + col0+1] += gv1 * v11;
                } else {
                    C[(size_t)row0*N + col0]       = v00;
                    C[(size_t)row0*N + col0+1]     = v01;
                    C[(size_t)(row0+8)*N + col0]   = v10;
                    C[(size_t)(row0+8)*N + col0+1] = v11;
                }
            }
        }
    }
}

// ---------------- pre-norm + AdaLN modulation ----------------
__global__ void k_prenorm_mod(int l, const float* __restrict__ norm_w) {
    int t = blockIdx.x;
    int b = t / LL;
    const float* aff = &g_aff[(l*BB + b)*6*DM];
    float vals[3];
    float ss = 0.f;
    #pragma unroll
    for (int i = 0; i < 3; i++) {
        int d = threadIdx.x + i*256;
        float v = g_resid[t*DM + d] + g_hidden[t*DM + d];
        g_resid[t*DM + d] = v;
        vals[i] = v;
        ss += v*v;
    }
    ss = block_reduce_sum(ss);
    float rstd = rsqrtf(ss * (1.f/DM) + 1e-5f);
    #pragma unroll
    for (int i = 0; i < 3; i++) {
        int d = threadIdx.x + i*256;
        float x = vals[i] * rstd * norm_w[l*DM + d];
        g_hidden[t*DM + d] = x;
        float u = x * (1.f + aff[DM + d]) + aff[d];
        split2(u, &g_u_hi[t*DM + d], &g_u_lo[t*DM + d]);
    }
}

// ---------------- conv + dt ----------------
__global__ void k_conv_dt(int l, const float* __restrict__ conv_w,
                          const float* __restrict__ conv_b,
                          const float* __restrict__ dt_bias,
                          const float* __restrict__ A_log) {
    int t  = blockIdx.x;
    int b  = t / LL, tt = t % LL;
    for (int c = threadIdx.x; c < CONVD; c += 256) {
        const float* wc = conv_w + (l*CONVD + c)*4;
        float acc = conv_b[l*CONVD + c];
        #pragma unroll
        for (int j = 0; j < 4; j++) {
            int ts = tt - 3 + j;
            if (ts >= 0) acc += wc[j] * g_zx[(size_t)(b*LL + ts)*DIP + DI + c];
        }
        g_xBC[(size_t)t*CONVD + c] = siluf(acc);
    }
    if (threadIdx.x < NH) {
        int hh = threadIdx.x;
        float x = g_zx[(size_t)t*DIP + DI + CONVD + hh] + dt_bias[l*NH + hh];
        float dt = (x > 20.f) ? x : log1pf(expf(x));
        g_dt[t*NH + hh] = dt;
        g_dA[t*NH + hh] = expf(-expf(A_log[l*NH + hh]) * dt);
    }
}

// ---------------- SSM scan ----------------
#define TCH 8
__global__ __launch_bounds__(256) void k_scan(int l, const float* __restrict__ D_ssm) {
    int bh = blockIdx.x;
    int b = bh / NH, hh = bh % NH;
    int ps = blockIdx.y;
    int tid = threadIdx.x;
    int pl = tid >> 3;
    int p  = ps*32 + pl;
    int ng = tid & 7;
    int nb = ng * 16;
    float hreg[16];
    #pragma unroll
    for (int i = 0; i < 16; i++) hreg[i] = 0.f;

    __shared__ float sx[TCH][32];
    __shared__ float sB[TCH][DSTATE];
    __shared__ float sC[TCH][DSTATE];
    __shared__ float sdt[TCH], sdA[TCH];
    float Dh = D_ssm[l*NH + hh];

    for (int t0 = 0; t0 < LL; t0 += TCH) {
        __syncthreads();
        for (int idx = tid; idx < TCH*288; idx += 256) {
            int st = idx / 288, off = idx % 288;
            size_t tok = (size_t)(b*LL + t0 + st);
            if (off < 32)
                sx[st][off] = g_xBC[tok*CONVD + hh*HD + ps*32 + off];
            else if (off < 160)
                sB[st][off-32] = g_xBC[tok*CONVD + DI + (off-32)];
            else
                sC[st][off-160] = g_xBC[tok*CONVD + DI + DSTATE + (off-160)];
        }
        if (tid < TCH) {
            int tok = b*LL + t0 + tid;
            sdt[tid] = g_dt[tok*NH + hh];
            sdA[tid] = g_dA[tok*NH + hh];
        }
        __syncthreads();
        #pragma unroll
        for (int st = 0; st < TCH; st++) {
            float dtt = sdt[st], dAt = sdA[st];
            float xp  = sx[st][pl];
            float dbx = dtt * xp;
            float y = 0.f;
            #pragma unroll
            for (int i = 0; i < 16; i++) {
                float hv = hreg[i]*dAt + dbx*sB[st][nb+i];
                hreg[i] = hv;
                y += hv * sC[st][nb+i];
            }
            y += __shfl_xor_sync(0xffffffffu, y, 1);
            y += __shfl_xor_sync(0xffffffffu, y, 2);
            y += __shfl_xor_sync(0xffffffffu, y, 4);
            if (ng == 0) {
                int tok = b*LL + t0 + st;
                g_y[(size_t)tok*DI + hh*HD + p] = y + xp * Dh;
            }
        }
    }
}

// ---------------- gated RMS norm -> y hi/lo ----------------
__global__ void k_gatenorm(int l, const float* __restrict__ ssm_norm_w) {
    int t = blockIdx.x;
    __shared__ float sv[DI];
    float ss = 0.f;
    for (int d = threadIdx.x; d < DI; d += 256) {
        float z = g_zx[(size_t)t*DIP + d];
        float v = g_y[(size_t)t*DI + d] * siluf(z);
        sv[d] = v;
        ss += v*v;
    }
    ss = block_reduce_sum(ss);
    float rstd = rsqrtf(ss * (1.f/DI) + 1e-5f);
    for (int d = threadIdx.x; d < DI; d += 256) {
        float v = sv[d] * rstd * ssm_norm_w[l*DI + d];
        split2(v, &g_y_hi[(size_t)t*DI + d], &g_y_lo[(size_t)t*DI + d]);
    }
}

// ---------------- u = ln_noaffine(hidden)*(1+sc_msa)+sh_msa (hidden already accumulated) ----------------
__global__ void k_post_mamba(int l) {
    int t = blockIdx.x;
    int b = t / LL;
    const float* aff = &g_aff[(l*BB + b)*6*DM];
    float vals[3];
    float s1 = 0.f;
    #pragma unroll
    for (int i = 0; i < 3; i++) {
        int d = threadIdx.x + i*256;
        float v = g_hidden[t*DM + d];
        vals[i] = v;
        s1 += v;
    }
    s1 = block_reduce_sum(s1);
    float mean = s1 * (1.f/DM);
    float s2 = 0.f;
    #pragma unroll
    for (int i = 0; i < 3; i++) { float c = vals[i] - mean; s2 += c*c; }
    s2 = block_reduce_sum(s2);
    float rstd = rsqrtf(s2 * (1.f/DM) + 1e-6f);
    #pragma unroll
    for (int i = 0; i < 3; i++) {
        int d = threadIdx.x + i*256;
        float x = (vals[i] - mean) * rstd;
        float u = x * (1.f + aff[4*DM + d]) + aff[3*DM + d];
        split2(u, &g_u_hi[t*DM + d], &g_u_lo[t*DM + d]);
    }
}

// ---------------- cross attention ----------------
__global__ __launch_bounds__(512) void k_attn(int l) {
    int qt = blockIdx.x, hh = blockIdx.y, b = blockIdx.z;
    int warp = threadIdx.x >> 5, lane = threadIdx.x & 31;
    const float* kp = g_kall + (size_t)l*BB*LCC*AINNER;
    const float* vp = g_vall + (size_t)l*BB*LCC*AINNER;
    __shared__ float Ks[64][65];
    __shared__ float Vs[64][64];
    __shared__ float Qs[16][64];
    __shared__ float Ps[16][64];
    for (int idx = threadIdx.x; idx < 64*64; idx += 512) {
        int m = idx >> 6, d = idx & 63;
        Ks[m][d] = kp[(size_t)(b*LCC + m)*AINNER + hh*ADD + d];
        Vs[m][d] = vp[(size_t)(b*LCC + m)*AINNER + hh*ADD + d];
    }
    for (int idx = threadIdx.x; idx < 16*64; idx += 512) {
        int q = idx >> 6, d = idx & 63;
        Qs[q][d] = g_q[(size_t)(b*LL + qt*16 + q)*AINNER + hh*ADD + d];
    }
    __syncthreads();
    int q = warp;
    float s0 = 0.f, s1 = 0.f;
    #pragma unroll 8
    for (int d = 0; d < 64; d++) {
        float qd = Qs[q][d];
        s0 += qd * Ks[lane][d];
        s1 += qd * Ks[lane+32][d];
    }
    s0 *= 0.125f; s1 *= 0.125f;
    float mx = fmaxf(s0, s1);
    #pragma unroll
    for (int o = 16; o > 0; o >>= 1) mx = fmaxf(mx, __shfl_xor_sync(0xffffffffu, mx, o));
    float e0 = expf(s0 - mx), e1 = expf(s1 - mx);
    float sum = e0 + e1;
    #pragma unroll
    for (int o = 16; o > 0; o >>= 1) sum += __shfl_xor_sync(0xffffffffu, sum, o);
    float inv = 1.f / sum;
    Ps[q][lane] = e0 * inv;
    Ps[q][lane+32] = e1 * inv;
    __syncwarp();
    float o0 = 0.f, o1 = 0.f;
    #pragma unroll 8
    for (int m = 0; m < 64; m++) {
        float pm = Ps[q][m];
        o0 += pm * Vs[m][lane];
        o1 += pm * Vs[m][lane+32];
    }
    size_t base = (size_t)(b*LL + qt*16 + q)*AINNER + hh*ADD;
    split2(o0, &g_ao_hi[base + lane],      &g_ao_lo[base + lane]);
    split2(o1, &g_ao_hi[base + lane + 32], &g_ao_lo[base + lane + 32]);
}

// ---------------- final rmsnorm ----------------
__global__ void k_final(const float* __restrict__ norm_f_w, float* __restrict__ out) {
    int t = blockIdx.x;
    float vals[3];
    float ss = 0.f;
    #pragma unroll
    for (int i = 0; i < 3; i++) {
        int d = threadIdx.x + i*256;
        float v = g_hidden[t*DM + d] + g_resid[t*DM + d];
        vals[i] = v;
        ss += v*v;
    }
    ss = block_reduce_sum(ss);
    float rstd = rsqrtf(ss * (1.f/DM) + 1e-5f);
    #pragma unroll
    for (int i = 0; i < 3; i++) {
        int d = threadIdx.x + i*256;
        out[t*DM + d] = vals[i] * rstd * norm_f_w[d];
    }
}

// ---------------- host ----------------
#define GETSYM(p, T, s) do { void* tmp_; cudaGetSymbolAddress(&tmp_, s); p = (T*)tmp_; } while(0)

extern "C" void kernel_launch(void* const* d_in, const int* in_sizes, int n_in,
                              void* d_out, int out_size) {
    const float* hs        = (const float*)d_in[0];
    const float* ref       = (const float*)d_in[1];
    const float* norm_w    = (const float*)d_in[2];
    const float* ada_w     = (const float*)d_in[3];
    const float* ada_b     = (const float*)d_in[4];
    const float* in_w      = (const float*)d_in[5];
    const float* conv_w    = (const float*)d_in[6];
    const float* conv_b    = (const float*)d_in[7];
    const float* dt_bias   = (const float*)d_in[8];
    const float* A_log     = (const float*)d_in[9];
    const float* D_ssm     = (const float*)d_in[10];
    const float* ssm_nw    = (const float*)d_in[11];
    const float* out_w     = (const float*)d_in[12];
    const float* out_b     = (const float*)d_in[13];
    const float* q_w       = (const float*)d_in[14];
    const float* k_w       = (const float*)d_in[15];
    const float* v_w       = (const float*)d_in[16];
    const float* o_w       = (const float*)d_in[17];
    const float* o_b       = (const float*)d_in[18];
    const float* norm_f_w  = (const float*)d_in[19];
    float* out = (float*)d_out;

    static int smem_set = 0;
    if (!smem_set) {
        cudaFuncSetAttribute(gemm_bs, cudaFuncAttributeMaxDynamicSharedMemorySize,
                             GEMM_SMEM_BYTES);
        smem_set = 1;
    }

    float *p_zx, *p_q, *p_kall, *p_vall, *p_hidden, *p_aff;
    GETSYM(p_zx,    float, g_zx);
    GETSYM(p_q,     float, g_q);
    GETSYM(p_kall,  float, g_kall);
    GETSYM(p_vall,  float, g_vall);
    GETSYM(p_hidden,float, g_hidden);
    GETSYM(p_aff,   float, g_aff);

    bf16 *u_hi,*u_lo,*y_hi,*y_lo,*ao_hi,*ao_lo,*ref_hi,*ref_lo;
    bf16 *wi_hi,*wi_lo,*wo_hi,*wo_lo,*wq_hi,*wq_lo,*wk_hi,*wk_lo,*wv_hi,*wv_lo,*wp_hi,*wp_lo;
    GETSYM(u_hi,  bf16, g_u_hi);   GETSYM(u_lo,  bf16, g_u_lo);
    GETSYM(y_hi,  bf16, g_y_hi);   GETSYM(y_lo,  bf16, g_y_lo);
    GETSYM(ao_hi, bf16, g_ao_hi);  GETSYM(ao_lo, bf16, g_ao_lo);
    GETSYM(ref_hi,bf16, g_ref_hi); GETSYM(ref_lo,bf16, g_ref_lo);
    GETSYM(wi_hi, bf16, g_wi_hi);  GETSYM(wi_lo, bf16, g_wi_lo);
    GETSYM(wo_hi, bf16, g_wo_hi);  GETSYM(wo_lo, bf16, g_wo_lo);
    GETSYM(wq_hi, bf16, g_wq_hi);  GETSYM(wq_lo, bf16, g_wq_lo);
    GETSYM(wk_hi, bf16, g_wk_hi);  GETSYM(wk_lo, bf16, g_wk_lo);
    GETSYM(wv_hi, bf16, g_wv_hi);  GETSYM(wv_lo, bf16, g_wv_lo);
    GETSYM(wp_hi, bf16, g_wp_hi);  GETSYM(wp_lo, bf16, g_wp_lo);

    const int M = BB*LL;   // 1024

    #define SPLIT(src, hi, lo, n) k_split<<<((n)+255)/256, 256>>>(src, hi, lo, n)
    // launches 0..4
    SPLIT(in_w,  wi_hi, wi_lo, NLAYER*DM*DIP);
    SPLIT(k_w,   wk_hi, wk_lo, NLAYER*DM*AINNER);
    SPLIT(v_w,   wv_hi, wv_lo, NLAYER*DM*AINNER);
    SPLIT(ref,   ref_hi, ref_lo, BB*LCC*DM);
    k_init<<<(BB*LL*DM + 255)/256, 256>>>(hs);
    // launch 5: profiled by ncu (-s 5 -c 1) — k-projection GEMM
    gemm_bs64<<<dim3(AINNER/64, (BB*LCC)/64, NLAYER), 256, S64_BYTES>>>(ref_hi, ref_lo,
        wk_hi, wk_lo, nullptr, nullptr, p_kall, BB*LCC, AINNER, DM,
        (long)DM*AINNER, (long)BB*LCC*AINNER);
    gemm_bs64<<<dim3(AINNER/64, (BB*LCC)/64, NLAYER), 256, S64_BYTES>>>(ref_hi, ref_lo,
        wv_hi, wv_lo, nullptr, nullptr, p_vall, BB*LCC, AINNER, DM,
        (long)DM*AINNER, (long)BB*LCC*AINNER);

    SPLIT(out_w, wo_hi, wo_lo, NLAYER*DI*DM);
    SPLIT(q_w,   wq_hi, wq_lo, NLAYER*DM*AINNER);
    SPLIT(o_w,   wp_hi, wp_lo, NLAYER*AINNER*DM);
    k_condsilu<<<(BB*DM + 255)/256, 256>>>(ref);
    k_ada<<<(NLAYER*BB*6*DM + 255)/256, 256>>>(ada_w, ada_b);

    for (int l = 0; l < NLAYER; l++) {
        k_prenorm_mod<<<M, 256>>>(l, norm_w);
        gemm_bs<<<dim3((DIP+127)/128, M/128), 256, GEMM_SMEM_BYTES>>>(u_hi, u_lo,
            wi_hi + (size_t)l*DM*DIP, wi_lo + (size_t)l*DM*DIP,
            p_zx, M, DIP, DM);
        k_conv_dt<<<M, 256>>>(l, conv_w, conv_b, dt_bias, A_log);
        k_scan<<<dim3(BB*NH, 2), 256>>>(l, D_ssm);
        k_gatenorm<<<M, 256>>>(l, ssm_nw);
        // out-proj: hidden += g_mba * (y @ out_w + out_b)
        gemm_bs64<<<dim3(DM/64, M/64), 256, S64_BYTES>>>(y_hi, y_lo,
            wo_hi + (size_t)l*DI*DM, wo_lo + (size_t)l*DI*DM, out_b + l*DM,
            p_aff + (size_t)(l*BB)*6*DM + 2*DM,
            p_hidden, M, DM, DI, 0, 0);
        k_post_mamba<<<M, 256>>>(l);
        gemm_bs64<<<dim3(AINNER/64, M/64), 256, S64_BYTES>>>(u_hi, u_lo,
            wq_hi + (size_t)l*DM*AINNER, wq_lo + (size_t)l*DM*AINNER, nullptr, nullptr,
            p_q, M, AINNER, DM, 0, 0);
        k_attn<<<dim3(LL/16, AHH, BB), 512>>>(l);
        // o-proj: hidden += g_msa * (ao @ o_w + o_b)
        gemm_bs64<<<dim3(DM/64, M/64), 256, S64_BYTES>>>(ao_hi, ao_lo,
            wp_hi + (size_t)l*AINNER*DM, wp_lo + (size_t)l*AINNER*DM, o_b + l*DM,
            p_aff + (size_t)(l*BB)*6*DM + 5*DM,
            p_hidden, M, DM, AINNER, 0, 0);
    }
    k_final<<<M, 256>>>(norm_f_w, out);
}

// round 9
// speedup vs baseline: 2.4403x; 1.0439x over previous
#include <cuda_runtime.h>
#include <math.h>
#include <stdint.h>

#define BB 2
#define LL 512
#define LCC 64
#define DM 768
#define DI 1536
#define NH 24
#define HD 64
#define DSTATE 128
#define CONVD 1792
#define DIP 3352
#define NLAYER 8
#define AHH 8
#define ADD 64
#define AINNER 512

// ---------------- scratch ----------------
__device__ float g_hidden[BB*LL*DM];
__device__ float g_resid [BB*LL*DM];
__device__ float g_u     [BB*LL*DM];
__device__ float g_zx    [BB*LL*DIP];
__device__ float g_xBC   [BB*LL*CONVD];
__device__ float g_dt    [BB*LL*NH];
__device__ float g_dA    [BB*LL*NH];
__device__ float g_y     [BB*LL*DI];
__device__ float g_q     [BB*LL*AINNER];
__device__ float g_ao    [BB*LL*AINNER];
__device__ float g_kall  [NLAYER*BB*LCC*AINNER];
__device__ float g_vall  [NLAYER*BB*LCC*AINNER];
__device__ float g_aff   [NLAYER*BB*6*DM];
__device__ float g_csilu [BB*DM];

__device__ __forceinline__ float siluf(float x) { return x / (1.f + expf(-x)); }

__device__ __forceinline__ float block_reduce_sum(float v) {
    __shared__ float red_s[33];
    int lane = threadIdx.x & 31;
    int wid  = threadIdx.x >> 5;
    #pragma unroll
    for (int o = 16; o > 0; o >>= 1) v += __shfl_xor_sync(0xffffffffu, v, o);
    if (lane == 0) red_s[wid] = v;
    __syncthreads();
    int nw = (blockDim.x + 31) >> 5;
    if (wid == 0) {
        float x = (lane < nw) ? red_s[lane] : 0.f;
        #pragma unroll
        for (int o = 16; o > 0; o >>= 1) x += __shfl_xor_sync(0xffffffffu, x, o);
        if (lane == 0) red_s[32] = x;
    }
    __syncthreads();
    float r = red_s[32];
    __syncthreads();
    return r;
}

// ---------------- init ----------------
__global__ void k_init(const float* __restrict__ hs) {
    int i = blockIdx.x * 256 + threadIdx.x;
    if (i < BB*LL*DM) { g_hidden[i] = hs[i]; g_resid[i] = 0.f; }
}

__global__ void k_condsilu(const float* __restrict__ ref) {
    int i = blockIdx.x * 256 + threadIdx.x;
    if (i >= BB*DM) return;
    int b = i / DM, d = i % DM;
    float s = 0.f;
    for (int m = 0; m < LCC; m++) s += ref[(b*LCC + m)*DM + d];
    s *= (1.f / LCC);
    g_csilu[i] = siluf(s);
}

__global__ void k_ada(const float* __restrict__ ada_w, const float* __restrict__ ada_b) {
    int i = blockIdx.x * 256 + threadIdx.x;
    if (i >= NLAYER*BB*6*DM) return;
    int j  = i % (6*DM);
    int lb = i / (6*DM);
    int b  = lb % BB;
    int l  = lb / BB;
    float s = ada_b[l*6*DM + j];
    const float* cs = &g_csilu[b*DM];
    const float* w  = ada_w + (size_t)l*DM*6*DM + j;
    for (int d = 0; d < DM; d++) s += cs[d] * w[(size_t)d*6*DM];
    g_aff[i] = s;
}

// ================= TF32 tensor-core GEMM =================
__device__ __forceinline__ uint32_t f2tf(float f) {
    uint32_t r;
    asm("cvt.rna.tf32.f32 %0, %1;" : "=r"(r) : "f"(f));
    return r;
}
__device__ __forceinline__ void mma_tf32(float* d, const uint32_t* a, uint32_t b0, uint32_t b1) {
    asm volatile("mma.sync.aligned.m16n8k8.row.col.f32.tf32.tf32.f32 "
        "{%0,%1,%2,%3}, {%4,%5,%6,%7}, {%8,%9}, {%0,%1,%2,%3};"
        : "+f"(d[0]), "+f"(d[1]), "+f"(d[2]), "+f"(d[3])
        : "r"(a[0]), "r"(a[1]), "r"(a[2]), "r"(a[3]), "r"(b0), "r"(b1));
}
__device__ __forceinline__ void cp16(void* smem, const void* gmem) {
    uint32_t s = (uint32_t)__cvta_generic_to_shared(smem);
    asm volatile("cp.async.cg.shared.global [%0], [%1], 16;" :: "r"(s), "l"(gmem));
}

// ---------------- 128x128 tile (in_proj) ----------------
#define APX 36                       // A smem pitch (floats), conflict-free frags
#define BPX 136                      // B smem pitch (floats), conflict-free frags
#define A_FLOATS (128*APX)           // 4608
#define STG128   (A_FLOATS + 32*BPX) // 8960 floats / stage
#define SM128_BYTES (2*STG128*4)     // 71680

__global__ __launch_bounds__(256, 2) void gemm128(const float* __restrict__ A,
                                                  const float* __restrict__ W,
                                                  float* __restrict__ C,
                                                  int M, int N, int K) {
    extern __shared__ float sm[];
    int tid = threadIdx.x;
    int n0 = blockIdx.x * 128, m0 = blockIdx.y * 128;
    int warp = tid >> 5, lane = tid & 31;
    int wm = warp >> 2, wn = warp & 3;

    float acc[4][4][4];
    #pragma unroll
    for (int i = 0; i < 4; i++)
        #pragma unroll
        for (int j = 0; j < 4; j++)
            #pragma unroll
            for (int v = 0; v < 4; v++) acc[i][j][v] = 0.f;

    int nt = K >> 5;

    auto load_tile = [&](int it, int st) {
        float* base = sm + st*STG128;
        // A: 128x32 floats = 1024 float4 chunks, 4/thread
        #pragma unroll
        for (int j = 0; j < 4; j++) {
            int chunk = tid + j*256;
            int row = chunk >> 3, q = chunk & 7;
            cp16(&base[row*APX + q*4], A + (size_t)(m0 + row)*K + it*32 + q*4);
        }
        // B: 32x128 floats = 1024 float4 chunks, 4/thread
        #pragma unroll
        for (int j = 0; j < 4; j++) {
            int chunk = tid + j*256;
            int row = chunk >> 5, q = chunk & 31;
            int col = n0 + q*4;
            if (col + 3 < N) {
                cp16(&base[A_FLOATS + row*BPX + q*4], W + (size_t)(it*32 + row)*N + col);
            } else {
                float4 v = make_float4(0.f,0.f,0.f,0.f);
                const float* src = W + (size_t)(it*32 + row)*N;
                if (col   < N) v.x = src[col];
                if (col+1 < N) v.y = src[col+1];
                if (col+2 < N) v.z = src[col+2];
                if (col+3 < N) v.w = src[col+3];
                *reinterpret_cast<float4*>(&base[A_FLOATS + row*BPX + q*4]) = v;
            }
        }
        asm volatile("cp.async.commit_group;");
    };

    load_tile(0, 0);

    int gq = lane >> 2, lq = lane & 3;  // frag coords
    for (int it = 0; it < nt; it++) {
        if (it + 1 < nt) {
            load_tile(it + 1, (it + 1) & 1);
            asm volatile("cp.async.wait_group 1;");
        } else {
            asm volatile("cp.async.wait_group 0;");
        }
        __syncthreads();

        float* base = sm + (it & 1)*STG128;
        float* Bs = base + A_FLOATS;
        #pragma unroll
        for (int ks = 0; ks < 4; ks++) {
            int kk = ks * 8;
            uint32_t af[4][4];
            #pragma unroll
            for (int mt = 0; mt < 4; mt++) {
                int r = wm*64 + mt*16 + gq;
                int c = kk + lq;
                af[mt][0] = f2tf(base[r*APX + c]);
                af[mt][1] = f2tf(base[(r+8)*APX + c]);
                af[mt][2] = f2tf(base[r*APX + c + 4]);
                af[mt][3] = f2tf(base[(r+8)*APX + c + 4]);
            }
            uint32_t bf[4][2];
            #pragma unroll
            for (int ntile = 0; ntile < 4; ntile++) {
                int col = wn*32 + ntile*8 + gq;
                int k0 = kk + lq;
                bf[ntile][0] = f2tf(Bs[k0*BPX + col]);
                bf[ntile][1] = f2tf(Bs[(k0+4)*BPX + col]);
            }
            #pragma unroll
            for (int mt = 0; mt < 4; mt++)
                #pragma unroll
                for (int ntile = 0; ntile < 4; ntile++)
                    mma_tf32(acc[mt][ntile], af[mt], bf[ntile][0], bf[ntile][1]);
        }
        __syncthreads();
    }

    int gr = lane >> 2, gc = (lane & 3)*2;
    #pragma unroll
    for (int mt = 0; mt < 4; mt++) {
        #pragma unroll
        for (int ntile = 0; ntile < 4; ntile++) {
            int row0 = m0 + wm*64 + mt*16 + gr;
            int col0 = n0 + wn*32 + ntile*8 + gc;
            if (col0 < N) {
                C[(size_t)row0*N + col0]     = acc[mt][ntile][0];
                C[(size_t)(row0+8)*N + col0] = acc[mt][ntile][2];
            }
            if (col0 + 1 < N) {
                C[(size_t)row0*N + col0+1]     = acc[mt][ntile][1];
                C[(size_t)(row0+8)*N + col0+1] = acc[mt][ntile][3];
            }
        }
    }
}

// ---------------- 64x64 tile (small GEMMs; optional gate-accum epilogue) ----------------
#define BPX64 72
#define A_FLOATS64 (64*APX)              // 2304
#define STG64 (A_FLOATS64 + 32*BPX64)    // 4608 floats

// gate!=null: C[r,c] += gate[(r/LL)*6*DM + c] * (acc + bias[c]); else C = acc (+bias)
__global__ __launch_bounds__(256) void gemm64(const float* __restrict__ A,
                                              const float* __restrict__ W,
                                              const float* __restrict__ bias,
                                              const float* __restrict__ gate,
                                              float* __restrict__ C,
                                              int M, int N, int K,
                                              long wz, long cz) {
    __shared__ float sm[2*STG64];

    W += (size_t)blockIdx.z * wz;
    C += (size_t)blockIdx.z * cz;

    int tid = threadIdx.x;
    int n0 = blockIdx.x * 64, m0 = blockIdx.y * 64;
    int warp = tid >> 5, lane = tid & 31;
    int wm = warp >> 2, wn = warp & 3;

    float acc[2][2][4];
    #pragma unroll
    for (int i = 0; i < 2; i++)
        #pragma unroll
        for (int j = 0; j < 2; j++)
            #pragma unroll
            for (int v = 0; v < 4; v++) acc[i][j][v] = 0.f;

    int nt = K >> 5;

    auto load_tile = [&](int it, int st) {
        float* base = sm + st*STG64;
        // A: 64x32 = 512 float4, 2/thread
        #pragma unroll
        for (int j = 0; j < 2; j++) {
            int chunk = tid + j*256;
            int row = chunk >> 3, q = chunk & 7;
            cp16(&base[row*APX + q*4], A + (size_t)(m0 + row)*K + it*32 + q*4);
        }
        // B: 32x64 = 512 float4, 2/thread
        #pragma unroll
        for (int j = 0; j < 2; j++) {
            int chunk = tid + j*256;
            int row = chunk >> 4, q = chunk & 15;
            int col = n0 + q*4;
            if (col + 3 < N) {
                cp16(&base[A_FLOATS64 + row*BPX64 + q*4], W + (size_t)(it*32 + row)*N + col);
            } else {
                float4 v = make_float4(0.f,0.f,0.f,0.f);
                const float* src = W + (size_t)(it*32 + row)*N;
                if (col   < N) v.x = src[col];
                if (col+1 < N) v.y = src[col+1];
                if (col+2 < N) v.z = src[col+2];
                if (col+3 < N) v.w = src[col+3];
                *reinterpret_cast<float4*>(&base[A_FLOATS64 + row*BPX64 + q*4]) = v;
            }
        }
        asm volatile("cp.async.commit_group;");
    };

    load_tile(0, 0);

    int gq = lane >> 2, lq = lane & 3;
    for (int it = 0; it < nt; it++) {
        if (it + 1 < nt) {
            load_tile(it + 1, (it + 1) & 1);
            asm volatile("cp.async.wait_group 1;");
        } else {
            asm volatile("cp.async.wait_group 0;");
        }
        __syncthreads();

        float* base = sm + (it & 1)*STG64;
        float* Bs = base + A_FLOATS64;
        #pragma unroll
        for (int ks = 0; ks < 4; ks++) {
            int kk = ks * 8;
            uint32_t af[2][4];
            #pragma unroll
            for (int mt = 0; mt < 2; mt++) {
                int r = wm*32 + mt*16 + gq;
                int c = kk + lq;
                af[mt][0] = f2tf(base[r*APX + c]);
                af[mt][1] = f2tf(base[(r+8)*APX + c]);
                af[mt][2] = f2tf(base[r*APX + c + 4]);
                af[mt][3] = f2tf(base[(r+8)*APX + c + 4]);
            }
            uint32_t bf[2][2];
            #pragma unroll
            for (int ntile = 0; ntile < 2; ntile++) {
                int col = wn*16 + ntile*8 + gq;
                int k0 = kk + lq;
                bf[ntile][0] = f2tf(Bs[k0*BPX64 + col]);
                bf[ntile][1] = f2tf(Bs[(k0+4)*BPX64 + col]);
            }
            #pragma unroll
            for (int mt = 0; mt < 2; mt++)
                #pragma unroll
                for (int ntile = 0; ntile < 2; ntile++)
                    mma_tf32(acc[mt][ntile], af[mt], bf[ntile][0], bf[ntile][1]);
        }
        __syncthreads();
    }

    int gr = lane >> 2, gc = (lane & 3)*2;
    #pragma unroll
    for (int mt = 0; mt < 2; mt++) {
        int row0 = m0 + wm*32 + mt*16 + gr;
        int bidx = row0 / LL;
        #pragma unroll
        for (int ntile = 0; ntile < 2; ntile++) {
            int col0 = n0 + wn*16 + ntile*8 + gc;
            float b0 = bias ? bias[col0] : 0.f;
            float b1 = bias ? bias[col0+1] : 0.f;
            float v00 = acc[mt][ntile][0] + b0, v01 = acc[mt][ntile][1] + b1;
            float v10 = acc[mt][ntile][2] + b0, v11 = acc[mt][ntile][3] + b1;
            if (col0 < N) {
                if (gate) {
                    float gv0 = gate[bidx*6*DM + col0];
                    float gv1 = gate[bidx*6*DM + col0 + 1];
                    C[(size_t)row0*N + col0]       += gv0 * v00;
                    C[(size_t)row0*N + col0+1]     += gv1 * v01;
                    C[(size_t)(row0+8)*N + col0]   += gv0 * v10;
                    C[(size_t)(row0+8)*N + col0+1] += gv1 * v11;
                } else {
                    C[(size_t)row0*N + col0]       = v00;
                    C[(size_t)row0*N + col0+1]     = v01;
                    C[(size_t)(row0+8)*N + col0]   = v10;
                    C[(size_t)(row0+8)*N + col0+1] = v11;
                }
            }
        }
    }
}

// ---------------- pre-norm + AdaLN modulation ----------------
__global__ void k_prenorm_mod(int l, const float* __restrict__ norm_w) {
    int t = blockIdx.x;
    int b = t / LL;
    const float* aff = &g_aff[(l*BB + b)*6*DM];
    float vals[3];
    float ss = 0.f;
    #pragma unroll
    for (int i = 0; i < 3; i++) {
        int d = threadIdx.x + i*256;
        float v = g_resid[t*DM + d] + g_hidden[t*DM + d];
        g_resid[t*DM + d] = v;
        vals[i] = v;
        ss += v*v;
    }
    ss = block_reduce_sum(ss);
    float rstd = rsqrtf(ss * (1.f/DM) + 1e-5f);
    #pragma unroll
    for (int i = 0; i < 3; i++) {
        int d = threadIdx.x + i*256;
        float x = vals[i] * rstd * norm_w[l*DM + d];
        g_hidden[t*DM + d] = x;
        g_u[t*DM + d] = x * (1.f + aff[DM + d]) + aff[d];
    }
}

// ---------------- conv + dt ----------------
__global__ void k_conv_dt(int l, const float* __restrict__ conv_w,
                          const float* __restrict__ conv_b,
                          const float* __restrict__ dt_bias,
                          const float* __restrict__ A_log) {
    int t  = blockIdx.x;
    int b  = t / LL, tt = t % LL;
    for (int c = threadIdx.x; c < CONVD; c += 256) {
        const float* wc = conv_w + (l*CONVD + c)*4;
        float acc = conv_b[l*CONVD + c];
        #pragma unroll
        for (int j = 0; j < 4; j++) {
            int ts = tt - 3 + j;
            if (ts >= 0) acc += wc[j] * g_zx[(size_t)(b*LL + ts)*DIP + DI + c];
        }
        g_xBC[(size_t)t*CONVD + c] = siluf(acc);
    }
    if (threadIdx.x < NH) {
        int hh = threadIdx.x;
        float x = g_zx[(size_t)t*DIP + DI + CONVD + hh] + dt_bias[l*NH + hh];
        float dt = (x > 20.f) ? x : log1pf(expf(x));
        g_dt[t*NH + hh] = dt;
        g_dA[t*NH + hh] = expf(-expf(A_log[l*NH + hh]) * dt);
    }
}

// ---------------- SSM scan ----------------
#define TCH 8
__global__ __launch_bounds__(256) void k_scan(int l, const float* __restrict__ D_ssm) {
    int bh = blockIdx.x;
    int b = bh / NH, hh = bh % NH;
    int ps = blockIdx.y;
    int tid = threadIdx.x;
    int pl = tid >> 3;
    int p  = ps*32 + pl;
    int ng = tid & 7;
    int nb = ng * 16;
    float hreg[16];
    #pragma unroll
    for (int i = 0; i < 16; i++) hreg[i] = 0.f;

    __shared__ float sx[TCH][32];
    __shared__ float sB[TCH][DSTATE];
    __shared__ float sC[TCH][DSTATE];
    __shared__ float sdt[TCH], sdA[TCH];
    float Dh = D_ssm[l*NH + hh];

    for (int t0 = 0; t0 < LL; t0 += TCH) {
        __syncthreads();
        for (int idx = tid; idx < TCH*288; idx += 256) {
            int st = idx / 288, off = idx % 288;
            size_t tok = (size_t)(b*LL + t0 + st);
            if (off < 32)
                sx[st][off] = g_xBC[tok*CONVD + hh*HD + ps*32 + off];
            else if (off < 160)
                sB[st][off-32] = g_xBC[tok*CONVD + DI + (off-32)];
            else
                sC[st][off-160] = g_xBC[tok*CONVD + DI + DSTATE + (off-160)];
        }
        if (tid < TCH) {
            int tok = b*LL + t0 + tid;
            sdt[tid] = g_dt[tok*NH + hh];
            sdA[tid] = g_dA[tok*NH + hh];
        }
        __syncthreads();
        #pragma unroll
        for (int st = 0; st < TCH; st++) {
            float dtt = sdt[st], dAt = sdA[st];
            float xp  = sx[st][pl];
            float dbx = dtt * xp;
            float y = 0.f;
            #pragma unroll
            for (int i = 0; i < 16; i++) {
                float hv = hreg[i]*dAt + dbx*sB[st][nb+i];
                hreg[i] = hv;
                y += hv * sC[st][nb+i];
            }
            y += __shfl_xor_sync(0xffffffffu, y, 1);
            y += __shfl_xor_sync(0xffffffffu, y, 2);
            y += __shfl_xor_sync(0xffffffffu, y, 4);
            if (ng == 0) {
                int tok = b*LL + t0 + st;
                g_y[(size_t)tok*DI + hh*HD + p] = y + xp * Dh;
            }
        }
    }
}

// ---------------- gated RMS norm ----------------
__global__ void k_gatenorm(int l, const float* __restrict__ ssm_norm_w) {
    int t = blockIdx.x;
    __shared__ float sv[DI];
    float ss = 0.f;
    for (int d = threadIdx.x; d < DI; d += 256) {
        float z = g_zx[(size_t)t*DIP + d];
        float v = g_y[(size_t)t*DI + d] * siluf(z);
        sv[d] = v;
        ss += v*v;
    }
    ss = block_reduce_sum(ss);
    float rstd = rsqrtf(ss * (1.f/DI) + 1e-5f);
    for (int d = threadIdx.x; d < DI; d += 256)
        g_y[(size_t)t*DI + d] = sv[d] * rstd * ssm_norm_w[l*DI + d];
}

// ---------------- u = ln_noaffine(hidden)*(1+sc_msa)+sh_msa ----------------
__global__ void k_post_mamba(int l) {
    int t = blockIdx.x;
    int b = t / LL;
    const float* aff = &g_aff[(l*BB + b)*6*DM];
    float vals[3];
    float s1 = 0.f;
    #pragma unroll
    for (int i = 0; i < 3; i++) {
        int d = threadIdx.x + i*256;
        float v = g_hidden[t*DM + d];
        vals[i] = v;
        s1 += v;
    }
    s1 = block_reduce_sum(s1);
    float mean = s1 * (1.f/DM);
    float s2 = 0.f;
    #pragma unroll
    for (int i = 0; i < 3; i++) { float c = vals[i] - mean; s2 += c*c; }
    s2 = block_reduce_sum(s2);
    float rstd = rsqrtf(s2 * (1.f/DM) + 1e-6f);
    #pragma unroll
    for (int i = 0; i < 3; i++) {
        int d = threadIdx.x + i*256;
        float x = (vals[i] - mean) * rstd;
        g_u[t*DM + d] = x * (1.f + aff[4*DM + d]) + aff[3*DM + d];
    }
}

// ---------------- cross attention ----------------
__global__ __launch_bounds__(512) void k_attn(int l) {
    int qt = blockIdx.x, hh = blockIdx.y, b = blockIdx.z;
    int warp = threadIdx.x >> 5, lane = threadIdx.x & 31;
    const float* kp = g_kall + (size_t)l*BB*LCC*AINNER;
    const float* vp = g_vall + (size_t)l*BB*LCC*AINNER;
    __shared__ float Ks[64][65];
    __shared__ float Vs[64][64];
    __shared__ float Qs[16][64];
    __shared__ float Ps[16][64];
    for (int idx = threadIdx.x; idx < 64*64; idx += 512) {
        int m = idx >> 6, d = idx & 63;
        Ks[m][d] = kp[(size_t)(b*LCC + m)*AINNER + hh*ADD + d];
        Vs[m][d] = vp[(size_t)(b*LCC + m)*AINNER + hh*ADD + d];
    }
    for (int idx = threadIdx.x; idx < 16*64; idx += 512) {
        int q = idx >> 6, d = idx & 63;
        Qs[q][d] = g_q[(size_t)(b*LL + qt*16 + q)*AINNER + hh*ADD + d];
    }
    __syncthreads();
    int q = warp;
    float s0 = 0.f, s1 = 0.f;
    #pragma unroll 8
    for (int d = 0; d < 64; d++) {
        float qd = Qs[q][d];
        s0 += qd * Ks[lane][d];
        s1 += qd * Ks[lane+32][d];
    }
    s0 *= 0.125f; s1 *= 0.125f;
    float mx = fmaxf(s0, s1);
    #pragma unroll
    for (int o = 16; o > 0; o >>= 1) mx = fmaxf(mx, __shfl_xor_sync(0xffffffffu, mx, o));
    float e0 = expf(s0 - mx), e1 = expf(s1 - mx);
    float sum = e0 + e1;
    #pragma unroll
    for (int o = 16; o > 0; o >>= 1) sum += __shfl_xor_sync(0xffffffffu, sum, o);
    float inv = 1.f / sum;
    Ps[q][lane] = e0 * inv;
    Ps[q][lane+32] = e1 * inv;
    __syncwarp();
    float o0 = 0.f, o1 = 0.f;
    #pragma unroll 8
    for (int m = 0; m < 64; m++) {
        float pm = Ps[q][m];
        o0 += pm * Vs[m][lane];
        o1 += pm * Vs[m][lane+32];
    }
    size_t base = (size_t)(b*LL + qt*16 + q)*AINNER + hh*ADD;
    g_ao[base + lane]      = o0;
    g_ao[base + lane + 32] = o1;
}

// ---------------- final rmsnorm ----------------
__global__ void k_final(const float* __restrict__ norm_f_w, float* __restrict__ out) {
    int t = blockIdx.x;
    float vals[3];
    float ss = 0.f;
    #pragma unroll
    for (int i = 0; i < 3; i++) {
        int d = threadIdx.x + i*256;
        float v = g_hidden[t*DM + d] + g_resid[t*DM + d];
        vals[i] = v;
        ss += v*v;
    }
    ss = block_reduce_sum(ss);
    float rstd = rsqrtf(ss * (1.f/DM) + 1e-5f);
    #pragma unroll
    for (int i = 0; i < 3; i++) {
        int d = threadIdx.x + i*256;
        out[t*DM + d] = vals[i] * rstd * norm_f_w[d];
    }
}

// ---------------- host ----------------
#define GETSYM(p, T, s) do { void* tmp_; cudaGetSymbolAddress(&tmp_, s); p = (T*)tmp_; } while(0)

extern "C" void kernel_launch(void* const* d_in, const int* in_sizes, int n_in,
                              void* d_out, int out_size) {
    const float* hs        = (const float*)d_in[0];
    const float* ref       = (const float*)d_in[1];
    const float* norm_w    = (const float*)d_in[2];
    const float* ada_w     = (const float*)d_in[3];
    const float* ada_b     = (const float*)d_in[4];
    const float* in_w      = (const float*)d_in[5];
    const float* conv_w    = (const float*)d_in[6];
    const float* conv_b    = (const float*)d_in[7];
    const float* dt_bias   = (const float*)d_in[8];
    const float* A_log     = (const float*)d_in[9];
    const float* D_ssm     = (const float*)d_in[10];
    const float* ssm_nw    = (const float*)d_in[11];
    const float* out_w     = (const float*)d_in[12];
    const float* out_b     = (const float*)d_in[13];
    const float* q_w       = (const float*)d_in[14];
    const float* k_w       = (const float*)d_in[15];
    const float* v_w       = (const float*)d_in[16];
    const float* o_w       = (const float*)d_in[17];
    const float* o_b       = (const float*)d_in[18];
    const float* norm_f_w  = (const float*)d_in[19];
    float* out = (float*)d_out;

    static int smem_set = 0;
    if (!smem_set) {
        cudaFuncSetAttribute(gemm128, cudaFuncAttributeMaxDynamicSharedMemorySize, SM128_BYTES);
        smem_set = 1;
    }

    float *p_u, *p_zx, *p_q, *p_ao, *p_y, *p_kall, *p_vall, *p_hidden, *p_aff;
    GETSYM(p_u,     float, g_u);
    GETSYM(p_zx,    float, g_zx);
    GETSYM(p_q,     float, g_q);
    GETSYM(p_ao,    float, g_ao);
    GETSYM(p_y,     float, g_y);
    GETSYM(p_kall,  float, g_kall);
    GETSYM(p_vall,  float, g_vall);
    GETSYM(p_hidden,float, g_hidden);
    GETSYM(p_aff,   float, g_aff);

    const int M = BB*LL;   // 1024

    // launches 0..4
    k_init<<<(BB*LL*DM + 255)/256, 256>>>(hs);
    k_condsilu<<<(BB*DM + 255)/256, 256>>>(ref);
    k_ada<<<(NLAYER*BB*6*DM + 255)/256, 256>>>(ada_w, ada_b);
    k_prenorm_mod<<<M, 256>>>(0, norm_w);
    gemm64<<<dim3(AINNER/64, (BB*LCC)/64, NLAYER), 256>>>(ref, k_w, nullptr, nullptr,
        p_kall, BB*LCC, AINNER, DM, (long)DM*AINNER, (long)BB*LCC*AINNER);
    // launch 5: ncu target — in_proj layer 0
    gemm128<<<dim3((DIP+127)/128, M/128), 256, SM128_BYTES>>>(p_u, in_w, p_zx, M, DIP, DM);
    gemm64<<<dim3(AINNER/64, (BB*LCC)/64, NLAYER), 256>>>(ref, v_w, nullptr, nullptr,
        p_vall, BB*LCC, AINNER, DM, (long)DM*AINNER, (long)BB*LCC*AINNER);

    for (int l = 0; l < NLAYER; l++) {
        if (l > 0) {
            k_prenorm_mod<<<M, 256>>>(l, norm_w);
            gemm128<<<dim3((DIP+127)/128, M/128), 256, SM128_BYTES>>>(p_u,
                in_w + (size_t)l*DM*DIP, p_zx, M, DIP, DM);
        }
        k_conv_dt<<<M, 256>>>(l, conv_w, conv_b, dt_bias, A_log);
        k_scan<<<dim3(BB*NH, 2), 256>>>(l, D_ssm);
        k_gatenorm<<<M, 256>>>(l, ssm_nw);
        // out-proj: hidden += g_mba * (y @ out_w + out_b)
        gemm64<<<dim3(DM/64, M/64), 256>>>(p_y, out_w + (size_t)l*DI*DM, out_b + l*DM,
            p_aff + (size_t)(l*BB)*6*DM + 2*DM, p_hidden, M, DM, DI, 0, 0);
        k_post_mamba<<<M, 256>>>(l);
        gemm64<<<dim3(AINNER/64, M/64), 256>>>(p_u, q_w + (size_t)l*DM*AINNER, nullptr,
            nullptr, p_q, M, AINNER, DM, 0, 0);
        k_attn<<<dim3(LL/16, AHH, BB), 512>>>(l);
        // o-proj: hidden += g_msa * (ao @ o_w + o_b)
        gemm64<<<dim3(DM/64, M/64), 256>>>(p_ao, o_w + (size_t)l*AINNER*DM, o_b + l*DM,
            p_aff + (size_t)(l*BB)*6*DM + 5*DM, p_hidden, M, DM, AINNER, 0, 0);
    }
    k_final<<<M, 256>>>(norm_f_w, out);
}

// round 10
// speedup vs baseline: 2.6214x; 1.0742x over previous
#include <cuda_runtime.h>
#include <cuda_bf16.h>
#include <math.h>
#include <stdint.h>

#define BB 2
#define LL 512
#define LCC 64
#define DM 768
#define DI 1536
#define NH 24
#define HD 64
#define DSTATE 128
#define CONVD 1792
#define DIP 3352
#define NLAYER 8
#define AHH 8
#define ADD 64
#define AINNER 512

typedef __nv_bfloat16 bf16;

// ---------------- scratch ----------------
__device__ float g_hidden[BB*LL*DM];
__device__ float g_resid [BB*LL*DM];
__device__ float g_zx    [BB*LL*DIP];
__device__ float g_xBC   [BB*LL*CONVD];
__device__ float g_dt    [BB*LL*NH];
__device__ float g_dA    [BB*LL*NH];
__device__ float g_y     [BB*LL*DI];
__device__ float g_q     [BB*LL*AINNER];
__device__ float g_kall  [NLAYER*BB*LCC*AINNER];
__device__ float g_vall  [NLAYER*BB*LCC*AINNER];
__device__ float g_aff   [NLAYER*BB*6*DM];
__device__ float g_csilu [BB*DM];

// bf16 activations (GEMM A inputs)
__device__ bf16 g_u_bf [BB*LL*DM];
__device__ bf16 g_y_bf [BB*LL*DI];
__device__ bf16 g_ao_bf[BB*LL*AINNER];
__device__ bf16 g_ref_bf[BB*LCC*DM];

// bf16 weights (GEMM B inputs, [K,N] layout as given)
__device__ bf16 g_wi_bf[NLAYER*DM*DIP];
__device__ bf16 g_wo_bf[NLAYER*DI*DM];
__device__ bf16 g_wq_bf[NLAYER*DM*AINNER];
__device__ bf16 g_wk_bf[NLAYER*DM*AINNER];
__device__ bf16 g_wv_bf[NLAYER*DM*AINNER];
__device__ bf16 g_wp_bf[NLAYER*AINNER*DM];

__device__ __forceinline__ float siluf(float x) { return x / (1.f + expf(-x)); }

__device__ __forceinline__ float block_reduce_sum(float v) {
    __shared__ float red_s[33];
    int lane = threadIdx.x & 31;
    int wid  = threadIdx.x >> 5;
    #pragma unroll
    for (int o = 16; o > 0; o >>= 1) v += __shfl_xor_sync(0xffffffffu, v, o);
    if (lane == 0) red_s[wid] = v;
    __syncthreads();
    int nw = (blockDim.x + 31) >> 5;
    if (wid == 0) {
        float x = (lane < nw) ? red_s[lane] : 0.f;
        #pragma unroll
        for (int o = 16; o > 0; o >>= 1) x += __shfl_xor_sync(0xffffffffu, x, o);
        if (lane == 0) red_s[32] = x;
    }
    __syncthreads();
    float r = red_s[32];
    __syncthreads();
    return r;
}

// ---------------- one-time converts ----------------
__global__ void k_tobf16(const float* __restrict__ src, bf16* __restrict__ dst, int n) {
    int i = blockIdx.x * 256 + threadIdx.x;
    if (i < n) dst[i] = __float2bfloat16(src[i]);
}

// ---------------- init ----------------
__global__ void k_init(const float* __restrict__ hs) {
    int i = blockIdx.x * 256 + threadIdx.x;
    if (i < BB*LL*DM) { g_hidden[i] = hs[i]; g_resid[i] = 0.f; }
}

__global__ void k_condsilu(const float* __restrict__ ref) {
    int i = blockIdx.x * 256 + threadIdx.x;
    if (i >= BB*DM) return;
    int b = i / DM, d = i % DM;
    float s = 0.f;
    for (int m = 0; m < LCC; m++) s += ref[(b*LCC + m)*DM + d];
    s *= (1.f / LCC);
    g_csilu[i] = siluf(s);
}

__global__ void k_ada(const float* __restrict__ ada_w, const float* __restrict__ ada_b) {
    int i = blockIdx.x * 256 + threadIdx.x;
    if (i >= NLAYER*BB*6*DM) return;
    int j  = i % (6*DM);
    int lb = i / (6*DM);
    int b  = lb % BB;
    int l  = lb / BB;
    float s = ada_b[l*6*DM + j];
    const float* cs = &g_csilu[b*DM];
    const float* w  = ada_w + (size_t)l*DM*6*DM + j;
    for (int d = 0; d < DM; d++) s += cs[d] * w[(size_t)d*6*DM];
    g_aff[i] = s;
}

// ================= bf16 tensor-core GEMM (single precision-level, ldmatrix) =================
__device__ __forceinline__ void ldsm4(uint32_t* r, uint32_t addr) {
    asm volatile("ldmatrix.sync.aligned.m8n8.x4.shared.b16 {%0,%1,%2,%3}, [%4];"
        : "=r"(r[0]), "=r"(r[1]), "=r"(r[2]), "=r"(r[3]) : "r"(addr));
}
__device__ __forceinline__ void ldsm4t(uint32_t* r, uint32_t addr) {
    asm volatile("ldmatrix.sync.aligned.m8n8.x4.trans.shared.b16 {%0,%1,%2,%3}, [%4];"
        : "=r"(r[0]), "=r"(r[1]), "=r"(r[2]), "=r"(r[3]) : "r"(addr));
}
__device__ __forceinline__ void mma_bf16(float* d, const uint32_t* a, uint32_t b0, uint32_t b1) {
    asm volatile("mma.sync.aligned.m16n8k16.row.col.f32.bf16.bf16.f32 "
        "{%0,%1,%2,%3}, {%4,%5,%6,%7}, {%8,%9}, {%0,%1,%2,%3};"
        : "+f"(d[0]), "+f"(d[1]), "+f"(d[2]), "+f"(d[3])
        : "r"(a[0]), "r"(a[1]), "r"(a[2]), "r"(a[3]), "r"(b0), "r"(b1));
}
__device__ __forceinline__ void cp16(void* smem, const void* gmem) {
    uint32_t s = (uint32_t)__cvta_generic_to_shared(smem);
    asm volatile("cp.async.cg.shared.global [%0], [%1], 16;" :: "r"(s), "l"(gmem));
}

#define AP 40    // A smem pitch (bf16)
#define BP 136   // B smem pitch (bf16)

// ---------------- 128x128 tile (in_proj) ----------------
#define OFF_B128 (128*AP)             // 5120 bf16
#define STG128   (128*AP + 32*BP)     // 9472 bf16 per stage (18944 B)

__global__ __launch_bounds__(256) void gemm128(const bf16* __restrict__ A,
                                               const bf16* __restrict__ W,
                                               float* __restrict__ C,
                                               int M, int N, int K) {
    __shared__ bf16 sm[2*STG128];
    int tid = threadIdx.x;
    int n0 = blockIdx.x * 128, m0 = blockIdx.y * 128;
    int warp = tid >> 5, lane = tid & 31;
    int wm = warp >> 2, wn = warp & 3;

    int a_row = tid >> 1, a_off = (tid & 1) * 16;
    int b_row0 = tid >> 4, b_off = (tid & 15) * 8;

    float acc[4][4][4];
    #pragma unroll
    for (int i = 0; i < 4; i++)
        #pragma unroll
        for (int j = 0; j < 4; j++)
            #pragma unroll
            for (int v = 0; v < 4; v++) acc[i][j][v] = 0.f;

    int nt = K >> 5;

    auto load_tile = [&](int it, int st) {
        bf16* base = sm + st*STG128;
        const bf16* src = A + (size_t)(m0 + a_row)*K + it*32 + a_off;
        cp16(&base[a_row*AP + a_off],     src);
        cp16(&base[a_row*AP + a_off + 8], src + 8);
        #pragma unroll
        for (int s = 0; s < 2; s++) {
            int row = b_row0 + s*16;
            int col = n0 + b_off;
            if (col < N) {
                cp16(&base[OFF_B128 + row*BP + b_off], W + (size_t)(it*32 + row)*N + col);
            } else {
                *reinterpret_cast<uint4*>(&base[OFF_B128 + row*BP + b_off]) = make_uint4(0,0,0,0);
            }
        }
        asm volatile("cp.async.commit_group;");
    };

    load_tile(0, 0);

    for (int it = 0; it < nt; it++) {
        if (it + 1 < nt) {
            load_tile(it + 1, (it + 1) & 1);
            asm volatile("cp.async.wait_group 1;");
        } else {
            asm volatile("cp.async.wait_group 0;");
        }
        __syncthreads();

        bf16* base = sm + (it & 1)*STG128;
        #pragma unroll
        for (int kt = 0; kt < 2; kt++) {
            int kk = kt * 16;
            uint32_t af[4][4];
            #pragma unroll
            for (int mt = 0; mt < 4; mt++) {
                int r = wm*64 + mt*16 + (lane & 15);
                int c = kk + (lane >> 4)*8;
                ldsm4(af[mt], (uint32_t)__cvta_generic_to_shared(&base[r*AP + c]));
            }
            uint32_t bfr[2][4];
            #pragma unroll
            for (int np = 0; np < 2; np++) {
                int kr = kk + (lane & 15);
                int c  = wn*32 + np*16 + (lane >> 4)*8;
                ldsm4t(bfr[np], (uint32_t)__cvta_generic_to_shared(&base[OFF_B128 + kr*BP + c]));
            }
            #pragma unroll
            for (int mt = 0; mt < 4; mt++)
                #pragma unroll
                for (int nt2 = 0; nt2 < 4; nt2++) {
                    int np = nt2 >> 1, s = (nt2 & 1)*2;
                    mma_bf16(acc[mt][nt2], af[mt], bfr[np][s], bfr[np][s+1]);
                }
        }
        __syncthreads();
    }

    int gr = lane >> 2, gc = (lane & 3)*2;
    #pragma unroll
    for (int mt = 0; mt < 4; mt++) {
        #pragma unroll
        for (int nt2 = 0; nt2 < 4; nt2++) {
            int row0 = m0 + wm*64 + mt*16 + gr;
            int col0 = n0 + wn*32 + nt2*8 + gc;
            if (col0 < N) {
                C[(size_t)row0*N + col0]     = acc[mt][nt2][0];
                C[(size_t)(row0+8)*N + col0] = acc[mt][nt2][2];
            }
            if (col0 + 1 < N) {
                C[(size_t)row0*N + col0+1]     = acc[mt][nt2][1];
                C[(size_t)(row0+8)*N + col0+1] = acc[mt][nt2][3];
            }
        }
    }
}

// ---------------- 64x64 tile (small GEMMs; optional gate-accum epilogue) ----------------
#define BP64 72
#define OFF_B64 (64*AP)              // 2560 bf16
#define STG64   (64*AP + 32*BP64)    // 4864 bf16 per stage

// gate!=null: C[r,c] += gate[(r/LL)*6*DM + c] * (acc + bias[c]); else C = acc (+bias)
__global__ __launch_bounds__(256) void gemm64(const bf16* __restrict__ A,
                                              const bf16* __restrict__ W,
                                              const float* __restrict__ bias,
                                              const float* __restrict__ gate,
                                              float* __restrict__ C,
                                              int M, int N, int K,
                                              long wz, long cz) {
    __shared__ bf16 sm[2*STG64];

    W += (size_t)blockIdx.z * wz;
    C += (size_t)blockIdx.z * cz;

    int tid = threadIdx.x;
    int n0 = blockIdx.x * 64, m0 = blockIdx.y * 64;
    int warp = tid >> 5, lane = tid & 31;
    int wm = warp >> 2, wn = warp & 3;

    int a_row = tid >> 2, a_off = (tid & 3) * 8;
    int b_row = tid >> 3, b_off = (tid & 7) * 8;

    float acc[2][2][4];
    #pragma unroll
    for (int i = 0; i < 2; i++)
        #pragma unroll
        for (int j = 0; j < 2; j++)
            #pragma unroll
            for (int v = 0; v < 4; v++) acc[i][j][v] = 0.f;

    int nt = K >> 5;

    auto load_tile = [&](int it, int st) {
        bf16* base = sm + st*STG64;
        cp16(&base[a_row*AP + a_off], A + (size_t)(m0 + a_row)*K + it*32 + a_off);
        int col = n0 + b_off;
        if (col < N) {
            cp16(&base[OFF_B64 + b_row*BP64 + b_off], W + (size_t)(it*32 + b_row)*N + col);
        } else {
            *reinterpret_cast<uint4*>(&base[OFF_B64 + b_row*BP64 + b_off]) = make_uint4(0,0,0,0);
        }
        asm volatile("cp.async.commit_group;");
    };

    load_tile(0, 0);

    for (int it = 0; it < nt; it++) {
        if (it + 1 < nt) {
            load_tile(it + 1, (it + 1) & 1);
            asm volatile("cp.async.wait_group 1;");
        } else {
            asm volatile("cp.async.wait_group 0;");
        }
        __syncthreads();

        bf16* base = sm + (it & 1)*STG64;
        #pragma unroll
        for (int kt = 0; kt < 2; kt++) {
            int kk = kt * 16;
            uint32_t af[2][4];
            #pragma unroll
            for (int mt = 0; mt < 2; mt++) {
                int r = wm*32 + mt*16 + (lane & 15);
                int c = kk + (lane >> 4)*8;
                ldsm4(af[mt], (uint32_t)__cvta_generic_to_shared(&base[r*AP + c]));
            }
            uint32_t bfr[4];
            {
                int kr = kk + (lane & 15);
                int c  = wn*16 + (lane >> 4)*8;
                ldsm4t(bfr, (uint32_t)__cvta_generic_to_shared(&base[OFF_B64 + kr*BP64 + c]));
            }
            #pragma unroll
            for (int mt = 0; mt < 2; mt++)
                #pragma unroll
                for (int nt2 = 0; nt2 < 2; nt2++) {
                    int s = nt2*2;
                    mma_bf16(acc[mt][nt2], af[mt], bfr[s], bfr[s+1]);
                }
        }
        __syncthreads();
    }

    int gr = lane >> 2, gc = (lane & 3)*2;
    #pragma unroll
    for (int mt = 0; mt < 2; mt++) {
        int row0 = m0 + wm*32 + mt*16 + gr;
        int bidx = row0 / LL;
        #pragma unroll
        for (int nt2 = 0; nt2 < 2; nt2++) {
            int col0 = n0 + wn*16 + nt2*8 + gc;
            float b0 = bias ? bias[col0] : 0.f;
            float b1 = bias ? bias[col0+1] : 0.f;
            float v00 = acc[mt][nt2][0] + b0, v01 = acc[mt][nt2][1] + b1;
            float v10 = acc[mt][nt2][2] + b0, v11 = acc[mt][nt2][3] + b1;
            if (col0 < N) {
                if (gate) {
                    float gv0 = gate[bidx*6*DM + col0];
                    float gv1 = gate[bidx*6*DM + col0 + 1];
                    C[(size_t)row0*N + col0]       += gv0 * v00;
                    C[(size_t)row0*N + col0+1]     += gv1 * v01;
                    C[(size_t)(row0+8)*N + col0]   += gv0 * v10;
                    C[(size_t)(row0+8)*N + col0+1] += gv1 * v11;
                } else {
                    C[(size_t)row0*N + col0]       = v00;
                    C[(size_t)row0*N + col0+1]     = v01;
                    C[(size_t)(row0+8)*N + col0]   = v10;
                    C[(size_t)(row0+8)*N + col0+1] = v11;
                }
            }
        }
    }
}

// ---------------- pre-norm + AdaLN modulation ----------------
__global__ void k_prenorm_mod(int l, const float* __restrict__ norm_w) {
    int t = blockIdx.x;
    int b = t / LL;
    const float* aff = &g_aff[(l*BB + b)*6*DM];
    float vals[3];
    float ss = 0.f;
    #pragma unroll
    for (int i = 0; i < 3; i++) {
        int d = threadIdx.x + i*256;
        float v = g_resid[t*DM + d] + g_hidden[t*DM + d];
        g_resid[t*DM + d] = v;
        vals[i] = v;
        ss += v*v;
    }
    ss = block_reduce_sum(ss);
    float rstd = rsqrtf(ss * (1.f/DM) + 1e-5f);
    #pragma unroll
    for (int i = 0; i < 3; i++) {
        int d = threadIdx.x + i*256;
        float x = vals[i] * rstd * norm_w[l*DM + d];
        g_hidden[t*DM + d] = x;
        g_u_bf[t*DM + d] = __float2bfloat16(x * (1.f + aff[DM + d]) + aff[d]);
    }
}

// ---------------- conv + dt ----------------
__global__ void k_conv_dt(int l, const float* __restrict__ conv_w,
                          const float* __restrict__ conv_b,
                          const float* __restrict__ dt_bias,
                          const float* __restrict__ A_log) {
    int t  = blockIdx.x;
    int b  = t / LL, tt = t % LL;
    for (int c = threadIdx.x; c < CONVD; c += 256) {
        const float* wc = conv_w + (l*CONVD + c)*4;
        float acc = conv_b[l*CONVD + c];
        #pragma unroll
        for (int j = 0; j < 4; j++) {
            int ts = tt - 3 + j;
            if (ts >= 0) acc += wc[j] * g_zx[(size_t)(b*LL + ts)*DIP + DI + c];
        }
        g_xBC[(size_t)t*CONVD + c] = siluf(acc);
    }
    if (threadIdx.x < NH) {
        int hh = threadIdx.x;
        float x = g_zx[(size_t)t*DIP + DI + CONVD + hh] + dt_bias[l*NH + hh];
        float dt = (x > 20.f) ? x : log1pf(expf(x));
        g_dt[t*NH + hh] = dt;
        g_dA[t*NH + hh] = expf(-expf(A_log[l*NH + hh]) * dt);
    }
}

// ---------------- SSM scan ----------------
#define TCH 8
__global__ __launch_bounds__(256) void k_scan(int l, const float* __restrict__ D_ssm) {
    int bh = blockIdx.x;
    int b = bh / NH, hh = bh % NH;
    int ps = blockIdx.y;
    int tid = threadIdx.x;
    int pl = tid >> 3;
    int p  = ps*32 + pl;
    int ng = tid & 7;
    int nb = ng * 16;
    float hreg[16];
    #pragma unroll
    for (int i = 0; i < 16; i++) hreg[i] = 0.f;

    __shared__ float sx[TCH][32];
    __shared__ float sB[TCH][DSTATE];
    __shared__ float sC[TCH][DSTATE];
    __shared__ float sdt[TCH], sdA[TCH];
    float Dh = D_ssm[l*NH + hh];

    for (int t0 = 0; t0 < LL; t0 += TCH) {
        __syncthreads();
        for (int idx = tid; idx < TCH*288; idx += 256) {
            int st = idx / 288, off = idx % 288;
            size_t tok = (size_t)(b*LL + t0 + st);
            if (off < 32)
                sx[st][off] = g_xBC[tok*CONVD + hh*HD + ps*32 + off];
            else if (off < 160)
                sB[st][off-32] = g_xBC[tok*CONVD + DI + (off-32)];
            else
                sC[st][off-160] = g_xBC[tok*CONVD + DI + DSTATE + (off-160)];
        }
        if (tid < TCH) {
            int tok = b*LL + t0 + tid;
            sdt[tid] = g_dt[tok*NH + hh];
            sdA[tid] = g_dA[tok*NH + hh];
        }
        __syncthreads();
        #pragma unroll
        for (int st = 0; st < TCH; st++) {
            float dtt = sdt[st], dAt = sdA[st];
            float xp  = sx[st][pl];
            float dbx = dtt * xp;
            float y = 0.f;
            #pragma unroll
            for (int i = 0; i < 16; i++) {
                float hv = hreg[i]*dAt + dbx*sB[st][nb+i];
                hreg[i] = hv;
                y += hv * sC[st][nb+i];
            }
            y += __shfl_xor_sync(0xffffffffu, y, 1);
            y += __shfl_xor_sync(0xffffffffu, y, 2);
            y += __shfl_xor_sync(0xffffffffu, y, 4);
            if (ng == 0) {
                int tok = b*LL + t0 + st;
                g_y[(size_t)tok*DI + hh*HD + p] = y + xp * Dh;
            }
        }
    }
}

// ---------------- gated RMS norm -> y bf16 ----------------
__global__ void k_gatenorm(int l, const float* __restrict__ ssm_norm_w) {
    int t = blockIdx.x;
    __shared__ float sv[DI];
    float ss = 0.f;
    for (int d = threadIdx.x; d < DI; d += 256) {
        float z = g_zx[(size_t)t*DIP + d];
        float v = g_y[(size_t)t*DI + d] * siluf(z);
        sv[d] = v;
        ss += v*v;
    }
    ss = block_reduce_sum(ss);
    float rstd = rsqrtf(ss * (1.f/DI) + 1e-5f);
    for (int d = threadIdx.x; d < DI; d += 256)
        g_y_bf[(size_t)t*DI + d] = __float2bfloat16(sv[d] * rstd * ssm_norm_w[l*DI + d]);
}

// ---------------- u = ln_noaffine(hidden)*(1+sc_msa)+sh_msa ----------------
__global__ void k_post_mamba(int l) {
    int t = blockIdx.x;
    int b = t / LL;
    const float* aff = &g_aff[(l*BB + b)*6*DM];
    float vals[3];
    float s1 = 0.f;
    #pragma unroll
    for (int i = 0; i < 3; i++) {
        int d = threadIdx.x + i*256;
        float v = g_hidden[t*DM + d];
        vals[i] = v;
        s1 += v;
    }
    s1 = block_reduce_sum(s1);
    float mean = s1 * (1.f/DM);
    float s2 = 0.f;
    #pragma unroll
    for (int i = 0; i < 3; i++) { float c = vals[i] - mean; s2 += c*c; }
    s2 = block_reduce_sum(s2);
    float rstd = rsqrtf(s2 * (1.f/DM) + 1e-6f);
    #pragma unroll
    for (int i = 0; i < 3; i++) {
        int d = threadIdx.x + i*256;
        float x = (vals[i] - mean) * rstd;
        g_u_bf[t*DM + d] = __float2bfloat16(x * (1.f + aff[4*DM + d]) + aff[3*DM + d]);
    }
}

// ---------------- cross attention ----------------
__global__ __launch_bounds__(512) void k_attn(int l) {
    int qt = blockIdx.x, hh = blockIdx.y, b = blockIdx.z;
    int warp = threadIdx.x >> 5, lane = threadIdx.x & 31;
    const float* kp = g_kall + (size_t)l*BB*LCC*AINNER;
    const float* vp = g_vall + (size_t)l*BB*LCC*AINNER;
    __shared__ float Ks[64][65];
    __shared__ float Vs[64][64];
    __shared__ float Qs[16][64];
    __shared__ float Ps[16][64];
    for (int idx = threadIdx.x; idx < 64*64; idx += 512) {
        int m = idx >> 6, d = idx & 63;
        Ks[m][d] = kp[(size_t)(b*LCC + m)*AINNER + hh*ADD + d];
        Vs[m][d] = vp[(size_t)(b*LCC + m)*AINNER + hh*ADD + d];
    }
    for (int idx = threadIdx.x; idx < 16*64; idx += 512) {
        int q = idx >> 6, d = idx & 63;
        Qs[q][d] = g_q[(size_t)(b*LL + qt*16 + q)*AINNER + hh*ADD + d];
    }
    __syncthreads();
    int q = warp;
    float s0 = 0.f, s1 = 0.f;
    #pragma unroll 8
    for (int d = 0; d < 64; d++) {
        float qd = Qs[q][d];
        s0 += qd * Ks[lane][d];
        s1 += qd * Ks[lane+32][d];
    }
    s0 *= 0.125f; s1 *= 0.125f;
    float mx = fmaxf(s0, s1);
    #pragma unroll
    for (int o = 16; o > 0; o >>= 1) mx = fmaxf(mx, __shfl_xor_sync(0xffffffffu, mx, o));
    float e0 = expf(s0 - mx), e1 = expf(s1 - mx);
    float sum = e0 + e1;
    #pragma unroll
    for (int o = 16; o > 0; o >>= 1) sum += __shfl_xor_sync(0xffffffffu, sum, o);
    float inv = 1.f / sum;
    Ps[q][lane] = e0 * inv;
    Ps[q][lane+32] = e1 * inv;
    __syncwarp();
    float o0 = 0.f, o1 = 0.f;
    #pragma unroll 8
    for (int m = 0; m < 64; m++) {
        float pm = Ps[q][m];
        o0 += pm * Vs[m][lane];
        o1 += pm * Vs[m][lane+32];
    }
    size_t base = (size_t)(b*LL + qt*16 + q)*AINNER + hh*ADD;
    g_ao_bf[base + lane]      = __float2bfloat16(o0);
    g_ao_bf[base + lane + 32] = __float2bfloat16(o1);
}

// ---------------- final rmsnorm ----------------
__global__ void k_final(const float* __restrict__ norm_f_w, float* __restrict__ out) {
    int t = blockIdx.x;
    float vals[3];
    float ss = 0.f;
    #pragma unroll
    for (int i = 0; i < 3; i++) {
        int d = threadIdx.x + i*256;
        float v = g_hidden[t*DM + d] + g_resid[t*DM + d];
        vals[i] = v;
        ss += v*v;
    }
    ss = block_reduce_sum(ss);
    float rstd = rsqrtf(ss * (1.f/DM) + 1e-5f);
    #pragma unroll
    for (int i = 0; i < 3; i++) {
        int d = threadIdx.x + i*256;
        out[t*DM + d] = vals[i] * rstd * norm_f_w[d];
    }
}

// ---------------- host ----------------
#define GETSYM(p, T, s) do { void* tmp_; cudaGetSymbolAddress(&tmp_, s); p = (T*)tmp_; } while(0)

extern "C" void kernel_launch(void* const* d_in, const int* in_sizes, int n_in,
                              void* d_out, int out_size) {
    const float* hs        = (const float*)d_in[0];
    const float* ref       = (const float*)d_in[1];
    const float* norm_w    = (const float*)d_in[2];
    const float* ada_w     = (const float*)d_in[3];
    const float* ada_b     = (const float*)d_in[4];
    const float* in_w      = (const float*)d_in[5];
    const float* conv_w    = (const float*)d_in[6];
    const float* conv_b    = (const float*)d_in[7];
    const float* dt_bias   = (const float*)d_in[8];
    const float* A_log     = (const float*)d_in[9];
    const float* D_ssm     = (const float*)d_in[10];
    const float* ssm_nw    = (const float*)d_in[11];
    const float* out_w     = (const float*)d_in[12];
    const float* out_b     = (const float*)d_in[13];
    const float* q_w       = (const float*)d_in[14];
    const float* k_w       = (const float*)d_in[15];
    const float* v_w       = (const float*)d_in[16];
    const float* o_w       = (const float*)d_in[17];
    const float* o_b       = (const float*)d_in[18];
    const float* norm_f_w  = (const float*)d_in[19];
    float* out = (float*)d_out;

    float *p_zx, *p_q, *p_y, *p_kall, *p_vall, *p_hidden, *p_aff;
    GETSYM(p_zx,    float, g_zx);
    GETSYM(p_q,     float, g_q);
    GETSYM(p_y,     float, g_y);
    GETSYM(p_kall,  float, g_kall);
    GETSYM(p_vall,  float, g_vall);
    GETSYM(p_hidden,float, g_hidden);
    GETSYM(p_aff,   float, g_aff);

    bf16 *u_bf,*y_bf,*ao_bf,*ref_bf,*wi_bf,*wo_bf,*wq_bf,*wk_bf,*wv_bf,*wp_bf;
    GETSYM(u_bf,  bf16, g_u_bf);
    GETSYM(y_bf,  bf16, g_y_bf);
    GETSYM(ao_bf, bf16, g_ao_bf);
    GETSYM(ref_bf,bf16, g_ref_bf);
    GETSYM(wi_bf, bf16, g_wi_bf);
    GETSYM(wo_bf, bf16, g_wo_bf);
    GETSYM(wq_bf, bf16, g_wq_bf);
    GETSYM(wk_bf, bf16, g_wk_bf);
    GETSYM(wv_bf, bf16, g_wv_bf);
    GETSYM(wp_bf, bf16, g_wp_bf);

    const int M = BB*LL;   // 1024
    #define CVT(src, dst, n) k_tobf16<<<((n)+255)/256, 256>>>(src, dst, n)

    // launches 0..4
    k_init<<<(BB*LL*DM + 255)/256, 256>>>(hs);
    k_condsilu<<<(BB*DM + 255)/256, 256>>>(ref);
    k_ada<<<(NLAYER*BB*6*DM + 255)/256, 256>>>(ada_w, ada_b);
    CVT(in_w, wi_bf, NLAYER*DM*DIP);
    k_prenorm_mod<<<M, 256>>>(0, norm_w);
    // launch 5: ncu target — in_proj layer 0
    gemm128<<<dim3((DIP+127)/128, M/128), 256>>>(u_bf, wi_bf, p_zx, M, DIP, DM);

    // remaining one-time converts + kv projections
    CVT(out_w, wo_bf, NLAYER*DI*DM);
    CVT(q_w,   wq_bf, NLAYER*DM*AINNER);
    CVT(k_w,   wk_bf, NLAYER*DM*AINNER);
    CVT(v_w,   wv_bf, NLAYER*DM*AINNER);
    CVT(o_w,   wp_bf, NLAYER*AINNER*DM);
    CVT(ref,   ref_bf, BB*LCC*DM);
    gemm64<<<dim3(AINNER/64, (BB*LCC)/64, NLAYER), 256>>>(ref_bf, wk_bf, nullptr, nullptr,
        p_kall, BB*LCC, AINNER, DM, (long)DM*AINNER, (long)BB*LCC*AINNER);
    gemm64<<<dim3(AINNER/64, (BB*LCC)/64, NLAYER), 256>>>(ref_bf, wv_bf, nullptr, nullptr,
        p_vall, BB*LCC, AINNER, DM, (long)DM*AINNER, (long)BB*LCC*AINNER);

    for (int l = 0; l < NLAYER; l++) {
        if (l > 0) {
            k_prenorm_mod<<<M, 256>>>(l, norm_w);
            gemm128<<<dim3((DIP+127)/128, M/128), 256>>>(u_bf,
                wi_bf + (size_t)l*DM*DIP, p_zx, M, DIP, DM);
        }
        k_conv_dt<<<M, 256>>>(l, conv_w, conv_b, dt_bias, A_log);
        k_scan<<<dim3(BB*NH, 2), 256>>>(l, D_ssm);
        k_gatenorm<<<M, 256>>>(l, ssm_nw);
        // out-proj: hidden += g_mba * (y @ out_w + out_b)
        gemm64<<<dim3(DM/64, M/64), 256>>>(y_bf, wo_bf + (size_t)l*DI*DM, out_b + l*DM,
            p_aff + (size_t)(l*BB)*6*DM + 2*DM, p_hidden, M, DM, DI, 0, 0);
        k_post_mamba<<<M, 256>>>(l);
        gemm64<<<dim3(AINNER/64, M/64), 256>>>(u_bf, wq_bf + (size_t)l*DM*AINNER, nullptr,
            nullptr, p_q, M, AINNER, DM, 0, 0);
        k_attn<<<dim3(LL/16, AHH, BB), 512>>>(l);
        // o-proj: hidden += g_msa * (ao @ o_w + o_b)
        gemm64<<<dim3(DM/64, M/64), 256>>>(ao_bf, wp_bf + (size_t)l*AINNER*DM, o_b + l*DM,
            p_aff + (size_t)(l*BB)*6*DM + 5*DM, p_hidden, M, DM, AINNER, 0, 0);
    }
    k_final<<<M, 256>>>(norm_f_w, out);
}